// round 12
// baseline (speedup 1.0000x reference)
#include <cuda_runtime.h>
#include <cuda_bf16.h>
#include <cstdint>
#include <math.h>

#define NTOK 3136
#define NPAD 3200
#define CDIM 256
#define NHEAD 8
#define DFFN 1024
#define NLAYER 4
#define TOPKK 16
#define HW 56
#define ATTN_SMEM (17856 * 4)

__device__ float g_c1[128 * NTOK];
__device__ float g_gp[NHEAD * NTOK];
__device__ float g_x[NPAD * CDIM];
__device__ float g_sq[NPAD];
__device__ float g_d2[(size_t)NPAD * NPAD];
__device__ int   g_near[NTOK];
__device__ int   g_maxnear[1];
__device__ float g_qkin[NPAD * CDIM];
__device__ float g_q[NPAD * CDIM];
__device__ float g_k[NPAD * CDIM];
__device__ float g_v[NPAD * CDIM];
__device__ float g_att[NPAD * CDIM];
__device__ float g_ffh[(size_t)NPAD * DFFN];
__device__ float g_y[NPAD * CDIM];

__device__ __forceinline__ float fexp(float x) {
    x = fmaxf(x, -87.0f);
    float y = x * 1.44269504088896341f;
    float r = rintf(y);
    float f = y - r;
    float p = 1.33335581e-3f;
    p = fmaf(p, f, 9.61812911e-3f);
    p = fmaf(p, f, 5.55041087e-2f);
    p = fmaf(p, f, 2.40226507e-1f);
    p = fmaf(p, f, 6.93147181e-1f);
    p = fmaf(p, f, 1.0f);
    return __int_as_float(__float_as_int(p) + (((int)r) << 23));
}

__device__ __forceinline__ unsigned f2tf32(float v) {
    unsigned r;
    asm("cvt.rna.tf32.f32 %0, %1;" : "=r"(r) : "f"(v));
    return r;
}

__device__ __forceinline__ void mma_tf32(float c[4],
    unsigned a0, unsigned a1, unsigned a2, unsigned a3,
    unsigned b0, unsigned b1)
{
    asm volatile(
        "mma.sync.aligned.m16n8k8.row.col.f32.tf32.tf32.f32 "
        "{%0,%1,%2,%3}, {%4,%5,%6,%7}, {%8,%9}, {%0,%1,%2,%3};\n"
        : "+f"(c[0]), "+f"(c[1]), "+f"(c[2]), "+f"(c[3])
        : "r"(a0), "r"(a1), "r"(a2), "r"(a3), "r"(b0), "r"(b1));
}

__global__ void pad_kernel(float* __restrict__ x, float* __restrict__ sqv) {
    int i = blockIdx.x * 256 + threadIdx.x;
    x[NTOK * CDIM + i] = 0.f;
    if (i < NPAD - NTOK) sqv[NTOK + i] = 0.f;
}

__global__ void transpose_kernel(const float* __restrict__ src, float* __restrict__ dst) {
    __shared__ float tile[32][33];
    int t0 = blockIdx.x * 32, c0 = blockIdx.y * 32;
    int tx = threadIdx.x, ty = threadIdx.y;
    tile[ty][tx] = src[(c0 + ty) * NTOK + t0 + tx];
    __syncthreads();
    dst[(t0 + ty) * CDIM + c0 + tx] = tile[tx][ty];
}

__global__ __launch_bounds__(256) void conv1_kernel(
    const float* __restrict__ src, const float* __restrict__ wt,
    const float* __restrict__ bias, float* __restrict__ out)
{
    __shared__ float ws[4 * 2304];
    __shared__ float red[4 * 256];
    int cog = blockIdx.x;
    int tid = threadIdx.x;
    int px = tid & 63, cig = tid >> 6;
    int p = blockIdx.y * 64 + px;
    for (int i = tid; i < 4 * 2304; i += 256) ws[i] = wt[cog * 4 * 2304 + i];
    __syncthreads();
    int y = p / HW, x = p % HW;
    float a[4][2];
    #pragma unroll
    for (int j = 0; j < 4; j++) { a[j][0] = 0.f; a[j][1] = 0.f; }
    for (int ci = cig * 64; ci < cig * 64 + 64; ci += 2) {
        #pragma unroll
        for (int par = 0; par < 2; par++) {
            const float* ip = src + (ci + par) * NTOK;
            const float* wp = ws + (ci + par) * 9;
            #pragma unroll
            for (int dy = 0; dy < 3; dy++) {
                int yy = y + dy - 1; if ((unsigned)yy >= HW) continue;
                #pragma unroll
                for (int dx = 0; dx < 3; dx++) {
                    int xx = x + dx - 1; if ((unsigned)xx >= HW) continue;
                    float v = ip[yy * HW + xx]; int wi = dy * 3 + dx;
                    a[0][par] = fmaf(v, wp[wi],          a[0][par]);
                    a[1][par] = fmaf(v, wp[2304 + wi],   a[1][par]);
                    a[2][par] = fmaf(v, wp[4608 + wi],   a[2][par]);
                    a[3][par] = fmaf(v, wp[6912 + wi],   a[3][par]);
                }
            }
        }
    }
    #pragma unroll
    for (int j = 0; j < 4; j++) red[j * 256 + tid] = a[j][0] + a[j][1];
    __syncthreads();
    if (tid < 64) {
        #pragma unroll
        for (int j = 0; j < 4; j++) {
            float s = (red[j*256 + tid] + red[j*256 + tid + 64])
                    + (red[j*256 + tid + 128] + red[j*256 + tid + 192]);
            out[(cog*4+j)*NTOK + p] = fmaxf(s + bias[cog*4+j], 0.f);
        }
    }
}

__global__ __launch_bounds__(256) void conv2_kernel(
    const float* __restrict__ c1, const float* __restrict__ wt,
    const float* __restrict__ bias, float* __restrict__ gp)
{
    __shared__ float ws[1152];
    __shared__ float red[256];
    int co = blockIdx.x;
    int tid = threadIdx.x;
    int px = tid & 63, cig = tid >> 6;
    int p = blockIdx.y * 64 + px;
    for (int i = tid; i < 1152; i += 256) ws[i] = wt[co * 1152 + i];
    __syncthreads();
    int y = p / HW, x = p % HW;
    float a0 = 0.f, a1 = 0.f;
    for (int ci = cig * 32; ci < cig * 32 + 32; ci += 2) {
        #pragma unroll
        for (int dy = 0; dy < 3; dy++) {
            int yy = y + dy - 1; if ((unsigned)yy >= HW) continue;
            #pragma unroll
            for (int dx = 0; dx < 3; dx++) {
                int xx = x + dx - 1; if ((unsigned)xx >= HW) continue;
                int po = yy * HW + xx, wi = dy * 3 + dx;
                a0 = fmaf(c1[(ci+0) * NTOK + po], ws[(ci+0) * 9 + wi], a0);
                a1 = fmaf(c1[(ci+1) * NTOK + po], ws[(ci+1) * 9 + wi], a1);
            }
        }
    }
    red[tid] = a0 + a1;
    __syncthreads();
    if (tid < 64) {
        float a = bias[co] + (red[tid] + red[tid + 64]) + (red[tid + 128] + red[tid + 192]);
        gp[co * NTOK + p] = 1.0f / (1.0f + __expf(-a));
    }
}

// sq + zero fused
__global__ __launch_bounds__(256) void sq_kernel(const float* __restrict__ x,
                                                 float* __restrict__ sq,
                                                 int* __restrict__ nearp,
                                                 int* __restrict__ maxn)
{
    int row = blockIdx.x * 8 + (threadIdx.x >> 5);
    int lane = threadIdx.x & 31;
    const float* r = x + row * CDIM;
    float s = 0.f;
    #pragma unroll
    for (int i = 0; i < 8; i++) { float v = r[lane + i * 32]; s = fmaf(v, v, s); }
    #pragma unroll
    for (int o = 16; o; o >>= 1) s += __shfl_xor_sync(0xffffffffu, s, o);
    if (lane == 0) {
        sq[row] = s;
        nearp[row] = 0;
        if (row == 0) *maxn = 0;
    }
}

__global__ __launch_bounds__(256) void d2_tf32_kernel(
    const float* __restrict__ X, const float* __restrict__ sqv,
    float* __restrict__ C)
{
    __shared__ float As[128 * 36];
    __shared__ float Bs[128 * 36];
    const int tid = threadIdx.x;
    const int wid = tid >> 5, lane = tid & 31;
    const int warpM = wid >> 2, warpN = wid & 3;
    const int i0 = blockIdx.x * 128, j0 = blockIdx.y * 128;
    const int gid = lane >> 2, qid = lane & 3;

    float acc[4][4][4];
    #pragma unroll
    for (int a = 0; a < 4; a++)
        #pragma unroll
        for (int b = 0; b < 4; b++)
            #pragma unroll
            for (int c = 0; c < 4; c++) acc[a][b][c] = 0.f;

    const int lrow = tid >> 1;
    const int lk = (tid & 1) * 16;
    const float* Ag = X + (size_t)(i0 + lrow) * CDIM + lk;
    const float* Bg = X + (size_t)(j0 + lrow) * CDIM + lk;
    float* Asw = As + lrow * 36 + lk;
    float* Bsw = Bs + lrow * 36 + lk;

    for (int k0 = 0; k0 < CDIM; k0 += 32) {
        __syncthreads();
        #pragma unroll
        for (int q = 0; q < 4; q++) {
            float4 av = *(const float4*)(Ag + k0 + q * 4);
            float4 bv = *(const float4*)(Bg + k0 + q * 4);
            float4 at, bt;
            at.x = __uint_as_float(f2tf32(av.x)); at.y = __uint_as_float(f2tf32(av.y));
            at.z = __uint_as_float(f2tf32(av.z)); at.w = __uint_as_float(f2tf32(av.w));
            bt.x = __uint_as_float(f2tf32(bv.x)); bt.y = __uint_as_float(f2tf32(bv.y));
            bt.z = __uint_as_float(f2tf32(bv.z)); bt.w = __uint_as_float(f2tf32(bv.w));
            *(float4*)&Asw[q * 4] = at;
            *(float4*)&Bsw[q * 4] = bt;
        }
        __syncthreads();
        #pragma unroll
        for (int k8 = 0; k8 < 4; k8++) {
            unsigned af[4][4], bf[4][2];
            #pragma unroll
            for (int tm = 0; tm < 4; tm++) {
                const float* p = As + (warpM * 64 + tm * 16 + gid) * 36 + k8 * 8 + qid;
                af[tm][0] = __float_as_uint(p[0]);
                af[tm][1] = __float_as_uint(p[8 * 36]);
                af[tm][2] = __float_as_uint(p[4]);
                af[tm][3] = __float_as_uint(p[8 * 36 + 4]);
            }
            #pragma unroll
            for (int tn = 0; tn < 4; tn++) {
                const float* p = Bs + (warpN * 32 + tn * 8 + gid) * 36 + k8 * 8 + qid;
                bf[tn][0] = __float_as_uint(p[0]);
                bf[tn][1] = __float_as_uint(p[4]);
            }
            #pragma unroll
            for (int tm = 0; tm < 4; tm++)
                #pragma unroll
                for (int tn = 0; tn < 4; tn++)
                    mma_tf32(acc[tm][tn], af[tm][0], af[tm][1], af[tm][2], af[tm][3],
                             bf[tn][0], bf[tn][1]);
        }
    }

    #pragma unroll
    for (int tm = 0; tm < 4; tm++) {
        const int r0 = i0 + warpM * 64 + tm * 16 + gid;
        const float sr0 = sqv[r0], sr1 = sqv[r0 + 8];
        #pragma unroll
        for (int tn = 0; tn < 4; tn++) {
            const int c0i = j0 + warpN * 32 + tn * 8 + qid * 2;
            const float sc0 = sqv[c0i], sc1 = sqv[c0i + 1];
            float2 v0, v1;
            v0.x = sr0 + sc0 - 2.f * acc[tm][tn][0];
            v0.y = sr0 + sc1 - 2.f * acc[tm][tn][1];
            v1.x = sr1 + sc0 - 2.f * acc[tm][tn][2];
            v1.y = sr1 + sc1 - 2.f * acc[tm][tn][3];
            *(float2*)&C[(size_t)r0 * NPAD + c0i] = v0;
            *(float2*)&C[(size_t)(r0 + 8) * NPAD + c0i] = v1;
        }
    }
}

// single-pass tf32 64x64 GEMM body (shared by mma1_gemm and qkv_gemm)
template<int EPI>
__device__ __forceinline__ void gemm64(
    const float* __restrict__ A, const float* __restrict__ B,
    const float* __restrict__ bias, float* __restrict__ C,
    int Nn, int K, int i0, int j0)
{
    __shared__ float Ah[64 * 36], Bh[64 * 36];
    const int tid = threadIdx.x;
    const int wid = tid >> 5, lane = tid & 31;
    const int warpM = wid >> 1, warpN = wid & 1;
    const int gid = lane >> 2, qid = lane & 3;

    float acc[2][4][4];
    #pragma unroll
    for (int a = 0; a < 2; a++)
        #pragma unroll
        for (int b = 0; b < 4; b++)
            #pragma unroll
            for (int c = 0; c < 4; c++) acc[a][b][c] = 0.f;

    const int lrow = tid >> 1;
    const int lk = (tid & 1) * 16;
    const float* Ag = A + (size_t)(i0 + lrow) * K + lk;
    const float* Bg = B + (size_t)(j0 + lrow) * K + lk;
    const int sbase = lrow * 36 + lk;

    for (int k0 = 0; k0 < K; k0 += 32) {
        __syncthreads();
        #pragma unroll
        for (int q = 0; q < 4; q++) {
            float4 av = *(const float4*)(Ag + k0 + q * 4);
            float4 bv = *(const float4*)(Bg + k0 + q * 4);
            float4 at, bt;
            at.x = __uint_as_float(f2tf32(av.x)); at.y = __uint_as_float(f2tf32(av.y));
            at.z = __uint_as_float(f2tf32(av.z)); at.w = __uint_as_float(f2tf32(av.w));
            bt.x = __uint_as_float(f2tf32(bv.x)); bt.y = __uint_as_float(f2tf32(bv.y));
            bt.z = __uint_as_float(f2tf32(bv.z)); bt.w = __uint_as_float(f2tf32(bv.w));
            *(float4*)&Ah[sbase + q * 4] = at;
            *(float4*)&Bh[sbase + q * 4] = bt;
        }
        __syncthreads();
        #pragma unroll
        for (int k8 = 0; k8 < 4; k8++) {
            unsigned af[2][4], bf[4][2];
            #pragma unroll
            for (int tm = 0; tm < 2; tm++) {
                const int off = (warpM * 32 + tm * 16 + gid) * 36 + k8 * 8 + qid;
                af[tm][0] = __float_as_uint(Ah[off]);
                af[tm][1] = __float_as_uint(Ah[off + 8 * 36]);
                af[tm][2] = __float_as_uint(Ah[off + 4]);
                af[tm][3] = __float_as_uint(Ah[off + 8 * 36 + 4]);
            }
            #pragma unroll
            for (int tn = 0; tn < 4; tn++) {
                const int off = (warpN * 32 + tn * 8 + gid) * 36 + k8 * 8 + qid;
                bf[tn][0] = __float_as_uint(Bh[off]);
                bf[tn][1] = __float_as_uint(Bh[off + 4]);
            }
            #pragma unroll
            for (int tm = 0; tm < 2; tm++)
                #pragma unroll
                for (int tn = 0; tn < 4; tn++)
                    mma_tf32(acc[tm][tn], af[tm][0], af[tm][1], af[tm][2], af[tm][3],
                             bf[tn][0], bf[tn][1]);
        }
    }

    #pragma unroll
    for (int tm = 0; tm < 2; tm++) {
        const int r0 = i0 + warpM * 32 + tm * 16 + gid;
        #pragma unroll
        for (int tn = 0; tn < 4; tn++) {
            const int c0i = j0 + warpN * 32 + tn * 8 + qid * 2;
            const float b0 = bias[c0i], b1 = bias[c0i + 1];
            float2 v0, v1;
            v0.x = acc[tm][tn][0] + b0; v0.y = acc[tm][tn][1] + b1;
            v1.x = acc[tm][tn][2] + b0; v1.y = acc[tm][tn][3] + b1;
            if (EPI == 1) {
                v0.x = fmaxf(v0.x, 0.f); v0.y = fmaxf(v0.y, 0.f);
                v1.x = fmaxf(v1.x, 0.f); v1.y = fmaxf(v1.y, 0.f);
            }
            *(float2*)&C[(size_t)r0 * Nn + c0i] = v0;
            *(float2*)&C[(size_t)(r0 + 8) * Nn + c0i] = v1;
        }
    }
}

template<int EPI>
__global__ __launch_bounds__(128) void mma1_gemm(
    const float* __restrict__ A, const float* __restrict__ B,
    const float* __restrict__ bias, float* __restrict__ C,
    int Nn, int K)
{
    gemm64<EPI>(A, B, bias, C, Nn, K, blockIdx.x * 64, blockIdx.y * 64);
}

// fused Q/K/V projection: blockIdx.y 0-3 -> Q, 4-7 -> K, 8-11 -> V
__global__ __launch_bounds__(128) void qkv_gemm(
    const float* __restrict__ qkin, const float* __restrict__ x,
    const float* __restrict__ Wq, const float* __restrict__ Wk,
    const float* __restrict__ Wv,
    const float* __restrict__ bq, const float* __restrict__ bk,
    const float* __restrict__ bv,
    float* __restrict__ q, float* __restrict__ k, float* __restrict__ v)
{
    int sel = blockIdx.y >> 2, jb = blockIdx.y & 3;
    const float* A  = (sel == 2) ? x : qkin;
    const float* B  = (sel == 0) ? Wq : ((sel == 1) ? Wk : Wv);
    const float* bi = (sel == 0) ? bq : ((sel == 1) ? bk : bv);
    float* C        = (sel == 0) ? q  : ((sel == 1) ? k  : v);
    gemm64<0>(A, B, bi, C, CDIM, CDIM, blockIdx.x * 64, jb * 64);
}

__global__ __launch_bounds__(256) void topk_kernel(const float* __restrict__ d2,
                                                   int* __restrict__ nearp)
{
    __shared__ float vals[NTOK];
    __shared__ float wv[8];
    __shared__ int   wi[8];
    int row = blockIdx.x, tid = threadIdx.x;
    int lane = tid & 31, w = tid >> 5;
    const float* rp = d2 + (size_t)row * NPAD;
    for (int i = tid; i < NTOK; i += 256) vals[i] = rp[i];
    __syncthreads();
    for (int it = 0; it < TOPKK; it++) {
        float bv = 3.0e38f; int bi = 0x7FFFFFFF;
        for (int i = tid; i < NTOK; i += 256) {
            float v = vals[i];
            if (v < bv) { bv = v; bi = i; }
        }
        #pragma unroll
        for (int o = 16; o; o >>= 1) {
            float ov = __shfl_xor_sync(0xffffffffu, bv, o);
            int   oi = __shfl_xor_sync(0xffffffffu, bi, o);
            if (ov < bv || (ov == bv && oi < bi)) { bv = ov; bi = oi; }
        }
        if (lane == 0) { wv[w] = bv; wi[w] = bi; }
        __syncthreads();
        if (tid == 0) {
            float fv = wv[0]; int fi = wi[0];
            #pragma unroll
            for (int j = 1; j < 8; j++) {
                if (wv[j] < fv || (wv[j] == fv && wi[j] < fi)) { fv = wv[j]; fi = wi[j]; }
            }
            atomicAdd(&nearp[fi], 1);
            vals[fi] = 3.0e38f;
        }
        __syncthreads();
    }
}

__global__ __launch_bounds__(256) void maxnear_kernel(const int* __restrict__ nearp,
                                                      int* __restrict__ out)
{
    __shared__ int sm[256];
    int tid = threadIdx.x;
    int m = 0;
    for (int i = tid; i < NTOK; i += 256) m = max(m, nearp[i]);
    sm[tid] = m;
    __syncthreads();
    for (int s = 128; s > 0; s >>= 1) {
        if (tid < s) sm[tid] = max(sm[tid], sm[tid+s]);
        __syncthreads();
    }
    if (tid == 0) *out = sm[0];
}

__global__ void qkin_kernel(const float* __restrict__ x, const int* __restrict__ nearp,
                            const int* __restrict__ maxn, const float* __restrict__ emb,
                            float* __restrict__ out)
{
    int t = blockIdx.x, c = threadIdx.x;
    float nf = (float)nearp[t], mf = (float)(*maxn);
    int ni = (int)((nf / mf) * 9.0f);
    if (ni > 9) ni = 9;
    out[t * CDIM + c] = x[t * CDIM + c] + emb[ni * CDIM + c];
}

// Flash attention, tf32 mma: 128 queries/block, 8 warps, dynamic smem
__global__ __launch_bounds__(256) void attn_kernel(
    const float* __restrict__ Q, const float* __restrict__ Km,
    const float* __restrict__ V, const float* __restrict__ gp,
    float* __restrict__ O)
{
    extern __shared__ float sb[];
    float* Qs  = sb;            // 128*36 = 4608
    float* Ks  = sb + 4608;     // 64*36  = 2304
    float* Vts = sb + 6912;     // 32*68  = 2176
    float* Ps  = sb + 9088;     // 8*16*68 = 8704
    float* gks = sb + 17792;    // 64

    const int h = blockIdx.y, qb = blockIdx.x, tid = threadIdx.x;
    const int w = tid >> 5, lane = tid & 31;
    const int gid = lane >> 2, qid = lane & 3;
    const float scale = 0.17677669529663687f;

    for (int idx = tid; idx < 128 * 32; idx += 256) {
        int i = idx >> 5, d = idx & 31;
        float qv = Q[(size_t)(qb * 128 + i) * CDIM + h * 32 + d] * scale;
        Qs[i * 36 + d] = __uint_as_float(f2tf32(qv));
    }
    const int qr0 = qb * 128 + w * 16 + gid;
    const float gq0 = gp[h * NTOK + min(qr0, NTOK - 1)];
    const float gq1 = gp[h * NTOK + min(qr0 + 8, NTOK - 1)];

    float oacc[4][4];
    #pragma unroll
    for (int dt = 0; dt < 4; dt++)
        #pragma unroll
        for (int c = 0; c < 4; c++) oacc[dt][c] = 0.f;
    float m0 = -1e30f, m1 = -1e30f, l0 = 0.f, l1 = 0.f;
    float* Pw = Ps + w * (16 * 68);

    for (int kt = 0; kt < 49; kt++) {
        __syncthreads();
        for (int idx = tid; idx < 64 * 32; idx += 256) {
            int j = idx >> 5, d = idx & 31;
            size_t gbase = (size_t)(kt * 64 + j) * CDIM + h * 32 + d;
            Ks[j * 36 + d] = __uint_as_float(f2tf32(Km[gbase]));
            Vts[d * 68 + j] = __uint_as_float(f2tf32(V[gbase]));
        }
        if (tid < 64) gks[tid] = gp[h * NTOK + kt * 64 + tid];
        __syncthreads();

        float sc[8][4];
        #pragma unroll
        for (int tn = 0; tn < 8; tn++)
            #pragma unroll
            for (int c = 0; c < 4; c++) sc[tn][c] = 0.f;
        #pragma unroll
        for (int k8 = 0; k8 < 4; k8++) {
            const int aoff = (w * 16 + gid) * 36 + k8 * 8 + qid;
            unsigned a0 = __float_as_uint(Qs[aoff]);
            unsigned a1 = __float_as_uint(Qs[aoff + 8 * 36]);
            unsigned a2 = __float_as_uint(Qs[aoff + 4]);
            unsigned a3 = __float_as_uint(Qs[aoff + 8 * 36 + 4]);
            #pragma unroll
            for (int tn = 0; tn < 8; tn++) {
                const int boff = (tn * 8 + gid) * 36 + k8 * 8 + qid;
                mma_tf32(sc[tn], a0, a1, a2, a3,
                         __float_as_uint(Ks[boff]), __float_as_uint(Ks[boff + 4]));
            }
        }
        float mn0 = -1e30f, mn1 = -1e30f;
        #pragma unroll
        for (int tn = 0; tn < 8; tn++) {
            float ga = gks[tn * 8 + qid * 2], gb = gks[tn * 8 + qid * 2 + 1];
            sc[tn][0] += fabsf(gq0 - ga); sc[tn][1] += fabsf(gq0 - gb);
            sc[tn][2] += fabsf(gq1 - ga); sc[tn][3] += fabsf(gq1 - gb);
            mn0 = fmaxf(mn0, fmaxf(sc[tn][0], sc[tn][1]));
            mn1 = fmaxf(mn1, fmaxf(sc[tn][2], sc[tn][3]));
        }
        mn0 = fmaxf(mn0, __shfl_xor_sync(0xffffffffu, mn0, 1));
        mn0 = fmaxf(mn0, __shfl_xor_sync(0xffffffffu, mn0, 2));
        mn1 = fmaxf(mn1, __shfl_xor_sync(0xffffffffu, mn1, 1));
        mn1 = fmaxf(mn1, __shfl_xor_sync(0xffffffffu, mn1, 2));
        if (mn0 > m0) {
            float corr = fexp(m0 - mn0);
            l0 *= corr;
            #pragma unroll
            for (int dt = 0; dt < 4; dt++) { oacc[dt][0] *= corr; oacc[dt][1] *= corr; }
            m0 = mn0;
        }
        if (mn1 > m1) {
            float corr = fexp(m1 - mn1);
            l1 *= corr;
            #pragma unroll
            for (int dt = 0; dt < 4; dt++) { oacc[dt][2] *= corr; oacc[dt][3] *= corr; }
            m1 = mn1;
        }
        float ps0 = 0.f, ps1 = 0.f;
        #pragma unroll
        for (int tn = 0; tn < 8; tn++) {
            float p00 = fexp(sc[tn][0] - m0), p01 = fexp(sc[tn][1] - m0);
            float p10 = fexp(sc[tn][2] - m1), p11 = fexp(sc[tn][3] - m1);
            ps0 += p00 + p01; ps1 += p10 + p11;
            int col = tn * 8 + qid * 2;
            Pw[gid * 68 + col]       = __uint_as_float(f2tf32(p00));
            Pw[gid * 68 + col + 1]   = __uint_as_float(f2tf32(p01));
            Pw[(gid + 8) * 68 + col]     = __uint_as_float(f2tf32(p10));
            Pw[(gid + 8) * 68 + col + 1] = __uint_as_float(f2tf32(p11));
        }
        ps0 += __shfl_xor_sync(0xffffffffu, ps0, 1);
        ps0 += __shfl_xor_sync(0xffffffffu, ps0, 2);
        ps1 += __shfl_xor_sync(0xffffffffu, ps1, 1);
        ps1 += __shfl_xor_sync(0xffffffffu, ps1, 2);
        l0 += ps0; l1 += ps1;
        __syncwarp();
        #pragma unroll
        for (int k8 = 0; k8 < 8; k8++) {
            const int aoff = gid * 68 + k8 * 8 + qid;
            unsigned a0 = __float_as_uint(Pw[aoff]);
            unsigned a1 = __float_as_uint(Pw[aoff + 8 * 68]);
            unsigned a2 = __float_as_uint(Pw[aoff + 4]);
            unsigned a3 = __float_as_uint(Pw[aoff + 8 * 68 + 4]);
            #pragma unroll
            for (int dt = 0; dt < 4; dt++) {
                const int boff = (dt * 8 + gid) * 68 + k8 * 8 + qid;
                mma_tf32(oacc[dt], a0, a1, a2, a3,
                         __float_as_uint(Vts[boff]), __float_as_uint(Vts[boff + 4]));
            }
        }
        __syncwarp();
    }

    const float inv0 = 1.f / l0, inv1 = 1.f / l1;
    #pragma unroll
    for (int dt = 0; dt < 4; dt++) {
        const int col = h * 32 + dt * 8 + qid * 2;
        float2 v0, v1;
        v0.x = oacc[dt][0] * inv0; v0.y = oacc[dt][1] * inv0;
        v1.x = oacc[dt][2] * inv1; v1.y = oacc[dt][3] * inv1;
        *(float2*)&O[(size_t)qr0 * CDIM + col] = v0;
        *(float2*)&O[(size_t)(qr0 + 8) * CDIM + col] = v1;
    }
}

template<int FINAL>
__global__ __launch_bounds__(256) void add_ln_kernel(
    const float* __restrict__ a, const float* __restrict__ b,
    const float* __restrict__ g, const float* __restrict__ be,
    float* __restrict__ out)
{
    __shared__ float red[8];
    int row = blockIdx.x, tid = threadIdx.x;
    float v = a[row * CDIM + tid];
    if (!FINAL) v += b[row * CDIM + tid];
    float s = v;
    #pragma unroll
    for (int o = 16; o; o >>= 1) s += __shfl_xor_sync(0xffffffffu, s, o);
    if ((tid & 31) == 0) red[tid >> 5] = s;
    __syncthreads();
    float mean = 0.f;
    #pragma unroll
    for (int i = 0; i < 8; i++) mean += red[i];
    mean *= (1.f / 256.f);
    float d = v - mean;
    __syncthreads();
    s = d * d;
    #pragma unroll
    for (int o = 16; o; o >>= 1) s += __shfl_xor_sync(0xffffffffu, s, o);
    if ((tid & 31) == 0) red[tid >> 5] = s;
    __syncthreads();
    float var = 0.f;
    #pragma unroll
    for (int i = 0; i < 8; i++) var += red[i];
    var *= (1.f / 256.f);
    float r = d * rsqrtf(var + 1e-5f) * g[tid] + be[tid];
    if (FINAL) out[tid * NTOK + row] = r;
    else       out[row * CDIM + tid] = r;
}

extern "C" void kernel_launch(void* const* d_in, const int* in_sizes, int n_in,
                              void* d_out, int out_size)
{
    (void)in_sizes; (void)n_in; (void)out_size;
    const float* src  = (const float*)d_in[0];
    const float* c1w  = (const float*)d_in[1];
    const float* c1b  = (const float*)d_in[2];
    const float* c2w  = (const float*)d_in[3];
    const float* c2b  = (const float*)d_in[4];
    const float* nemb = (const float*)d_in[5];
    const float* Wq   = (const float*)d_in[6];
    const float* bq   = (const float*)d_in[7];
    const float* Wk   = (const float*)d_in[8];
    const float* bk   = (const float*)d_in[9];
    const float* Wv   = (const float*)d_in[10];
    const float* bv   = (const float*)d_in[11];
    const float* Wo   = (const float*)d_in[12];
    const float* bo   = (const float*)d_in[13];
    const float* W1   = (const float*)d_in[14];
    const float* b1   = (const float*)d_in[15];
    const float* W2   = (const float*)d_in[16];
    const float* b2   = (const float*)d_in[17];
    const float* ln1g = (const float*)d_in[18];
    const float* ln1b = (const float*)d_in[19];
    const float* ln2g = (const float*)d_in[20];
    const float* ln2b = (const float*)d_in[21];
    const float* ng   = (const float*)d_in[22];
    const float* nb   = (const float*)d_in[23];

    float *c1, *gp, *x, *sqv, *d2, *qkin, *q, *k, *v, *att, *ffh, *yb;
    int *nearp, *maxn;
    cudaGetSymbolAddress((void**)&c1,    g_c1);
    cudaGetSymbolAddress((void**)&gp,    g_gp);
    cudaGetSymbolAddress((void**)&x,     g_x);
    cudaGetSymbolAddress((void**)&sqv,   g_sq);
    cudaGetSymbolAddress((void**)&d2,    g_d2);
    cudaGetSymbolAddress((void**)&nearp, g_near);
    cudaGetSymbolAddress((void**)&maxn,  g_maxnear);
    cudaGetSymbolAddress((void**)&qkin,  g_qkin);
    cudaGetSymbolAddress((void**)&q,     g_q);
    cudaGetSymbolAddress((void**)&k,     g_k);
    cudaGetSymbolAddress((void**)&v,     g_v);
    cudaGetSymbolAddress((void**)&att,   g_att);
    cudaGetSymbolAddress((void**)&ffh,   g_ffh);
    cudaGetSymbolAddress((void**)&yb,    g_y);

    cudaFuncSetAttribute(attn_kernel, cudaFuncAttributeMaxDynamicSharedMemorySize,
                         ATTN_SMEM);

    pad_kernel<<<64, 256>>>(x, sqv);
    transpose_kernel<<<dim3(98, 8), dim3(32, 32)>>>(src, x);
    conv1_kernel<<<dim3(32, 49), 256>>>(src, c1w, c1b, c1);
    conv2_kernel<<<dim3(8, 49), 256>>>(c1, c2w, c2b, gp);

    for (int i = 0; i < NLAYER; i++) {
        sq_kernel<<<392, 256>>>(x, sqv, nearp, maxn);
        d2_tf32_kernel<<<dim3(25, 25), 256>>>(x, sqv, d2);
        topk_kernel<<<NTOK, 256>>>(d2, nearp);
        maxnear_kernel<<<1, 256>>>(nearp, maxn);
        qkin_kernel<<<NTOK, 256>>>(x, nearp, maxn, nemb, qkin);

        qkv_gemm<<<dim3(50, 12), 128>>>(qkin, x,
            Wq + i*CDIM*CDIM, Wk + i*CDIM*CDIM, Wv + i*CDIM*CDIM,
            bq + i*CDIM, bk + i*CDIM, bv + i*CDIM, q, k, v);

        attn_kernel<<<dim3(25, NHEAD), 256, ATTN_SMEM>>>(q, k, v, gp, att);

        mma1_gemm<0><<<dim3(50, 4), 128>>>(att, Wo + i*CDIM*CDIM, bo + i*CDIM, yb, CDIM, CDIM);
        add_ln_kernel<0><<<NTOK, 256>>>(x, yb, ln1g + i*CDIM, ln1b + i*CDIM, x);

        mma1_gemm<1><<<dim3(50, 16), 128>>>(x, W1 + i*DFFN*CDIM, b1 + i*DFFN, ffh, DFFN, CDIM);
        mma1_gemm<0><<<dim3(50, 4), 128>>>(ffh, W2 + i*CDIM*DFFN, b2 + i*CDIM, yb, CDIM, DFFN);
        add_ln_kernel<0><<<NTOK, 256>>>(x, yb, ln2g + i*CDIM, ln2b + i*CDIM, x);
    }

    add_ln_kernel<1><<<NTOK, 256>>>(x, nullptr, ng, nb, (float*)d_out);
}

// round 13
// speedup vs baseline: 1.0590x; 1.0590x over previous
#include <cuda_runtime.h>
#include <cuda_bf16.h>
#include <cstdint>
#include <math.h>

#define NTOK 3136
#define NPAD 3200
#define CDIM 256
#define NHEAD 8
#define DFFN 1024
#define NLAYER 4
#define TOPKK 16
#define HW 56

__device__ float g_c1[128 * NTOK];
__device__ float g_gp[NHEAD * NTOK];
__device__ float g_x[NPAD * CDIM];
__device__ float g_sq[NPAD];
__device__ float g_d2[(size_t)NPAD * NPAD];
__device__ int   g_near[NTOK];
__device__ int   g_maxnear[1];
__device__ int   g_ni[NPAD];
__device__ float g_q[NPAD * CDIM];
__device__ float g_k[NPAD * CDIM];
__device__ float g_v[NPAD * CDIM];
__device__ float g_att[NPAD * CDIM];
__device__ float g_ffh[(size_t)NPAD * DFFN];
__device__ float g_y[NPAD * CDIM];

__device__ __forceinline__ float fexp(float x) {
    x = fmaxf(x, -87.0f);
    float y = x * 1.44269504088896341f;
    float r = rintf(y);
    float f = y - r;
    float p = 1.33335581e-3f;
    p = fmaf(p, f, 9.61812911e-3f);
    p = fmaf(p, f, 5.55041087e-2f);
    p = fmaf(p, f, 2.40226507e-1f);
    p = fmaf(p, f, 6.93147181e-1f);
    p = fmaf(p, f, 1.0f);
    return __int_as_float(__float_as_int(p) + (((int)r) << 23));
}

__device__ __forceinline__ unsigned f2tf32(float v) {
    unsigned r;
    asm("cvt.rna.tf32.f32 %0, %1;" : "=r"(r) : "f"(v));
    return r;
}

__device__ __forceinline__ void mma_tf32(float c[4],
    unsigned a0, unsigned a1, unsigned a2, unsigned a3,
    unsigned b0, unsigned b1)
{
    asm volatile(
        "mma.sync.aligned.m16n8k8.row.col.f32.tf32.tf32.f32 "
        "{%0,%1,%2,%3}, {%4,%5,%6,%7}, {%8,%9}, {%0,%1,%2,%3};\n"
        : "+f"(c[0]), "+f"(c[1]), "+f"(c[2]), "+f"(c[3])
        : "r"(a0), "r"(a1), "r"(a2), "r"(a3), "r"(b0), "r"(b1));
}

__global__ void pad_kernel(float* __restrict__ x, float* __restrict__ sqv) {
    int i = blockIdx.x * 256 + threadIdx.x;
    x[NTOK * CDIM + i] = 0.f;
    if (i < NPAD - NTOK) sqv[NTOK + i] = 0.f;
}

__global__ void transpose_kernel(const float* __restrict__ src, float* __restrict__ dst) {
    __shared__ float tile[32][33];
    int t0 = blockIdx.x * 32, c0 = blockIdx.y * 32;
    int tx = threadIdx.x, ty = threadIdx.y;
    tile[ty][tx] = src[(c0 + ty) * NTOK + t0 + tx];
    __syncthreads();
    dst[(t0 + ty) * CDIM + c0 + tx] = tile[tx][ty];
}

__global__ __launch_bounds__(256) void conv1_kernel(
    const float* __restrict__ src, const float* __restrict__ wt,
    const float* __restrict__ bias, float* __restrict__ out)
{
    __shared__ float ws[4 * 2304];
    __shared__ float red[4 * 256];
    int cog = blockIdx.x;
    int tid = threadIdx.x;
    int px = tid & 63, cig = tid >> 6;
    int p = blockIdx.y * 64 + px;
    for (int i = tid; i < 4 * 2304; i += 256) ws[i] = wt[cog * 4 * 2304 + i];
    __syncthreads();
    int y = p / HW, x = p % HW;
    float a[4][2];
    #pragma unroll
    for (int j = 0; j < 4; j++) { a[j][0] = 0.f; a[j][1] = 0.f; }
    for (int ci = cig * 64; ci < cig * 64 + 64; ci += 2) {
        #pragma unroll
        for (int par = 0; par < 2; par++) {
            const float* ip = src + (ci + par) * NTOK;
            const float* wp = ws + (ci + par) * 9;
            #pragma unroll
            for (int dy = 0; dy < 3; dy++) {
                int yy = y + dy - 1; if ((unsigned)yy >= HW) continue;
                #pragma unroll
                for (int dx = 0; dx < 3; dx++) {
                    int xx = x + dx - 1; if ((unsigned)xx >= HW) continue;
                    float v = ip[yy * HW + xx]; int wi = dy * 3 + dx;
                    a[0][par] = fmaf(v, wp[wi],          a[0][par]);
                    a[1][par] = fmaf(v, wp[2304 + wi],   a[1][par]);
                    a[2][par] = fmaf(v, wp[4608 + wi],   a[2][par]);
                    a[3][par] = fmaf(v, wp[6912 + wi],   a[3][par]);
                }
            }
        }
    }
    #pragma unroll
    for (int j = 0; j < 4; j++) red[j * 256 + tid] = a[j][0] + a[j][1];
    __syncthreads();
    if (tid < 64) {
        #pragma unroll
        for (int j = 0; j < 4; j++) {
            float s = (red[j*256 + tid] + red[j*256 + tid + 64])
                    + (red[j*256 + tid + 128] + red[j*256 + tid + 192]);
            out[(cog*4+j)*NTOK + p] = fmaxf(s + bias[cog*4+j], 0.f);
        }
    }
}

__global__ __launch_bounds__(256) void conv2_kernel(
    const float* __restrict__ c1, const float* __restrict__ wt,
    const float* __restrict__ bias, float* __restrict__ gp)
{
    __shared__ float ws[1152];
    __shared__ float red[256];
    int co = blockIdx.x;
    int tid = threadIdx.x;
    int px = tid & 63, cig = tid >> 6;
    int p = blockIdx.y * 64 + px;
    for (int i = tid; i < 1152; i += 256) ws[i] = wt[co * 1152 + i];
    __syncthreads();
    int y = p / HW, x = p % HW;
    float a0 = 0.f, a1 = 0.f;
    for (int ci = cig * 32; ci < cig * 32 + 32; ci += 2) {
        #pragma unroll
        for (int dy = 0; dy < 3; dy++) {
            int yy = y + dy - 1; if ((unsigned)yy >= HW) continue;
            #pragma unroll
            for (int dx = 0; dx < 3; dx++) {
                int xx = x + dx - 1; if ((unsigned)xx >= HW) continue;
                int po = yy * HW + xx, wi = dy * 3 + dx;
                a0 = fmaf(c1[(ci+0) * NTOK + po], ws[(ci+0) * 9 + wi], a0);
                a1 = fmaf(c1[(ci+1) * NTOK + po], ws[(ci+1) * 9 + wi], a1);
            }
        }
    }
    red[tid] = a0 + a1;
    __syncthreads();
    if (tid < 64) {
        float a = bias[co] + (red[tid] + red[tid + 64]) + (red[tid + 128] + red[tid + 192]);
        gp[co * NTOK + p] = 1.0f / (1.0f + __expf(-a));
    }
}

__global__ __launch_bounds__(256) void sq_kernel(const float* __restrict__ x,
                                                 float* __restrict__ sq,
                                                 int* __restrict__ nearp,
                                                 int* __restrict__ maxn)
{
    int row = blockIdx.x * 8 + (threadIdx.x >> 5);
    int lane = threadIdx.x & 31;
    const float* r = x + row * CDIM;
    float s = 0.f;
    #pragma unroll
    for (int i = 0; i < 8; i++) { float v = r[lane + i * 32]; s = fmaf(v, v, s); }
    #pragma unroll
    for (int o = 16; o; o >>= 1) s += __shfl_xor_sync(0xffffffffu, s, o);
    if (lane == 0) {
        sq[row] = s;
        if (row < NTOK) nearp[row] = 0;
        if (row == 0) *maxn = 0;
    }
}

__global__ __launch_bounds__(256) void d2_tf32_kernel(
    const float* __restrict__ X, const float* __restrict__ sqv,
    float* __restrict__ C)
{
    __shared__ float As[128 * 36];
    __shared__ float Bs[128 * 36];
    const int tid = threadIdx.x;
    const int wid = tid >> 5, lane = tid & 31;
    const int warpM = wid >> 2, warpN = wid & 3;
    const int i0 = blockIdx.x * 128, j0 = blockIdx.y * 128;
    const int gid = lane >> 2, qid = lane & 3;

    float acc[4][4][4];
    #pragma unroll
    for (int a = 0; a < 4; a++)
        #pragma unroll
        for (int b = 0; b < 4; b++)
            #pragma unroll
            for (int c = 0; c < 4; c++) acc[a][b][c] = 0.f;

    const int lrow = tid >> 1;
    const int lk = (tid & 1) * 16;
    const float* Ag = X + (size_t)(i0 + lrow) * CDIM + lk;
    const float* Bg = X + (size_t)(j0 + lrow) * CDIM + lk;
    float* Asw = As + lrow * 36 + lk;
    float* Bsw = Bs + lrow * 36 + lk;

    for (int k0 = 0; k0 < CDIM; k0 += 32) {
        __syncthreads();
        #pragma unroll
        for (int q = 0; q < 4; q++) {
            float4 av = *(const float4*)(Ag + k0 + q * 4);
            float4 bv = *(const float4*)(Bg + k0 + q * 4);
            float4 at, bt;
            at.x = __uint_as_float(f2tf32(av.x)); at.y = __uint_as_float(f2tf32(av.y));
            at.z = __uint_as_float(f2tf32(av.z)); at.w = __uint_as_float(f2tf32(av.w));
            bt.x = __uint_as_float(f2tf32(bv.x)); bt.y = __uint_as_float(f2tf32(bv.y));
            bt.z = __uint_as_float(f2tf32(bv.z)); bt.w = __uint_as_float(f2tf32(bv.w));
            *(float4*)&Asw[q * 4] = at;
            *(float4*)&Bsw[q * 4] = bt;
        }
        __syncthreads();
        #pragma unroll
        for (int k8 = 0; k8 < 4; k8++) {
            unsigned af[4][4], bf[4][2];
            #pragma unroll
            for (int tm = 0; tm < 4; tm++) {
                const float* p = As + (warpM * 64 + tm * 16 + gid) * 36 + k8 * 8 + qid;
                af[tm][0] = __float_as_uint(p[0]);
                af[tm][1] = __float_as_uint(p[8 * 36]);
                af[tm][2] = __float_as_uint(p[4]);
                af[tm][3] = __float_as_uint(p[8 * 36 + 4]);
            }
            #pragma unroll
            for (int tn = 0; tn < 4; tn++) {
                const float* p = Bs + (warpN * 32 + tn * 8 + gid) * 36 + k8 * 8 + qid;
                bf[tn][0] = __float_as_uint(p[0]);
                bf[tn][1] = __float_as_uint(p[4]);
            }
            #pragma unroll
            for (int tm = 0; tm < 4; tm++)
                #pragma unroll
                for (int tn = 0; tn < 4; tn++)
                    mma_tf32(acc[tm][tn], af[tm][0], af[tm][1], af[tm][2], af[tm][3],
                             bf[tn][0], bf[tn][1]);
        }
    }

    #pragma unroll
    for (int tm = 0; tm < 4; tm++) {
        const int r0 = i0 + warpM * 64 + tm * 16 + gid;
        const float sr0 = sqv[r0], sr1 = sqv[r0 + 8];
        #pragma unroll
        for (int tn = 0; tn < 4; tn++) {
            const int c0i = j0 + warpN * 32 + tn * 8 + qid * 2;
            const float sc0 = sqv[c0i], sc1 = sqv[c0i + 1];
            float2 v0, v1;
            v0.x = sr0 + sc0 - 2.f * acc[tm][tn][0];
            v0.y = sr0 + sc1 - 2.f * acc[tm][tn][1];
            v1.x = sr1 + sc0 - 2.f * acc[tm][tn][2];
            v1.y = sr1 + sc1 - 2.f * acc[tm][tn][3];
            *(float2*)&C[(size_t)r0 * NPAD + c0i] = v0;
            *(float2*)&C[(size_t)(r0 + 8) * NPAD + c0i] = v1;
        }
    }
}

// single-pass tf32 64x64 GEMM body; ADDEMB: A[row][k] += emb[ni[row]][k]
template<int EPI, int ADDEMB>
__device__ __forceinline__ void gemm64(
    const float* __restrict__ A, const float* __restrict__ B,
    const float* __restrict__ bias, float* __restrict__ C,
    int Nn, int K, int i0, int j0,
    const int* __restrict__ ni, const float* __restrict__ emb)
{
    __shared__ float Ah[64 * 36], Bh[64 * 36];
    const int tid = threadIdx.x;
    const int wid = tid >> 5, lane = tid & 31;
    const int warpM = wid >> 1, warpN = wid & 1;
    const int gid = lane >> 2, qid = lane & 3;

    float acc[2][4][4];
    #pragma unroll
    for (int a = 0; a < 2; a++)
        #pragma unroll
        for (int b = 0; b < 4; b++)
            #pragma unroll
            for (int c = 0; c < 4; c++) acc[a][b][c] = 0.f;

    const int lrow = tid >> 1;
    const int lk = (tid & 1) * 16;
    const float* Ag = A + (size_t)(i0 + lrow) * K + lk;
    const float* Bg = B + (size_t)(j0 + lrow) * K + lk;
    const float* Eg = ADDEMB ? (emb + (size_t)ni[i0 + lrow] * CDIM + lk) : nullptr;
    const int sbase = lrow * 36 + lk;

    for (int k0 = 0; k0 < K; k0 += 32) {
        __syncthreads();
        #pragma unroll
        for (int q = 0; q < 4; q++) {
            float4 av = *(const float4*)(Ag + k0 + q * 4);
            float4 bv = *(const float4*)(Bg + k0 + q * 4);
            if (ADDEMB) {
                float4 ev = *(const float4*)(Eg + k0 + q * 4);
                av.x += ev.x; av.y += ev.y; av.z += ev.z; av.w += ev.w;
            }
            float4 at, bt;
            at.x = __uint_as_float(f2tf32(av.x)); at.y = __uint_as_float(f2tf32(av.y));
            at.z = __uint_as_float(f2tf32(av.z)); at.w = __uint_as_float(f2tf32(av.w));
            bt.x = __uint_as_float(f2tf32(bv.x)); bt.y = __uint_as_float(f2tf32(bv.y));
            bt.z = __uint_as_float(f2tf32(bv.z)); bt.w = __uint_as_float(f2tf32(bv.w));
            *(float4*)&Ah[sbase + q * 4] = at;
            *(float4*)&Bh[sbase + q * 4] = bt;
        }
        __syncthreads();
        #pragma unroll
        for (int k8 = 0; k8 < 4; k8++) {
            unsigned af[2][4], bf[4][2];
            #pragma unroll
            for (int tm = 0; tm < 2; tm++) {
                const int off = (warpM * 32 + tm * 16 + gid) * 36 + k8 * 8 + qid;
                af[tm][0] = __float_as_uint(Ah[off]);
                af[tm][1] = __float_as_uint(Ah[off + 8 * 36]);
                af[tm][2] = __float_as_uint(Ah[off + 4]);
                af[tm][3] = __float_as_uint(Ah[off + 8 * 36 + 4]);
            }
            #pragma unroll
            for (int tn = 0; tn < 4; tn++) {
                const int off = (warpN * 32 + tn * 8 + gid) * 36 + k8 * 8 + qid;
                bf[tn][0] = __float_as_uint(Bh[off]);
                bf[tn][1] = __float_as_uint(Bh[off + 4]);
            }
            #pragma unroll
            for (int tm = 0; tm < 2; tm++)
                #pragma unroll
                for (int tn = 0; tn < 4; tn++)
                    mma_tf32(acc[tm][tn], af[tm][0], af[tm][1], af[tm][2], af[tm][3],
                             bf[tn][0], bf[tn][1]);
        }
    }

    #pragma unroll
    for (int tm = 0; tm < 2; tm++) {
        const int r0 = i0 + warpM * 32 + tm * 16 + gid;
        #pragma unroll
        for (int tn = 0; tn < 4; tn++) {
            const int c0i = j0 + warpN * 32 + tn * 8 + qid * 2;
            const float b0 = bias[c0i], b1 = bias[c0i + 1];
            float2 v0, v1;
            v0.x = acc[tm][tn][0] + b0; v0.y = acc[tm][tn][1] + b1;
            v1.x = acc[tm][tn][2] + b0; v1.y = acc[tm][tn][3] + b1;
            if (EPI == 1) {
                v0.x = fmaxf(v0.x, 0.f); v0.y = fmaxf(v0.y, 0.f);
                v1.x = fmaxf(v1.x, 0.f); v1.y = fmaxf(v1.y, 0.f);
            }
            *(float2*)&C[(size_t)r0 * Nn + c0i] = v0;
            *(float2*)&C[(size_t)(r0 + 8) * Nn + c0i] = v1;
        }
    }
}

template<int EPI>
__global__ __launch_bounds__(128) void mma1_gemm(
    const float* __restrict__ A, const float* __restrict__ B,
    const float* __restrict__ bias, float* __restrict__ C,
    int Nn, int K)
{
    gemm64<EPI, 0>(A, B, bias, C, Nn, K, blockIdx.x * 64, blockIdx.y * 64,
                   nullptr, nullptr);
}

// fused QKV: blockIdx.y 0-3 -> Q(x+emb), 4-7 -> K(x+emb), 8-11 -> V(x)
__global__ __launch_bounds__(128) void qkv_gemm(
    const float* __restrict__ x, const int* __restrict__ ni,
    const float* __restrict__ emb,
    const float* __restrict__ Wq, const float* __restrict__ Wk,
    const float* __restrict__ Wv,
    const float* __restrict__ bq, const float* __restrict__ bk,
    const float* __restrict__ bv,
    float* __restrict__ q, float* __restrict__ k, float* __restrict__ v)
{
    int sel = blockIdx.y >> 2, jb = blockIdx.y & 3;
    if (sel == 2) {
        gemm64<0, 0>(x, Wv, bv, v, CDIM, CDIM, blockIdx.x * 64, jb * 64,
                     nullptr, nullptr);
    } else if (sel == 0) {
        gemm64<0, 1>(x, Wq, bq, q, CDIM, CDIM, blockIdx.x * 64, jb * 64, ni, emb);
    } else {
        gemm64<0, 1>(x, Wk, bk, k, CDIM, CDIM, blockIdx.x * 64, jb * 64, ni, emb);
    }
}

__global__ __launch_bounds__(256) void topk_kernel(const float* __restrict__ d2,
                                                   int* __restrict__ nearp)
{
    __shared__ float vals[NTOK];
    __shared__ float wv[8];
    __shared__ int   wi[8];
    int row = blockIdx.x, tid = threadIdx.x;
    int lane = tid & 31, w = tid >> 5;
    const float* rp = d2 + (size_t)row * NPAD;
    for (int i = tid; i < NTOK; i += 256) vals[i] = rp[i];
    __syncthreads();
    for (int it = 0; it < TOPKK; it++) {
        float bv = 3.0e38f; int bi = 0x7FFFFFFF;
        for (int i = tid; i < NTOK; i += 256) {
            float v = vals[i];
            if (v < bv) { bv = v; bi = i; }
        }
        #pragma unroll
        for (int o = 16; o; o >>= 1) {
            float ov = __shfl_xor_sync(0xffffffffu, bv, o);
            int   oi = __shfl_xor_sync(0xffffffffu, bi, o);
            if (ov < bv || (ov == bv && oi < bi)) { bv = ov; bi = oi; }
        }
        if (lane == 0) { wv[w] = bv; wi[w] = bi; }
        __syncthreads();
        if (w == 0) {
            float fv = (lane < 8) ? wv[lane] : 3.0e38f;
            int   fi = (lane < 8) ? wi[lane] : 0x7FFFFFFF;
            #pragma unroll
            for (int o = 4; o; o >>= 1) {
                float ov = __shfl_xor_sync(0xffffffffu, fv, o);
                int   oi = __shfl_xor_sync(0xffffffffu, fi, o);
                if (ov < fv || (ov == fv && oi < fi)) { fv = ov; fi = oi; }
            }
            if (lane == 0) {
                atomicAdd(&nearp[fi], 1);
                vals[fi] = 3.0e38f;
            }
        }
        __syncthreads();
    }
}

__global__ __launch_bounds__(256) void maxnear_kernel(const int* __restrict__ nearp,
                                                      int* __restrict__ out)
{
    __shared__ int sm[256];
    int tid = threadIdx.x;
    int m = 0;
    for (int i = tid; i < NTOK; i += 256) m = max(m, nearp[i]);
    sm[tid] = m;
    __syncthreads();
    for (int s = 128; s > 0; s >>= 1) {
        if (tid < s) sm[tid] = max(sm[tid], sm[tid+s]);
        __syncthreads();
    }
    if (tid == 0) *out = sm[0];
}

__global__ void ni_kernel(const int* __restrict__ nearp, const int* __restrict__ maxn,
                          int* __restrict__ ni)
{
    int i = blockIdx.x * 256 + threadIdx.x;
    if (i >= NPAD) return;
    int r = 0;
    if (i < NTOK) {
        float nf = (float)nearp[i], mf = (float)(*maxn);
        r = (int)((nf / mf) * 9.0f);
        if (r > 9) r = 9;
    }
    ni[i] = r;
}

// Flash attention, tf32 mma (round-11 winner: 64 queries, 128 threads, 392 blocks)
__global__ __launch_bounds__(128) void attn_kernel(
    const float* __restrict__ Q, const float* __restrict__ Km,
    const float* __restrict__ V, const float* __restrict__ gp,
    float* __restrict__ O)
{
    __shared__ float Qs[64 * 36];
    __shared__ float Ks[64 * 36];
    __shared__ float Vts[32 * 68];
    __shared__ float Ps[4 * 16 * 68];
    __shared__ float gks[64];

    const int h = blockIdx.y, qb = blockIdx.x, tid = threadIdx.x;
    const int w = tid >> 5, lane = tid & 31;
    const int gid = lane >> 2, qid = lane & 3;
    const float scale = 0.17677669529663687f;

    for (int idx = tid; idx < 64 * 32; idx += 128) {
        int i = idx >> 5, d = idx & 31;
        float qv = Q[(size_t)(qb * 64 + i) * CDIM + h * 32 + d] * scale;
        Qs[i * 36 + d] = __uint_as_float(f2tf32(qv));
    }
    const float gq0 = gp[h * NTOK + qb * 64 + w * 16 + gid];
    const float gq1 = gp[h * NTOK + qb * 64 + w * 16 + gid + 8];

    float oacc[4][4];
    #pragma unroll
    for (int dt = 0; dt < 4; dt++)
        #pragma unroll
        for (int c = 0; c < 4; c++) oacc[dt][c] = 0.f;
    float m0 = -1e30f, m1 = -1e30f, l0 = 0.f, l1 = 0.f;
    float* Pw = Ps + w * (16 * 68);

    for (int kt = 0; kt < 49; kt++) {
        __syncthreads();
        for (int idx = tid; idx < 64 * 32; idx += 128) {
            int j = idx >> 5, d = idx & 31;
            size_t gbase = (size_t)(kt * 64 + j) * CDIM + h * 32 + d;
            Ks[j * 36 + d] = __uint_as_float(f2tf32(Km[gbase]));
            Vts[d * 68 + j] = __uint_as_float(f2tf32(V[gbase]));
        }
        if (tid < 64) gks[tid] = gp[h * NTOK + kt * 64 + tid];
        __syncthreads();

        float sc[8][4];
        #pragma unroll
        for (int tn = 0; tn < 8; tn++)
            #pragma unroll
            for (int c = 0; c < 4; c++) sc[tn][c] = 0.f;
        #pragma unroll
        for (int k8 = 0; k8 < 4; k8++) {
            const int aoff = (w * 16 + gid) * 36 + k8 * 8 + qid;
            unsigned a0 = __float_as_uint(Qs[aoff]);
            unsigned a1 = __float_as_uint(Qs[aoff + 8 * 36]);
            unsigned a2 = __float_as_uint(Qs[aoff + 4]);
            unsigned a3 = __float_as_uint(Qs[aoff + 8 * 36 + 4]);
            #pragma unroll
            for (int tn = 0; tn < 8; tn++) {
                const int boff = (tn * 8 + gid) * 36 + k8 * 8 + qid;
                mma_tf32(sc[tn], a0, a1, a2, a3,
                         __float_as_uint(Ks[boff]), __float_as_uint(Ks[boff + 4]));
            }
        }
        float mn0 = -1e30f, mn1 = -1e30f;
        #pragma unroll
        for (int tn = 0; tn < 8; tn++) {
            float ga = gks[tn * 8 + qid * 2], gb = gks[tn * 8 + qid * 2 + 1];
            sc[tn][0] += fabsf(gq0 - ga); sc[tn][1] += fabsf(gq0 - gb);
            sc[tn][2] += fabsf(gq1 - ga); sc[tn][3] += fabsf(gq1 - gb);
            mn0 = fmaxf(mn0, fmaxf(sc[tn][0], sc[tn][1]));
            mn1 = fmaxf(mn1, fmaxf(sc[tn][2], sc[tn][3]));
        }
        mn0 = fmaxf(mn0, __shfl_xor_sync(0xffffffffu, mn0, 1));
        mn0 = fmaxf(mn0, __shfl_xor_sync(0xffffffffu, mn0, 2));
        mn1 = fmaxf(mn1, __shfl_xor_sync(0xffffffffu, mn1, 1));
        mn1 = fmaxf(mn1, __shfl_xor_sync(0xffffffffu, mn1, 2));
        if (mn0 > m0) {
            float corr = fexp(m0 - mn0);
            l0 *= corr;
            #pragma unroll
            for (int dt = 0; dt < 4; dt++) { oacc[dt][0] *= corr; oacc[dt][1] *= corr; }
            m0 = mn0;
        }
        if (mn1 > m1) {
            float corr = fexp(m1 - mn1);
            l1 *= corr;
            #pragma unroll
            for (int dt = 0; dt < 4; dt++) { oacc[dt][2] *= corr; oacc[dt][3] *= corr; }
            m1 = mn1;
        }
        float ps0 = 0.f, ps1 = 0.f;
        #pragma unroll
        for (int tn = 0; tn < 8; tn++) {
            float p00 = fexp(sc[tn][0] - m0), p01 = fexp(sc[tn][1] - m0);
            float p10 = fexp(sc[tn][2] - m1), p11 = fexp(sc[tn][3] - m1);
            ps0 += p00 + p01; ps1 += p10 + p11;
            int col = tn * 8 + qid * 2;
            Pw[gid * 68 + col]       = __uint_as_float(f2tf32(p00));
            Pw[gid * 68 + col + 1]   = __uint_as_float(f2tf32(p01));
            Pw[(gid + 8) * 68 + col]     = __uint_as_float(f2tf32(p10));
            Pw[(gid + 8) * 68 + col + 1] = __uint_as_float(f2tf32(p11));
        }
        ps0 += __shfl_xor_sync(0xffffffffu, ps0, 1);
        ps0 += __shfl_xor_sync(0xffffffffu, ps0, 2);
        ps1 += __shfl_xor_sync(0xffffffffu, ps1, 1);
        ps1 += __shfl_xor_sync(0xffffffffu, ps1, 2);
        l0 += ps0; l1 += ps1;
        __syncwarp();
        #pragma unroll
        for (int k8 = 0; k8 < 8; k8++) {
            const int aoff = gid * 68 + k8 * 8 + qid;
            unsigned a0 = __float_as_uint(Pw[aoff]);
            unsigned a1 = __float_as_uint(Pw[aoff + 8 * 68]);
            unsigned a2 = __float_as_uint(Pw[aoff + 4]);
            unsigned a3 = __float_as_uint(Pw[aoff + 8 * 68 + 4]);
            #pragma unroll
            for (int dt = 0; dt < 4; dt++) {
                const int boff = (dt * 8 + gid) * 68 + k8 * 8 + qid;
                mma_tf32(oacc[dt], a0, a1, a2, a3,
                         __float_as_uint(Vts[boff]), __float_as_uint(Vts[boff + 4]));
            }
        }
        __syncwarp();
    }

    const float inv0 = 1.f / l0, inv1 = 1.f / l1;
    const int r0g = qb * 64 + w * 16 + gid, r1g = r0g + 8;
    #pragma unroll
    for (int dt = 0; dt < 4; dt++) {
        const int col = h * 32 + dt * 8 + qid * 2;
        float2 v0, v1;
        v0.x = oacc[dt][0] * inv0; v0.y = oacc[dt][1] * inv0;
        v1.x = oacc[dt][2] * inv1; v1.y = oacc[dt][3] * inv1;
        *(float2*)&O[(size_t)r0g * CDIM + col] = v0;
        *(float2*)&O[(size_t)r1g * CDIM + col] = v1;
    }
}

template<int FINAL>
__global__ __launch_bounds__(256) void add_ln_kernel(
    const float* __restrict__ a, const float* __restrict__ b,
    const float* __restrict__ g, const float* __restrict__ be,
    float* __restrict__ out)
{
    __shared__ float red[8];
    int row = blockIdx.x, tid = threadIdx.x;
    float v = a[row * CDIM + tid];
    if (!FINAL) v += b[row * CDIM + tid];
    float s = v;
    #pragma unroll
    for (int o = 16; o; o >>= 1) s += __shfl_xor_sync(0xffffffffu, s, o);
    if ((tid & 31) == 0) red[tid >> 5] = s;
    __syncthreads();
    float mean = 0.f;
    #pragma unroll
    for (int i = 0; i < 8; i++) mean += red[i];
    mean *= (1.f / 256.f);
    float d = v - mean;
    __syncthreads();
    s = d * d;
    #pragma unroll
    for (int o = 16; o; o >>= 1) s += __shfl_xor_sync(0xffffffffu, s, o);
    if ((tid & 31) == 0) red[tid >> 5] = s;
    __syncthreads();
    float var = 0.f;
    #pragma unroll
    for (int i = 0; i < 8; i++) var += red[i];
    var *= (1.f / 256.f);
    float r = d * rsqrtf(var + 1e-5f) * g[tid] + be[tid];
    if (FINAL) out[tid * NTOK + row] = r;
    else       out[row * CDIM + tid] = r;
}

extern "C" void kernel_launch(void* const* d_in, const int* in_sizes, int n_in,
                              void* d_out, int out_size)
{
    (void)in_sizes; (void)n_in; (void)out_size;
    const float* src  = (const float*)d_in[0];
    const float* c1w  = (const float*)d_in[1];
    const float* c1b  = (const float*)d_in[2];
    const float* c2w  = (const float*)d_in[3];
    const float* c2b  = (const float*)d_in[4];
    const float* nemb = (const float*)d_in[5];
    const float* Wq   = (const float*)d_in[6];
    const float* bq   = (const float*)d_in[7];
    const float* Wk   = (const float*)d_in[8];
    const float* bk   = (const float*)d_in[9];
    const float* Wv   = (const float*)d_in[10];
    const float* bv   = (const float*)d_in[11];
    const float* Wo   = (const float*)d_in[12];
    const float* bo   = (const float*)d_in[13];
    const float* W1   = (const float*)d_in[14];
    const float* b1   = (const float*)d_in[15];
    const float* W2   = (const float*)d_in[16];
    const float* b2   = (const float*)d_in[17];
    const float* ln1g = (const float*)d_in[18];
    const float* ln1b = (const float*)d_in[19];
    const float* ln2g = (const float*)d_in[20];
    const float* ln2b = (const float*)d_in[21];
    const float* ng   = (const float*)d_in[22];
    const float* nb   = (const float*)d_in[23];

    float *c1, *gp, *x, *sqv, *d2, *q, *k, *v, *att, *ffh, *yb;
    int *nearp, *maxn, *niv;
    cudaGetSymbolAddress((void**)&c1,    g_c1);
    cudaGetSymbolAddress((void**)&gp,    g_gp);
    cudaGetSymbolAddress((void**)&x,     g_x);
    cudaGetSymbolAddress((void**)&sqv,   g_sq);
    cudaGetSymbolAddress((void**)&d2,    g_d2);
    cudaGetSymbolAddress((void**)&nearp, g_near);
    cudaGetSymbolAddress((void**)&maxn,  g_maxnear);
    cudaGetSymbolAddress((void**)&niv,   g_ni);
    cudaGetSymbolAddress((void**)&q,     g_q);
    cudaGetSymbolAddress((void**)&k,     g_k);
    cudaGetSymbolAddress((void**)&v,     g_v);
    cudaGetSymbolAddress((void**)&att,   g_att);
    cudaGetSymbolAddress((void**)&ffh,   g_ffh);
    cudaGetSymbolAddress((void**)&yb,    g_y);

    pad_kernel<<<64, 256>>>(x, sqv);
    transpose_kernel<<<dim3(98, 8), dim3(32, 32)>>>(src, x);
    conv1_kernel<<<dim3(32, 49), 256>>>(src, c1w, c1b, c1);
    conv2_kernel<<<dim3(8, 49), 256>>>(c1, c2w, c2b, gp);

    for (int i = 0; i < NLAYER; i++) {
        sq_kernel<<<400, 256>>>(x, sqv, nearp, maxn);
        d2_tf32_kernel<<<dim3(25, 25), 256>>>(x, sqv, d2);
        topk_kernel<<<NTOK, 256>>>(d2, nearp);
        maxnear_kernel<<<1, 256>>>(nearp, maxn);
        ni_kernel<<<13, 256>>>(nearp, maxn, niv);

        qkv_gemm<<<dim3(50, 12), 128>>>(x, niv, nemb,
            Wq + i*CDIM*CDIM, Wk + i*CDIM*CDIM, Wv + i*CDIM*CDIM,
            bq + i*CDIM, bk + i*CDIM, bv + i*CDIM, q, k, v);

        attn_kernel<<<dim3(49, NHEAD), 128>>>(q, k, v, gp, att);

        mma1_gemm<0><<<dim3(50, 4), 128>>>(att, Wo + i*CDIM*CDIM, bo + i*CDIM, yb, CDIM, CDIM);
        add_ln_kernel<0><<<NTOK, 256>>>(x, yb, ln1g + i*CDIM, ln1b + i*CDIM, x);

        mma1_gemm<1><<<dim3(50, 16), 128>>>(x, W1 + i*DFFN*CDIM, b1 + i*DFFN, ffh, DFFN, CDIM);
        mma1_gemm<0><<<dim3(50, 4), 128>>>(ffh, W2 + i*CDIM*DFFN, b2 + i*CDIM, yb, CDIM, DFFN);
        add_ln_kernel<0><<<NTOK, 256>>>(x, yb, ln2g + i*CDIM, ln2b + i*CDIM, x);
    }

    add_ln_kernel<1><<<NTOK, 256>>>(x, nullptr, ng, nb, (float*)d_out);
}

// round 14
// speedup vs baseline: 1.1361x; 1.0728x over previous
#include <cuda_runtime.h>
#include <cuda_bf16.h>
#include <cstdint>
#include <math.h>

#define NTOK 3136
#define NPAD 3200
#define CDIM 256
#define NHEAD 8
#define DFFN 1024
#define NLAYER 4
#define TOPKK 16
#define HW 56

__device__ float g_c1[128 * NTOK];
__device__ float g_gp[NHEAD * NTOK];
__device__ float g_x[NPAD * CDIM];
__device__ float g_sq[NPAD];
__device__ float g_d2[(size_t)NPAD * NPAD];
__device__ int   g_near[NTOK];
__device__ int   g_maxnear[1];
__device__ int   g_ni[NPAD];
__device__ float g_q[NPAD * CDIM];
__device__ float g_k[NPAD * CDIM];
__device__ float g_v[NPAD * CDIM];
__device__ float g_att[NPAD * CDIM];
__device__ float g_ffh[(size_t)NPAD * DFFN];
__device__ float g_y[NPAD * CDIM];

__device__ __forceinline__ float fexp(float x) {
    x = fmaxf(x, -87.0f);
    float y = x * 1.44269504088896341f;
    float r = rintf(y);
    float f = y - r;
    float p = 1.33335581e-3f;
    p = fmaf(p, f, 9.61812911e-3f);
    p = fmaf(p, f, 5.55041087e-2f);
    p = fmaf(p, f, 2.40226507e-1f);
    p = fmaf(p, f, 6.93147181e-1f);
    p = fmaf(p, f, 1.0f);
    return __int_as_float(__float_as_int(p) + (((int)r) << 23));
}

__device__ __forceinline__ unsigned f2tf32(float v) {
    unsigned r;
    asm("cvt.rna.tf32.f32 %0, %1;" : "=r"(r) : "f"(v));
    return r;
}

__device__ __forceinline__ void mma_tf32(float c[4],
    unsigned a0, unsigned a1, unsigned a2, unsigned a3,
    unsigned b0, unsigned b1)
{
    asm volatile(
        "mma.sync.aligned.m16n8k8.row.col.f32.tf32.tf32.f32 "
        "{%0,%1,%2,%3}, {%4,%5,%6,%7}, {%8,%9}, {%0,%1,%2,%3};\n"
        : "+f"(c[0]), "+f"(c[1]), "+f"(c[2]), "+f"(c[3])
        : "r"(a0), "r"(a1), "r"(a2), "r"(a3), "r"(b0), "r"(b1));
}

__global__ void pad_kernel(float* __restrict__ x, float* __restrict__ sqv) {
    int i = blockIdx.x * 256 + threadIdx.x;
    x[NTOK * CDIM + i] = 0.f;
    if (i < NPAD - NTOK) sqv[NTOK + i] = 0.f;
}

__global__ void transpose_kernel(const float* __restrict__ src, float* __restrict__ dst) {
    __shared__ float tile[32][33];
    int t0 = blockIdx.x * 32, c0 = blockIdx.y * 32;
    int tx = threadIdx.x, ty = threadIdx.y;
    tile[ty][tx] = src[(c0 + ty) * NTOK + t0 + tx];
    __syncthreads();
    dst[(t0 + ty) * CDIM + c0 + tx] = tile[tx][ty];
}

__global__ __launch_bounds__(256) void conv1_kernel(
    const float* __restrict__ src, const float* __restrict__ wt,
    const float* __restrict__ bias, float* __restrict__ out)
{
    __shared__ float ws[4 * 2304];
    __shared__ float red[4 * 256];
    int cog = blockIdx.x;
    int tid = threadIdx.x;
    int px = tid & 63, cig = tid >> 6;
    int p = blockIdx.y * 64 + px;
    for (int i = tid; i < 4 * 2304; i += 256) ws[i] = wt[cog * 4 * 2304 + i];
    __syncthreads();
    int y = p / HW, x = p % HW;
    float a[4][2];
    #pragma unroll
    for (int j = 0; j < 4; j++) { a[j][0] = 0.f; a[j][1] = 0.f; }
    for (int ci = cig * 64; ci < cig * 64 + 64; ci += 2) {
        #pragma unroll
        for (int par = 0; par < 2; par++) {
            const float* ip = src + (ci + par) * NTOK;
            const float* wp = ws + (ci + par) * 9;
            #pragma unroll
            for (int dy = 0; dy < 3; dy++) {
                int yy = y + dy - 1; if ((unsigned)yy >= HW) continue;
                #pragma unroll
                for (int dx = 0; dx < 3; dx++) {
                    int xx = x + dx - 1; if ((unsigned)xx >= HW) continue;
                    float v = ip[yy * HW + xx]; int wi = dy * 3 + dx;
                    a[0][par] = fmaf(v, wp[wi],          a[0][par]);
                    a[1][par] = fmaf(v, wp[2304 + wi],   a[1][par]);
                    a[2][par] = fmaf(v, wp[4608 + wi],   a[2][par]);
                    a[3][par] = fmaf(v, wp[6912 + wi],   a[3][par]);
                }
            }
        }
    }
    #pragma unroll
    for (int j = 0; j < 4; j++) red[j * 256 + tid] = a[j][0] + a[j][1];
    __syncthreads();
    if (tid < 64) {
        #pragma unroll
        for (int j = 0; j < 4; j++) {
            float s = (red[j*256 + tid] + red[j*256 + tid + 64])
                    + (red[j*256 + tid + 128] + red[j*256 + tid + 192]);
            out[(cog*4+j)*NTOK + p] = fmaxf(s + bias[cog*4+j], 0.f);
        }
    }
}

__global__ __launch_bounds__(256) void conv2_kernel(
    const float* __restrict__ c1, const float* __restrict__ wt,
    const float* __restrict__ bias, float* __restrict__ gp)
{
    __shared__ float ws[1152];
    __shared__ float red[256];
    int co = blockIdx.x;
    int tid = threadIdx.x;
    int px = tid & 63, cig = tid >> 6;
    int p = blockIdx.y * 64 + px;
    for (int i = tid; i < 1152; i += 256) ws[i] = wt[co * 1152 + i];
    __syncthreads();
    int y = p / HW, x = p % HW;
    float a0 = 0.f, a1 = 0.f;
    for (int ci = cig * 32; ci < cig * 32 + 32; ci += 2) {
        #pragma unroll
        for (int dy = 0; dy < 3; dy++) {
            int yy = y + dy - 1; if ((unsigned)yy >= HW) continue;
            #pragma unroll
            for (int dx = 0; dx < 3; dx++) {
                int xx = x + dx - 1; if ((unsigned)xx >= HW) continue;
                int po = yy * HW + xx, wi = dy * 3 + dx;
                a0 = fmaf(c1[(ci+0) * NTOK + po], ws[(ci+0) * 9 + wi], a0);
                a1 = fmaf(c1[(ci+1) * NTOK + po], ws[(ci+1) * 9 + wi], a1);
            }
        }
    }
    red[tid] = a0 + a1;
    __syncthreads();
    if (tid < 64) {
        float a = bias[co] + (red[tid] + red[tid + 64]) + (red[tid + 128] + red[tid + 192]);
        gp[co * NTOK + p] = 1.0f / (1.0f + __expf(-a));
    }
}

__global__ __launch_bounds__(256) void sq_kernel(const float* __restrict__ x,
                                                 float* __restrict__ sq,
                                                 int* __restrict__ nearp,
                                                 int* __restrict__ maxn)
{
    int row = blockIdx.x * 8 + (threadIdx.x >> 5);
    int lane = threadIdx.x & 31;
    const float* r = x + row * CDIM;
    float s = 0.f;
    #pragma unroll
    for (int i = 0; i < 8; i++) { float v = r[lane + i * 32]; s = fmaf(v, v, s); }
    #pragma unroll
    for (int o = 16; o; o >>= 1) s += __shfl_xor_sync(0xffffffffu, s, o);
    if (lane == 0) {
        sq[row] = s;
        if (row < NTOK) nearp[row] = 0;
        if (row == 0) *maxn = 0;
    }
}

__global__ __launch_bounds__(256) void d2_tf32_kernel(
    const float* __restrict__ X, const float* __restrict__ sqv,
    float* __restrict__ C)
{
    __shared__ float As[128 * 36];
    __shared__ float Bs[128 * 36];
    const int tid = threadIdx.x;
    const int wid = tid >> 5, lane = tid & 31;
    const int warpM = wid >> 2, warpN = wid & 3;
    const int i0 = blockIdx.x * 128, j0 = blockIdx.y * 128;
    const int gid = lane >> 2, qid = lane & 3;

    float acc[4][4][4];
    #pragma unroll
    for (int a = 0; a < 4; a++)
        #pragma unroll
        for (int b = 0; b < 4; b++)
            #pragma unroll
            for (int c = 0; c < 4; c++) acc[a][b][c] = 0.f;

    const int lrow = tid >> 1;
    const int lk = (tid & 1) * 16;
    const float* Ag = X + (size_t)(i0 + lrow) * CDIM + lk;
    const float* Bg = X + (size_t)(j0 + lrow) * CDIM + lk;
    float* Asw = As + lrow * 36 + lk;
    float* Bsw = Bs + lrow * 36 + lk;

    float4 pa[4], pb[4];
    #pragma unroll
    for (int q = 0; q < 4; q++) {
        pa[q] = *(const float4*)(Ag + q * 4);
        pb[q] = *(const float4*)(Bg + q * 4);
    }
    for (int k0 = 0; k0 < CDIM; k0 += 32) {
        __syncthreads();
        #pragma unroll
        for (int q = 0; q < 4; q++) {
            float4 at, bt;
            at.x = __uint_as_float(f2tf32(pa[q].x)); at.y = __uint_as_float(f2tf32(pa[q].y));
            at.z = __uint_as_float(f2tf32(pa[q].z)); at.w = __uint_as_float(f2tf32(pa[q].w));
            bt.x = __uint_as_float(f2tf32(pb[q].x)); bt.y = __uint_as_float(f2tf32(pb[q].y));
            bt.z = __uint_as_float(f2tf32(pb[q].z)); bt.w = __uint_as_float(f2tf32(pb[q].w));
            *(float4*)&Asw[q * 4] = at;
            *(float4*)&Bsw[q * 4] = bt;
        }
        __syncthreads();
        if (k0 + 32 < CDIM) {
            #pragma unroll
            for (int q = 0; q < 4; q++) {
                pa[q] = *(const float4*)(Ag + k0 + 32 + q * 4);
                pb[q] = *(const float4*)(Bg + k0 + 32 + q * 4);
            }
        }
        #pragma unroll
        for (int k8 = 0; k8 < 4; k8++) {
            unsigned af[4][4], bf[4][2];
            #pragma unroll
            for (int tm = 0; tm < 4; tm++) {
                const float* p = As + (warpM * 64 + tm * 16 + gid) * 36 + k8 * 8 + qid;
                af[tm][0] = __float_as_uint(p[0]);
                af[tm][1] = __float_as_uint(p[8 * 36]);
                af[tm][2] = __float_as_uint(p[4]);
                af[tm][3] = __float_as_uint(p[8 * 36 + 4]);
            }
            #pragma unroll
            for (int tn = 0; tn < 4; tn++) {
                const float* p = Bs + (warpN * 32 + tn * 8 + gid) * 36 + k8 * 8 + qid;
                bf[tn][0] = __float_as_uint(p[0]);
                bf[tn][1] = __float_as_uint(p[4]);
            }
            #pragma unroll
            for (int tm = 0; tm < 4; tm++)
                #pragma unroll
                for (int tn = 0; tn < 4; tn++)
                    mma_tf32(acc[tm][tn], af[tm][0], af[tm][1], af[tm][2], af[tm][3],
                             bf[tn][0], bf[tn][1]);
        }
    }

    #pragma unroll
    for (int tm = 0; tm < 4; tm++) {
        const int r0 = i0 + warpM * 64 + tm * 16 + gid;
        const float sr0 = sqv[r0], sr1 = sqv[r0 + 8];
        #pragma unroll
        for (int tn = 0; tn < 4; tn++) {
            const int c0i = j0 + warpN * 32 + tn * 8 + qid * 2;
            const float sc0 = sqv[c0i], sc1 = sqv[c0i + 1];
            float2 v0, v1;
            v0.x = sr0 + sc0 - 2.f * acc[tm][tn][0];
            v0.y = sr0 + sc1 - 2.f * acc[tm][tn][1];
            v1.x = sr1 + sc0 - 2.f * acc[tm][tn][2];
            v1.y = sr1 + sc1 - 2.f * acc[tm][tn][3];
            *(float2*)&C[(size_t)r0 * NPAD + c0i] = v0;
            *(float2*)&C[(size_t)(r0 + 8) * NPAD + c0i] = v1;
        }
    }
}

// single-pass tf32 64x64 GEMM with register prefetch; ADDEMB adds emb[ni[row]]
template<int EPI, int ADDEMB>
__device__ __forceinline__ void gemm64(
    const float* __restrict__ A, const float* __restrict__ B,
    const float* __restrict__ bias, float* __restrict__ C,
    int Nn, int K, int i0, int j0,
    const int* __restrict__ ni, const float* __restrict__ emb)
{
    __shared__ float Ah[64 * 36], Bh[64 * 36];
    const int tid = threadIdx.x;
    const int wid = tid >> 5, lane = tid & 31;
    const int warpM = wid >> 1, warpN = wid & 1;
    const int gid = lane >> 2, qid = lane & 3;

    float acc[2][4][4];
    #pragma unroll
    for (int a = 0; a < 2; a++)
        #pragma unroll
        for (int b = 0; b < 4; b++)
            #pragma unroll
            for (int c = 0; c < 4; c++) acc[a][b][c] = 0.f;

    const int lrow = tid >> 1;
    const int lk = (tid & 1) * 16;
    const float* Ag = A + (size_t)(i0 + lrow) * K + lk;
    const float* Bg = B + (size_t)(j0 + lrow) * K + lk;
    const float* Eg = ADDEMB ? (emb + (size_t)ni[i0 + lrow] * CDIM + lk) : nullptr;
    const int sbase = lrow * 36 + lk;

    float4 pa[4], pb[4];
    #pragma unroll
    for (int q = 0; q < 4; q++) {
        pa[q] = *(const float4*)(Ag + q * 4);
        pb[q] = *(const float4*)(Bg + q * 4);
        if (ADDEMB) {
            float4 ev = *(const float4*)(Eg + q * 4);
            pa[q].x += ev.x; pa[q].y += ev.y; pa[q].z += ev.z; pa[q].w += ev.w;
        }
    }
    for (int k0 = 0; k0 < K; k0 += 32) {
        __syncthreads();
        #pragma unroll
        for (int q = 0; q < 4; q++) {
            float4 at, bt;
            at.x = __uint_as_float(f2tf32(pa[q].x)); at.y = __uint_as_float(f2tf32(pa[q].y));
            at.z = __uint_as_float(f2tf32(pa[q].z)); at.w = __uint_as_float(f2tf32(pa[q].w));
            bt.x = __uint_as_float(f2tf32(pb[q].x)); bt.y = __uint_as_float(f2tf32(pb[q].y));
            bt.z = __uint_as_float(f2tf32(pb[q].z)); bt.w = __uint_as_float(f2tf32(pb[q].w));
            *(float4*)&Ah[sbase + q * 4] = at;
            *(float4*)&Bh[sbase + q * 4] = bt;
        }
        __syncthreads();
        if (k0 + 32 < K) {
            #pragma unroll
            for (int q = 0; q < 4; q++) {
                pa[q] = *(const float4*)(Ag + k0 + 32 + q * 4);
                pb[q] = *(const float4*)(Bg + k0 + 32 + q * 4);
                if (ADDEMB) {
                    float4 ev = *(const float4*)(Eg + k0 + 32 + q * 4);
                    pa[q].x += ev.x; pa[q].y += ev.y; pa[q].z += ev.z; pa[q].w += ev.w;
                }
            }
        }
        #pragma unroll
        for (int k8 = 0; k8 < 4; k8++) {
            unsigned af[2][4], bf[4][2];
            #pragma unroll
            for (int tm = 0; tm < 2; tm++) {
                const int off = (warpM * 32 + tm * 16 + gid) * 36 + k8 * 8 + qid;
                af[tm][0] = __float_as_uint(Ah[off]);
                af[tm][1] = __float_as_uint(Ah[off + 8 * 36]);
                af[tm][2] = __float_as_uint(Ah[off + 4]);
                af[tm][3] = __float_as_uint(Ah[off + 8 * 36 + 4]);
            }
            #pragma unroll
            for (int tn = 0; tn < 4; tn++) {
                const int off = (warpN * 32 + tn * 8 + gid) * 36 + k8 * 8 + qid;
                bf[tn][0] = __float_as_uint(Bh[off]);
                bf[tn][1] = __float_as_uint(Bh[off + 4]);
            }
            #pragma unroll
            for (int tm = 0; tm < 2; tm++)
                #pragma unroll
                for (int tn = 0; tn < 4; tn++)
                    mma_tf32(acc[tm][tn], af[tm][0], af[tm][1], af[tm][2], af[tm][3],
                             bf[tn][0], bf[tn][1]);
        }
    }

    #pragma unroll
    for (int tm = 0; tm < 2; tm++) {
        const int r0 = i0 + warpM * 32 + tm * 16 + gid;
        #pragma unroll
        for (int tn = 0; tn < 4; tn++) {
            const int c0i = j0 + warpN * 32 + tn * 8 + qid * 2;
            const float b0 = bias[c0i], b1 = bias[c0i + 1];
            float2 v0, v1;
            v0.x = acc[tm][tn][0] + b0; v0.y = acc[tm][tn][1] + b1;
            v1.x = acc[tm][tn][2] + b0; v1.y = acc[tm][tn][3] + b1;
            if (EPI == 1) {
                v0.x = fmaxf(v0.x, 0.f); v0.y = fmaxf(v0.y, 0.f);
                v1.x = fmaxf(v1.x, 0.f); v1.y = fmaxf(v1.y, 0.f);
            }
            *(float2*)&C[(size_t)r0 * Nn + c0i] = v0;
            *(float2*)&C[(size_t)(r0 + 8) * Nn + c0i] = v1;
        }
    }
}

template<int EPI>
__global__ __launch_bounds__(128) void mma1_gemm(
    const float* __restrict__ A, const float* __restrict__ B,
    const float* __restrict__ bias, float* __restrict__ C,
    int Nn, int K)
{
    gemm64<EPI, 0>(A, B, bias, C, Nn, K, blockIdx.x * 64, blockIdx.y * 64,
                   nullptr, nullptr);
}

__global__ __launch_bounds__(128) void qkv_gemm(
    const float* __restrict__ x, const int* __restrict__ ni,
    const float* __restrict__ emb,
    const float* __restrict__ Wq, const float* __restrict__ Wk,
    const float* __restrict__ Wv,
    const float* __restrict__ bq, const float* __restrict__ bk,
    const float* __restrict__ bv,
    float* __restrict__ q, float* __restrict__ k, float* __restrict__ v)
{
    int sel = blockIdx.y >> 2, jb = blockIdx.y & 3;
    if (sel == 2) {
        gemm64<0, 0>(x, Wv, bv, v, CDIM, CDIM, blockIdx.x * 64, jb * 64,
                     nullptr, nullptr);
    } else if (sel == 0) {
        gemm64<0, 1>(x, Wq, bq, q, CDIM, CDIM, blockIdx.x * 64, jb * 64, ni, emb);
    } else {
        gemm64<0, 1>(x, Wk, bk, k, CDIM, CDIM, blockIdx.x * 64, jb * 64, ni, emb);
    }
}

__global__ __launch_bounds__(256) void topk_kernel(const float* __restrict__ d2,
                                                   int* __restrict__ nearp)
{
    __shared__ float vals[NTOK];
    __shared__ float wv[8];
    __shared__ int   wi[8];
    int row = blockIdx.x, tid = threadIdx.x;
    int lane = tid & 31, w = tid >> 5;
    const float* rp = d2 + (size_t)row * NPAD;
    for (int i = tid; i < NTOK; i += 256) vals[i] = rp[i];
    __syncthreads();
    for (int it = 0; it < TOPKK; it++) {
        float bv = 3.0e38f; int bi = 0x7FFFFFFF;
        for (int i = tid; i < NTOK; i += 256) {
            float v = vals[i];
            if (v < bv) { bv = v; bi = i; }
        }
        #pragma unroll
        for (int o = 16; o; o >>= 1) {
            float ov = __shfl_xor_sync(0xffffffffu, bv, o);
            int   oi = __shfl_xor_sync(0xffffffffu, bi, o);
            if (ov < bv || (ov == bv && oi < bi)) { bv = ov; bi = oi; }
        }
        if (lane == 0) { wv[w] = bv; wi[w] = bi; }
        __syncthreads();
        if (w == 0) {
            float fv = (lane < 8) ? wv[lane] : 3.0e38f;
            int   fi = (lane < 8) ? wi[lane] : 0x7FFFFFFF;
            #pragma unroll
            for (int o = 4; o; o >>= 1) {
                float ov = __shfl_xor_sync(0xffffffffu, fv, o);
                int   oi = __shfl_xor_sync(0xffffffffu, fi, o);
                if (ov < fv || (ov == fv && oi < fi)) { fv = ov; fi = oi; }
            }
            if (lane == 0) {
                atomicAdd(&nearp[fi], 1);
                vals[fi] = 3.0e38f;
            }
        }
        __syncthreads();
    }
}

// max in-degree + ni indices in one launch (single block)
__global__ __launch_bounds__(256) void maxni_kernel(const int* __restrict__ nearp,
                                                    int* __restrict__ ni)
{
    __shared__ int sm[256];
    int tid = threadIdx.x;
    int m = 0;
    for (int i = tid; i < NTOK; i += 256) m = max(m, nearp[i]);
    sm[tid] = m;
    __syncthreads();
    for (int s = 128; s > 0; s >>= 1) {
        if (tid < s) sm[tid] = max(sm[tid], sm[tid+s]);
        __syncthreads();
    }
    float mf = (float)sm[0];
    for (int i = tid; i < NPAD; i += 256) {
        int r = 0;
        if (i < NTOK) {
            r = (int)(((float)nearp[i] / mf) * 9.0f);
            if (r > 9) r = 9;
        }
        ni[i] = r;
    }
}

// Flash attention, tf32 mma, 64 queries/block, vectorized float4 staging
__global__ __launch_bounds__(128) void attn_kernel(
    const float* __restrict__ Q, const float* __restrict__ Km,
    const float* __restrict__ V, const float* __restrict__ gp,
    float* __restrict__ O)
{
    __shared__ float Qs[64 * 36];
    __shared__ float Ks[64 * 36];
    __shared__ float Vts[32 * 68];
    __shared__ float Ps[4 * 16 * 68];
    __shared__ float gks[64];

    const int h = blockIdx.y, qb = blockIdx.x, tid = threadIdx.x;
    const int w = tid >> 5, lane = tid & 31;
    const int gid = lane >> 2, qid = lane & 3;
    const float scale = 0.17677669529663687f;

    #pragma unroll
    for (int u = tid; u < 512; u += 128) {
        int i = u >> 3, dq = (u & 7) * 4;
        float4 t = *(const float4*)(Q + (size_t)(qb * 64 + i) * CDIM + h * 32 + dq);
        float4 o;
        o.x = __uint_as_float(f2tf32(t.x * scale));
        o.y = __uint_as_float(f2tf32(t.y * scale));
        o.z = __uint_as_float(f2tf32(t.z * scale));
        o.w = __uint_as_float(f2tf32(t.w * scale));
        *(float4*)&Qs[i * 36 + dq] = o;
    }
    const float gq0 = gp[h * NTOK + qb * 64 + w * 16 + gid];
    const float gq1 = gp[h * NTOK + qb * 64 + w * 16 + gid + 8];

    float oacc[4][4];
    #pragma unroll
    for (int dt = 0; dt < 4; dt++)
        #pragma unroll
        for (int c = 0; c < 4; c++) oacc[dt][c] = 0.f;
    float m0 = -1e30f, m1 = -1e30f, l0 = 0.f, l1 = 0.f;
    float* Pw = Ps + w * (16 * 68);

    for (int kt = 0; kt < 49; kt++) {
        __syncthreads();
        #pragma unroll
        for (int u = tid; u < 512; u += 128) {
            int j = u >> 3, dq = (u & 7) * 4;
            size_t gbase = (size_t)(kt * 64 + j) * CDIM + h * 32 + dq;
            float4 kv = *(const float4*)(Km + gbase);
            float4 vv = *(const float4*)(V + gbase);
            float4 ko;
            ko.x = __uint_as_float(f2tf32(kv.x)); ko.y = __uint_as_float(f2tf32(kv.y));
            ko.z = __uint_as_float(f2tf32(kv.z)); ko.w = __uint_as_float(f2tf32(kv.w));
            *(float4*)&Ks[j * 36 + dq] = ko;
            Vts[(dq + 0) * 68 + j] = __uint_as_float(f2tf32(vv.x));
            Vts[(dq + 1) * 68 + j] = __uint_as_float(f2tf32(vv.y));
            Vts[(dq + 2) * 68 + j] = __uint_as_float(f2tf32(vv.z));
            Vts[(dq + 3) * 68 + j] = __uint_as_float(f2tf32(vv.w));
        }
        if (tid < 64) gks[tid] = gp[h * NTOK + kt * 64 + tid];
        __syncthreads();

        float sc[8][4];
        #pragma unroll
        for (int tn = 0; tn < 8; tn++)
            #pragma unroll
            for (int c = 0; c < 4; c++) sc[tn][c] = 0.f;
        #pragma unroll
        for (int k8 = 0; k8 < 4; k8++) {
            const int aoff = (w * 16 + gid) * 36 + k8 * 8 + qid;
            unsigned a0 = __float_as_uint(Qs[aoff]);
            unsigned a1 = __float_as_uint(Qs[aoff + 8 * 36]);
            unsigned a2 = __float_as_uint(Qs[aoff + 4]);
            unsigned a3 = __float_as_uint(Qs[aoff + 8 * 36 + 4]);
            #pragma unroll
            for (int tn = 0; tn < 8; tn++) {
                const int boff = (tn * 8 + gid) * 36 + k8 * 8 + qid;
                mma_tf32(sc[tn], a0, a1, a2, a3,
                         __float_as_uint(Ks[boff]), __float_as_uint(Ks[boff + 4]));
            }
        }
        float mn0 = -1e30f, mn1 = -1e30f;
        #pragma unroll
        for (int tn = 0; tn < 8; tn++) {
            float ga = gks[tn * 8 + qid * 2], gb = gks[tn * 8 + qid * 2 + 1];
            sc[tn][0] += fabsf(gq0 - ga); sc[tn][1] += fabsf(gq0 - gb);
            sc[tn][2] += fabsf(gq1 - ga); sc[tn][3] += fabsf(gq1 - gb);
            mn0 = fmaxf(mn0, fmaxf(sc[tn][0], sc[tn][1]));
            mn1 = fmaxf(mn1, fmaxf(sc[tn][2], sc[tn][3]));
        }
        mn0 = fmaxf(mn0, __shfl_xor_sync(0xffffffffu, mn0, 1));
        mn0 = fmaxf(mn0, __shfl_xor_sync(0xffffffffu, mn0, 2));
        mn1 = fmaxf(mn1, __shfl_xor_sync(0xffffffffu, mn1, 1));
        mn1 = fmaxf(mn1, __shfl_xor_sync(0xffffffffu, mn1, 2));
        if (mn0 > m0) {
            float corr = fexp(m0 - mn0);
            l0 *= corr;
            #pragma unroll
            for (int dt = 0; dt < 4; dt++) { oacc[dt][0] *= corr; oacc[dt][1] *= corr; }
            m0 = mn0;
        }
        if (mn1 > m1) {
            float corr = fexp(m1 - mn1);
            l1 *= corr;
            #pragma unroll
            for (int dt = 0; dt < 4; dt++) { oacc[dt][2] *= corr; oacc[dt][3] *= corr; }
            m1 = mn1;
        }
        float ps0 = 0.f, ps1 = 0.f;
        #pragma unroll
        for (int tn = 0; tn < 8; tn++) {
            float p00 = fexp(sc[tn][0] - m0), p01 = fexp(sc[tn][1] - m0);
            float p10 = fexp(sc[tn][2] - m1), p11 = fexp(sc[tn][3] - m1);
            ps0 += p00 + p01; ps1 += p10 + p11;
            int col = tn * 8 + qid * 2;
            Pw[gid * 68 + col]       = __uint_as_float(f2tf32(p00));
            Pw[gid * 68 + col + 1]   = __uint_as_float(f2tf32(p01));
            Pw[(gid + 8) * 68 + col]     = __uint_as_float(f2tf32(p10));
            Pw[(gid + 8) * 68 + col + 1] = __uint_as_float(f2tf32(p11));
        }
        ps0 += __shfl_xor_sync(0xffffffffu, ps0, 1);
        ps0 += __shfl_xor_sync(0xffffffffu, ps0, 2);
        ps1 += __shfl_xor_sync(0xffffffffu, ps1, 1);
        ps1 += __shfl_xor_sync(0xffffffffu, ps1, 2);
        l0 += ps0; l1 += ps1;
        __syncwarp();
        #pragma unroll
        for (int k8 = 0; k8 < 8; k8++) {
            const int aoff = gid * 68 + k8 * 8 + qid;
            unsigned a0 = __float_as_uint(Pw[aoff]);
            unsigned a1 = __float_as_uint(Pw[aoff + 8 * 68]);
            unsigned a2 = __float_as_uint(Pw[aoff + 4]);
            unsigned a3 = __float_as_uint(Pw[aoff + 8 * 68 + 4]);
            #pragma unroll
            for (int dt = 0; dt < 4; dt++) {
                const int boff = (dt * 8 + gid) * 68 + k8 * 8 + qid;
                mma_tf32(oacc[dt], a0, a1, a2, a3,
                         __float_as_uint(Vts[boff]), __float_as_uint(Vts[boff + 4]));
            }
        }
        __syncwarp();
    }

    const float inv0 = 1.f / l0, inv1 = 1.f / l1;
    const int r0g = qb * 64 + w * 16 + gid, r1g = r0g + 8;
    #pragma unroll
    for (int dt = 0; dt < 4; dt++) {
        const int col = h * 32 + dt * 8 + qid * 2;
        float2 v0, v1;
        v0.x = oacc[dt][0] * inv0; v0.y = oacc[dt][1] * inv0;
        v1.x = oacc[dt][2] * inv1; v1.y = oacc[dt][3] * inv1;
        *(float2*)&O[(size_t)r0g * CDIM + col] = v0;
        *(float2*)&O[(size_t)r1g * CDIM + col] = v1;
    }
}

// one-pass LN: sum and sumsq reduced together
template<int FINAL>
__global__ __launch_bounds__(256) void add_ln_kernel(
    const float* __restrict__ a, const float* __restrict__ b,
    const float* __restrict__ g, const float* __restrict__ be,
    float* __restrict__ out)
{
    __shared__ float red1[8], red2[8];
    int row = blockIdx.x, tid = threadIdx.x;
    float v = a[row * CDIM + tid];
    if (!FINAL) v += b[row * CDIM + tid];
    float s1 = v, s2 = v * v;
    #pragma unroll
    for (int o = 16; o; o >>= 1) {
        s1 += __shfl_xor_sync(0xffffffffu, s1, o);
        s2 += __shfl_xor_sync(0xffffffffu, s2, o);
    }
    if ((tid & 31) == 0) { red1[tid >> 5] = s1; red2[tid >> 5] = s2; }
    __syncthreads();
    float mean = 0.f, ex2 = 0.f;
    #pragma unroll
    for (int i = 0; i < 8; i++) { mean += red1[i]; ex2 += red2[i]; }
    mean *= (1.f / 256.f);
    ex2  *= (1.f / 256.f);
    float var = ex2 - mean * mean;
    float r = (v - mean) * rsqrtf(var + 1e-5f) * g[tid] + be[tid];
    if (FINAL) out[tid * NTOK + row] = r;
    else       out[row * CDIM + tid] = r;
}

extern "C" void kernel_launch(void* const* d_in, const int* in_sizes, int n_in,
                              void* d_out, int out_size)
{
    (void)in_sizes; (void)n_in; (void)out_size;
    const float* src  = (const float*)d_in[0];
    const float* c1w  = (const float*)d_in[1];
    const float* c1b  = (const float*)d_in[2];
    const float* c2w  = (const float*)d_in[3];
    const float* c2b  = (const float*)d_in[4];
    const float* nemb = (const float*)d_in[5];
    const float* Wq   = (const float*)d_in[6];
    const float* bq   = (const float*)d_in[7];
    const float* Wk   = (const float*)d_in[8];
    const float* bk   = (const float*)d_in[9];
    const float* Wv   = (const float*)d_in[10];
    const float* bv   = (const float*)d_in[11];
    const float* Wo   = (const float*)d_in[12];
    const float* bo   = (const float*)d_in[13];
    const float* W1   = (const float*)d_in[14];
    const float* b1   = (const float*)d_in[15];
    const float* W2   = (const float*)d_in[16];
    const float* b2   = (const float*)d_in[17];
    const float* ln1g = (const float*)d_in[18];
    const float* ln1b = (const float*)d_in[19];
    const float* ln2g = (const float*)d_in[20];
    const float* ln2b = (const float*)d_in[21];
    const float* ng   = (const float*)d_in[22];
    const float* nb   = (const float*)d_in[23];

    float *c1, *gp, *x, *sqv, *d2, *q, *k, *v, *att, *ffh, *yb;
    int *nearp, *maxn, *niv;
    cudaGetSymbolAddress((void**)&c1,    g_c1);
    cudaGetSymbolAddress((void**)&gp,    g_gp);
    cudaGetSymbolAddress((void**)&x,     g_x);
    cudaGetSymbolAddress((void**)&sqv,   g_sq);
    cudaGetSymbolAddress((void**)&d2,    g_d2);
    cudaGetSymbolAddress((void**)&nearp, g_near);
    cudaGetSymbolAddress((void**)&maxn,  g_maxnear);
    cudaGetSymbolAddress((void**)&niv,   g_ni);
    cudaGetSymbolAddress((void**)&q,     g_q);
    cudaGetSymbolAddress((void**)&k,     g_k);
    cudaGetSymbolAddress((void**)&v,     g_v);
    cudaGetSymbolAddress((void**)&att,   g_att);
    cudaGetSymbolAddress((void**)&ffh,   g_ffh);
    cudaGetSymbolAddress((void**)&yb,    g_y);

    pad_kernel<<<64, 256>>>(x, sqv);
    transpose_kernel<<<dim3(98, 8), dim3(32, 32)>>>(src, x);
    conv1_kernel<<<dim3(32, 49), 256>>>(src, c1w, c1b, c1);
    conv2_kernel<<<dim3(8, 49), 256>>>(c1, c2w, c2b, gp);

    for (int i = 0; i < NLAYER; i++) {
        sq_kernel<<<400, 256>>>(x, sqv, nearp, maxn);
        d2_tf32_kernel<<<dim3(25, 25), 256>>>(x, sqv, d2);
        topk_kernel<<<NTOK, 256>>>(d2, nearp);
        maxni_kernel<<<1, 256>>>(nearp, niv);

        qkv_gemm<<<dim3(50, 12), 128>>>(x, niv, nemb,
            Wq + i*CDIM*CDIM, Wk + i*CDIM*CDIM, Wv + i*CDIM*CDIM,
            bq + i*CDIM, bk + i*CDIM, bv + i*CDIM, q, k, v);

        attn_kernel<<<dim3(49, NHEAD), 128>>>(q, k, v, gp, att);

        mma1_gemm<0><<<dim3(50, 4), 128>>>(att, Wo + i*CDIM*CDIM, bo + i*CDIM, yb, CDIM, CDIM);
        add_ln_kernel<0><<<NTOK, 256>>>(x, yb, ln1g + i*CDIM, ln1b + i*CDIM, x);

        mma1_gemm<1><<<dim3(50, 16), 128>>>(x, W1 + i*DFFN*CDIM, b1 + i*DFFN, ffh, DFFN, CDIM);
        mma1_gemm<0><<<dim3(50, 4), 128>>>(ffh, W2 + i*CDIM*DFFN, b2 + i*CDIM, yb, CDIM, DFFN);
        add_ln_kernel<0><<<NTOK, 256>>>(x, yb, ln2g + i*CDIM, ln2b + i*CDIM, x);
    }

    add_ln_kernel<1><<<NTOK, 256>>>(x, nullptr, ng, nb, (float*)d_out);
}

// round 15
// speedup vs baseline: 1.2573x; 1.1067x over previous
#include <cuda_runtime.h>
#include <cuda_bf16.h>
#include <cstdint>
#include <math.h>

#define NTOK 3136
#define NPAD 3200
#define CDIM 256
#define NHEAD 8
#define DFFN 1024
#define NLAYER 4
#define TOPKK 16
#define HW 56

__device__ float g_c1[128 * NTOK];
__device__ float g_gp[NHEAD * NTOK];
__device__ float g_x[NPAD * CDIM];
__device__ float g_sq[NPAD];
__device__ float g_d2[(size_t)NPAD * NPAD];
__device__ int   g_near[NTOK];
__device__ int   g_maxnear[1];
__device__ int   g_ni[NPAD];
__device__ float g_q[NPAD * CDIM];
__device__ float g_k[NPAD * CDIM];
__device__ float g_v[NPAD * CDIM];
__device__ float g_att[NPAD * CDIM];
__device__ float g_ffh[(size_t)NPAD * DFFN];
__device__ float g_y[NPAD * CDIM];

__device__ __forceinline__ float fexp(float x) {
    x = fmaxf(x, -87.0f);
    float y = x * 1.44269504088896341f;
    float r = rintf(y);
    float f = y - r;
    float p = 1.33335581e-3f;
    p = fmaf(p, f, 9.61812911e-3f);
    p = fmaf(p, f, 5.55041087e-2f);
    p = fmaf(p, f, 2.40226507e-1f);
    p = fmaf(p, f, 6.93147181e-1f);
    p = fmaf(p, f, 1.0f);
    return __int_as_float(__float_as_int(p) + (((int)r) << 23));
}

__device__ __forceinline__ unsigned f2tf32(float v) {
    unsigned r;
    asm("cvt.rna.tf32.f32 %0, %1;" : "=r"(r) : "f"(v));
    return r;
}

// pack two floats to bf16x2 (lo = first arg)
__device__ __forceinline__ unsigned pkbf(float lo, float hi) {
    unsigned r;
    asm("cvt.rn.bf16x2.f32 %0, %1, %2;" : "=r"(r) : "f"(hi), "f"(lo));
    return r;
}

__device__ __forceinline__ void mma_tf32(float c[4],
    unsigned a0, unsigned a1, unsigned a2, unsigned a3,
    unsigned b0, unsigned b1)
{
    asm volatile(
        "mma.sync.aligned.m16n8k8.row.col.f32.tf32.tf32.f32 "
        "{%0,%1,%2,%3}, {%4,%5,%6,%7}, {%8,%9}, {%0,%1,%2,%3};\n"
        : "+f"(c[0]), "+f"(c[1]), "+f"(c[2]), "+f"(c[3])
        : "r"(a0), "r"(a1), "r"(a2), "r"(a3), "r"(b0), "r"(b1));
}

__device__ __forceinline__ void mma_bf16(float c[4],
    unsigned a0, unsigned a1, unsigned a2, unsigned a3,
    unsigned b0, unsigned b1)
{
    asm volatile(
        "mma.sync.aligned.m16n8k16.row.col.f32.bf16.bf16.f32 "
        "{%0,%1,%2,%3}, {%4,%5,%6,%7}, {%8,%9}, {%0,%1,%2,%3};\n"
        : "+f"(c[0]), "+f"(c[1]), "+f"(c[2]), "+f"(c[3])
        : "r"(a0), "r"(a1), "r"(a2), "r"(a3), "r"(b0), "r"(b1));
}

__global__ void pad_kernel(float* __restrict__ x, float* __restrict__ sqv) {
    int i = blockIdx.x * 256 + threadIdx.x;
    x[NTOK * CDIM + i] = 0.f;
    if (i < NPAD - NTOK) sqv[NTOK + i] = 0.f;
}

__global__ void transpose_kernel(const float* __restrict__ src, float* __restrict__ dst) {
    __shared__ float tile[32][33];
    int t0 = blockIdx.x * 32, c0 = blockIdx.y * 32;
    int tx = threadIdx.x, ty = threadIdx.y;
    tile[ty][tx] = src[(c0 + ty) * NTOK + t0 + tx];
    __syncthreads();
    dst[(t0 + ty) * CDIM + c0 + tx] = tile[tx][ty];
}

__global__ __launch_bounds__(256) void conv1_kernel(
    const float* __restrict__ src, const float* __restrict__ wt,
    const float* __restrict__ bias, float* __restrict__ out)
{
    __shared__ float ws[4 * 2304];
    __shared__ float red[4 * 256];
    int cog = blockIdx.x;
    int tid = threadIdx.x;
    int px = tid & 63, cig = tid >> 6;
    int p = blockIdx.y * 64 + px;
    for (int i = tid; i < 4 * 2304; i += 256) ws[i] = wt[cog * 4 * 2304 + i];
    __syncthreads();
    int y = p / HW, x = p % HW;
    float a[4][2];
    #pragma unroll
    for (int j = 0; j < 4; j++) { a[j][0] = 0.f; a[j][1] = 0.f; }
    for (int ci = cig * 64; ci < cig * 64 + 64; ci += 2) {
        #pragma unroll
        for (int par = 0; par < 2; par++) {
            const float* ip = src + (ci + par) * NTOK;
            const float* wp = ws + (ci + par) * 9;
            #pragma unroll
            for (int dy = 0; dy < 3; dy++) {
                int yy = y + dy - 1; if ((unsigned)yy >= HW) continue;
                #pragma unroll
                for (int dx = 0; dx < 3; dx++) {
                    int xx = x + dx - 1; if ((unsigned)xx >= HW) continue;
                    float v = ip[yy * HW + xx]; int wi = dy * 3 + dx;
                    a[0][par] = fmaf(v, wp[wi],          a[0][par]);
                    a[1][par] = fmaf(v, wp[2304 + wi],   a[1][par]);
                    a[2][par] = fmaf(v, wp[4608 + wi],   a[2][par]);
                    a[3][par] = fmaf(v, wp[6912 + wi],   a[3][par]);
                }
            }
        }
    }
    #pragma unroll
    for (int j = 0; j < 4; j++) red[j * 256 + tid] = a[j][0] + a[j][1];
    __syncthreads();
    if (tid < 64) {
        #pragma unroll
        for (int j = 0; j < 4; j++) {
            float s = (red[j*256 + tid] + red[j*256 + tid + 64])
                    + (red[j*256 + tid + 128] + red[j*256 + tid + 192]);
            out[(cog*4+j)*NTOK + p] = fmaxf(s + bias[cog*4+j], 0.f);
        }
    }
}

__global__ __launch_bounds__(256) void conv2_kernel(
    const float* __restrict__ c1, const float* __restrict__ wt,
    const float* __restrict__ bias, float* __restrict__ gp)
{
    __shared__ float ws[1152];
    __shared__ float red[256];
    int co = blockIdx.x;
    int tid = threadIdx.x;
    int px = tid & 63, cig = tid >> 6;
    int p = blockIdx.y * 64 + px;
    for (int i = tid; i < 1152; i += 256) ws[i] = wt[co * 1152 + i];
    __syncthreads();
    int y = p / HW, x = p % HW;
    float a0 = 0.f, a1 = 0.f;
    for (int ci = cig * 32; ci < cig * 32 + 32; ci += 2) {
        #pragma unroll
        for (int dy = 0; dy < 3; dy++) {
            int yy = y + dy - 1; if ((unsigned)yy >= HW) continue;
            #pragma unroll
            for (int dx = 0; dx < 3; dx++) {
                int xx = x + dx - 1; if ((unsigned)xx >= HW) continue;
                int po = yy * HW + xx, wi = dy * 3 + dx;
                a0 = fmaf(c1[(ci+0) * NTOK + po], ws[(ci+0) * 9 + wi], a0);
                a1 = fmaf(c1[(ci+1) * NTOK + po], ws[(ci+1) * 9 + wi], a1);
            }
        }
    }
    red[tid] = a0 + a1;
    __syncthreads();
    if (tid < 64) {
        float a = bias[co] + (red[tid] + red[tid + 64]) + (red[tid + 128] + red[tid + 192]);
        gp[co * NTOK + p] = 1.0f / (1.0f + __expf(-a));
    }
}

__global__ __launch_bounds__(256) void sq_kernel(const float* __restrict__ x,
                                                 float* __restrict__ sq,
                                                 int* __restrict__ nearp,
                                                 int* __restrict__ maxn)
{
    int row = blockIdx.x * 8 + (threadIdx.x >> 5);
    int lane = threadIdx.x & 31;
    const float* r = x + row * CDIM;
    float s = 0.f;
    #pragma unroll
    for (int i = 0; i < 8; i++) { float v = r[lane + i * 32]; s = fmaf(v, v, s); }
    #pragma unroll
    for (int o = 16; o; o >>= 1) s += __shfl_xor_sync(0xffffffffu, s, o);
    if (lane == 0) {
        sq[row] = s;
        if (row < NTOK) nearp[row] = 0;
        if (row == 0) *maxn = 0;
    }
}

__global__ __launch_bounds__(256) void d2_tf32_kernel(
    const float* __restrict__ X, const float* __restrict__ sqv,
    float* __restrict__ C)
{
    __shared__ float As[128 * 36];
    __shared__ float Bs[128 * 36];
    const int tid = threadIdx.x;
    const int wid = tid >> 5, lane = tid & 31;
    const int warpM = wid >> 2, warpN = wid & 3;
    const int i0 = blockIdx.x * 128, j0 = blockIdx.y * 128;
    const int gid = lane >> 2, qid = lane & 3;

    float acc[4][4][4];
    #pragma unroll
    for (int a = 0; a < 4; a++)
        #pragma unroll
        for (int b = 0; b < 4; b++)
            #pragma unroll
            for (int c = 0; c < 4; c++) acc[a][b][c] = 0.f;

    const int lrow = tid >> 1;
    const int lk = (tid & 1) * 16;
    const float* Ag = X + (size_t)(i0 + lrow) * CDIM + lk;
    const float* Bg = X + (size_t)(j0 + lrow) * CDIM + lk;
    float* Asw = As + lrow * 36 + lk;
    float* Bsw = Bs + lrow * 36 + lk;

    float4 pa[4], pb[4];
    #pragma unroll
    for (int q = 0; q < 4; q++) {
        pa[q] = *(const float4*)(Ag + q * 4);
        pb[q] = *(const float4*)(Bg + q * 4);
    }
    for (int k0 = 0; k0 < CDIM; k0 += 32) {
        __syncthreads();
        #pragma unroll
        for (int q = 0; q < 4; q++) {
            float4 at, bt;
            at.x = __uint_as_float(f2tf32(pa[q].x)); at.y = __uint_as_float(f2tf32(pa[q].y));
            at.z = __uint_as_float(f2tf32(pa[q].z)); at.w = __uint_as_float(f2tf32(pa[q].w));
            bt.x = __uint_as_float(f2tf32(pb[q].x)); bt.y = __uint_as_float(f2tf32(pb[q].y));
            bt.z = __uint_as_float(f2tf32(pb[q].z)); bt.w = __uint_as_float(f2tf32(pb[q].w));
            *(float4*)&Asw[q * 4] = at;
            *(float4*)&Bsw[q * 4] = bt;
        }
        __syncthreads();
        if (k0 + 32 < CDIM) {
            #pragma unroll
            for (int q = 0; q < 4; q++) {
                pa[q] = *(const float4*)(Ag + k0 + 32 + q * 4);
                pb[q] = *(const float4*)(Bg + k0 + 32 + q * 4);
            }
        }
        #pragma unroll
        for (int k8 = 0; k8 < 4; k8++) {
            unsigned af[4][4], bf[4][2];
            #pragma unroll
            for (int tm = 0; tm < 4; tm++) {
                const float* p = As + (warpM * 64 + tm * 16 + gid) * 36 + k8 * 8 + qid;
                af[tm][0] = __float_as_uint(p[0]);
                af[tm][1] = __float_as_uint(p[8 * 36]);
                af[tm][2] = __float_as_uint(p[4]);
                af[tm][3] = __float_as_uint(p[8 * 36 + 4]);
            }
            #pragma unroll
            for (int tn = 0; tn < 4; tn++) {
                const float* p = Bs + (warpN * 32 + tn * 8 + gid) * 36 + k8 * 8 + qid;
                bf[tn][0] = __float_as_uint(p[0]);
                bf[tn][1] = __float_as_uint(p[4]);
            }
            #pragma unroll
            for (int tm = 0; tm < 4; tm++)
                #pragma unroll
                for (int tn = 0; tn < 4; tn++)
                    mma_tf32(acc[tm][tn], af[tm][0], af[tm][1], af[tm][2], af[tm][3],
                             bf[tn][0], bf[tn][1]);
        }
    }

    #pragma unroll
    for (int tm = 0; tm < 4; tm++) {
        const int r0 = i0 + warpM * 64 + tm * 16 + gid;
        const float sr0 = sqv[r0], sr1 = sqv[r0 + 8];
        #pragma unroll
        for (int tn = 0; tn < 4; tn++) {
            const int c0i = j0 + warpN * 32 + tn * 8 + qid * 2;
            const float sc0 = sqv[c0i], sc1 = sqv[c0i + 1];
            float2 v0, v1;
            v0.x = sr0 + sc0 - 2.f * acc[tm][tn][0];
            v0.y = sr0 + sc1 - 2.f * acc[tm][tn][1];
            v1.x = sr1 + sc0 - 2.f * acc[tm][tn][2];
            v1.y = sr1 + sc1 - 2.f * acc[tm][tn][3];
            *(float2*)&C[(size_t)r0 * NPAD + c0i] = v0;
            *(float2*)&C[(size_t)(r0 + 8) * NPAD + c0i] = v1;
        }
    }
}

// single-pass tf32 64x64 GEMM with register prefetch; ADDEMB adds emb[ni[row]]
template<int EPI, int ADDEMB>
__device__ __forceinline__ void gemm64(
    const float* __restrict__ A, const float* __restrict__ B,
    const float* __restrict__ bias, float* __restrict__ C,
    int Nn, int K, int i0, int j0,
    const int* __restrict__ ni, const float* __restrict__ emb)
{
    __shared__ float Ah[64 * 36], Bh[64 * 36];
    const int tid = threadIdx.x;
    const int wid = tid >> 5, lane = tid & 31;
    const int warpM = wid >> 1, warpN = wid & 1;
    const int gid = lane >> 2, qid = lane & 3;

    float acc[2][4][4];
    #pragma unroll
    for (int a = 0; a < 2; a++)
        #pragma unroll
        for (int b = 0; b < 4; b++)
            #pragma unroll
            for (int c = 0; c < 4; c++) acc[a][b][c] = 0.f;

    const int lrow = tid >> 1;
    const int lk = (tid & 1) * 16;
    const float* Ag = A + (size_t)(i0 + lrow) * K + lk;
    const float* Bg = B + (size_t)(j0 + lrow) * K + lk;
    const float* Eg = ADDEMB ? (emb + (size_t)ni[i0 + lrow] * CDIM + lk) : nullptr;
    const int sbase = lrow * 36 + lk;

    float4 pa[4], pb[4];
    #pragma unroll
    for (int q = 0; q < 4; q++) {
        pa[q] = *(const float4*)(Ag + q * 4);
        pb[q] = *(const float4*)(Bg + q * 4);
        if (ADDEMB) {
            float4 ev = *(const float4*)(Eg + q * 4);
            pa[q].x += ev.x; pa[q].y += ev.y; pa[q].z += ev.z; pa[q].w += ev.w;
        }
    }
    for (int k0 = 0; k0 < K; k0 += 32) {
        __syncthreads();
        #pragma unroll
        for (int q = 0; q < 4; q++) {
            float4 at, bt;
            at.x = __uint_as_float(f2tf32(pa[q].x)); at.y = __uint_as_float(f2tf32(pa[q].y));
            at.z = __uint_as_float(f2tf32(pa[q].z)); at.w = __uint_as_float(f2tf32(pa[q].w));
            bt.x = __uint_as_float(f2tf32(pb[q].x)); bt.y = __uint_as_float(f2tf32(pb[q].y));
            bt.z = __uint_as_float(f2tf32(pb[q].z)); bt.w = __uint_as_float(f2tf32(pb[q].w));
            *(float4*)&Ah[sbase + q * 4] = at;
            *(float4*)&Bh[sbase + q * 4] = bt;
        }
        __syncthreads();
        if (k0 + 32 < K) {
            #pragma unroll
            for (int q = 0; q < 4; q++) {
                pa[q] = *(const float4*)(Ag + k0 + 32 + q * 4);
                pb[q] = *(const float4*)(Bg + k0 + 32 + q * 4);
                if (ADDEMB) {
                    float4 ev = *(const float4*)(Eg + k0 + 32 + q * 4);
                    pa[q].x += ev.x; pa[q].y += ev.y; pa[q].z += ev.z; pa[q].w += ev.w;
                }
            }
        }
        #pragma unroll
        for (int k8 = 0; k8 < 4; k8++) {
            unsigned af[2][4], bf[4][2];
            #pragma unroll
            for (int tm = 0; tm < 2; tm++) {
                const int off = (warpM * 32 + tm * 16 + gid) * 36 + k8 * 8 + qid;
                af[tm][0] = __float_as_uint(Ah[off]);
                af[tm][1] = __float_as_uint(Ah[off + 8 * 36]);
                af[tm][2] = __float_as_uint(Ah[off + 4]);
                af[tm][3] = __float_as_uint(Ah[off + 8 * 36 + 4]);
            }
            #pragma unroll
            for (int tn = 0; tn < 4; tn++) {
                const int off = (warpN * 32 + tn * 8 + gid) * 36 + k8 * 8 + qid;
                bf[tn][0] = __float_as_uint(Bh[off]);
                bf[tn][1] = __float_as_uint(Bh[off + 4]);
            }
            #pragma unroll
            for (int tm = 0; tm < 2; tm++)
                #pragma unroll
                for (int tn = 0; tn < 4; tn++)
                    mma_tf32(acc[tm][tn], af[tm][0], af[tm][1], af[tm][2], af[tm][3],
                             bf[tn][0], bf[tn][1]);
        }
    }

    #pragma unroll
    for (int tm = 0; tm < 2; tm++) {
        const int r0 = i0 + warpM * 32 + tm * 16 + gid;
        #pragma unroll
        for (int tn = 0; tn < 4; tn++) {
            const int c0i = j0 + warpN * 32 + tn * 8 + qid * 2;
            const float b0 = bias[c0i], b1 = bias[c0i + 1];
            float2 v0, v1;
            v0.x = acc[tm][tn][0] + b0; v0.y = acc[tm][tn][1] + b1;
            v1.x = acc[tm][tn][2] + b0; v1.y = acc[tm][tn][3] + b1;
            if (EPI == 1) {
                v0.x = fmaxf(v0.x, 0.f); v0.y = fmaxf(v0.y, 0.f);
                v1.x = fmaxf(v1.x, 0.f); v1.y = fmaxf(v1.y, 0.f);
            }
            *(float2*)&C[(size_t)r0 * Nn + c0i] = v0;
            *(float2*)&C[(size_t)(r0 + 8) * Nn + c0i] = v1;
        }
    }
}

template<int EPI>
__global__ __launch_bounds__(128) void mma1_gemm(
    const float* __restrict__ A, const float* __restrict__ B,
    const float* __restrict__ bias, float* __restrict__ C,
    int Nn, int K)
{
    gemm64<EPI, 0>(A, B, bias, C, Nn, K, blockIdx.x * 64, blockIdx.y * 64,
                   nullptr, nullptr);
}

__global__ __launch_bounds__(128) void qkv_gemm(
    const float* __restrict__ x, const int* __restrict__ ni,
    const float* __restrict__ emb,
    const float* __restrict__ Wq, const float* __restrict__ Wk,
    const float* __restrict__ Wv,
    const float* __restrict__ bq, const float* __restrict__ bk,
    const float* __restrict__ bv,
    float* __restrict__ q, float* __restrict__ k, float* __restrict__ v)
{
    int sel = blockIdx.y >> 2, jb = blockIdx.y & 3;
    if (sel == 2) {
        gemm64<0, 0>(x, Wv, bv, v, CDIM, CDIM, blockIdx.x * 64, jb * 64,
                     nullptr, nullptr);
    } else if (sel == 0) {
        gemm64<0, 1>(x, Wq, bq, q, CDIM, CDIM, blockIdx.x * 64, jb * 64, ni, emb);
    } else {
        gemm64<0, 1>(x, Wk, bk, k, CDIM, CDIM, blockIdx.x * 64, jb * 64, ni, emb);
    }
}

__global__ __launch_bounds__(256) void topk_kernel(const float* __restrict__ d2,
                                                   int* __restrict__ nearp)
{
    __shared__ float vals[NTOK];
    __shared__ float wv[8];
    __shared__ int   wi[8];
    int row = blockIdx.x, tid = threadIdx.x;
    int lane = tid & 31, w = tid >> 5;
    const float* rp = d2 + (size_t)row * NPAD;
    for (int i = tid; i < NTOK; i += 256) vals[i] = rp[i];
    __syncthreads();
    for (int it = 0; it < TOPKK; it++) {
        float bv = 3.0e38f; int bi = 0x7FFFFFFF;
        for (int i = tid; i < NTOK; i += 256) {
            float v = vals[i];
            if (v < bv) { bv = v; bi = i; }
        }
        #pragma unroll
        for (int o = 16; o; o >>= 1) {
            float ov = __shfl_xor_sync(0xffffffffu, bv, o);
            int   oi = __shfl_xor_sync(0xffffffffu, bi, o);
            if (ov < bv || (ov == bv && oi < bi)) { bv = ov; bi = oi; }
        }
        if (lane == 0) { wv[w] = bv; wi[w] = bi; }
        __syncthreads();
        if (w == 0) {
            float fv = (lane < 8) ? wv[lane] : 3.0e38f;
            int   fi = (lane < 8) ? wi[lane] : 0x7FFFFFFF;
            #pragma unroll
            for (int o = 4; o; o >>= 1) {
                float ov = __shfl_xor_sync(0xffffffffu, fv, o);
                int   oi = __shfl_xor_sync(0xffffffffu, fi, o);
                if (ov < fv || (ov == fv && oi < fi)) { fv = ov; fi = oi; }
            }
            if (lane == 0) {
                atomicAdd(&nearp[fi], 1);
                vals[fi] = 3.0e38f;
            }
        }
        __syncthreads();
    }
}

__global__ __launch_bounds__(256) void maxni_kernel(const int* __restrict__ nearp,
                                                    int* __restrict__ ni)
{
    __shared__ int sm[256];
    int tid = threadIdx.x;
    int m = 0;
    for (int i = tid; i < NTOK; i += 256) m = max(m, nearp[i]);
    sm[tid] = m;
    __syncthreads();
    for (int s = 128; s > 0; s >>= 1) {
        if (tid < s) sm[tid] = max(sm[tid], sm[tid+s]);
        __syncthreads();
    }
    float mf = (float)sm[0];
    for (int i = tid; i < NPAD; i += 256) {
        int r = 0;
        if (i < NTOK) {
            r = (int)(((float)nearp[i] / mf) * 9.0f);
            if (r > 9) r = 9;
        }
        ni[i] = r;
    }
}

// Flash attention: bf16 m16n8k16 MMA, 64 queries/block, 4 warps split keys.
// Qs/Ks: [rows][40] bf16 (K-major), Vts: [32 d][72 keys] bf16, Ps: per-warp
// [16][72] bf16. fp32 softmax; C-fragment layout identical to tf32 path.
__global__ __launch_bounds__(128) void attn_kernel(
    const float* __restrict__ Q, const float* __restrict__ Km,
    const float* __restrict__ V, const float* __restrict__ gp,
    float* __restrict__ O)
{
    __shared__ __nv_bfloat16 Qs[64 * 40];
    __shared__ __nv_bfloat16 Ks[64 * 40];
    __shared__ __nv_bfloat16 Vts[32 * 72];
    __shared__ __nv_bfloat16 Ps[4 * 16 * 72];
    __shared__ float gks[64];

    const int h = blockIdx.y, qb = blockIdx.x, tid = threadIdx.x;
    const int w = tid >> 5, lane = tid & 31;
    const int gid = lane >> 2, qid = lane & 3;
    const float scale = 0.17677669529663687f;

    #pragma unroll
    for (int u = tid; u < 512; u += 128) {
        int i = u >> 3, dq = (u & 7) * 4;
        float4 t = *(const float4*)(Q + (size_t)(qb * 64 + i) * CDIM + h * 32 + dq);
        uint2 pk;
        pk.x = pkbf(t.x * scale, t.y * scale);
        pk.y = pkbf(t.z * scale, t.w * scale);
        *(uint2*)&Qs[i * 40 + dq] = pk;
    }
    const float gq0 = gp[h * NTOK + qb * 64 + w * 16 + gid];
    const float gq1 = gp[h * NTOK + qb * 64 + w * 16 + gid + 8];

    float oacc[4][4];
    #pragma unroll
    for (int dt = 0; dt < 4; dt++)
        #pragma unroll
        for (int c = 0; c < 4; c++) oacc[dt][c] = 0.f;
    float m0 = -1e30f, m1 = -1e30f, l0 = 0.f, l1 = 0.f;
    __nv_bfloat16* Pw = Ps + w * (16 * 72);

    for (int kt = 0; kt < 49; kt++) {
        __syncthreads();
        #pragma unroll
        for (int u = tid; u < 512; u += 128) {
            int j = u >> 3, dq = (u & 7) * 4;
            size_t gbase = (size_t)(kt * 64 + j) * CDIM + h * 32 + dq;
            float4 kv = *(const float4*)(Km + gbase);
            float4 vv = *(const float4*)(V + gbase);
            uint2 pk;
            pk.x = pkbf(kv.x, kv.y);
            pk.y = pkbf(kv.z, kv.w);
            *(uint2*)&Ks[j * 40 + dq] = pk;
            Vts[(dq + 0) * 72 + j] = __float2bfloat16_rn(vv.x);
            Vts[(dq + 1) * 72 + j] = __float2bfloat16_rn(vv.y);
            Vts[(dq + 2) * 72 + j] = __float2bfloat16_rn(vv.z);
            Vts[(dq + 3) * 72 + j] = __float2bfloat16_rn(vv.w);
        }
        if (tid < 64) gks[tid] = gp[h * NTOK + kt * 64 + tid];
        __syncthreads();

        // S = Q K^T  (2 x k16 steps, 8 n-tiles)
        float sc[8][4];
        #pragma unroll
        for (int tn = 0; tn < 8; tn++)
            #pragma unroll
            for (int c = 0; c < 4; c++) sc[tn][c] = 0.f;
        #pragma unroll
        for (int k16 = 0; k16 < 2; k16++) {
            const int ao = (w * 16 + gid) * 40 + k16 * 16 + qid * 2;
            unsigned a0 = *(const unsigned*)&Qs[ao];
            unsigned a1 = *(const unsigned*)&Qs[ao + 8 * 40];
            unsigned a2 = *(const unsigned*)&Qs[ao + 8];
            unsigned a3 = *(const unsigned*)&Qs[ao + 8 * 40 + 8];
            #pragma unroll
            for (int tn = 0; tn < 8; tn++) {
                const int bo = (tn * 8 + gid) * 40 + k16 * 16 + qid * 2;
                mma_bf16(sc[tn], a0, a1, a2, a3,
                         *(const unsigned*)&Ks[bo], *(const unsigned*)&Ks[bo + 8]);
            }
        }
        float mn0 = -1e30f, mn1 = -1e30f;
        #pragma unroll
        for (int tn = 0; tn < 8; tn++) {
            float ga = gks[tn * 8 + qid * 2], gb = gks[tn * 8 + qid * 2 + 1];
            sc[tn][0] += fabsf(gq0 - ga); sc[tn][1] += fabsf(gq0 - gb);
            sc[tn][2] += fabsf(gq1 - ga); sc[tn][3] += fabsf(gq1 - gb);
            mn0 = fmaxf(mn0, fmaxf(sc[tn][0], sc[tn][1]));
            mn1 = fmaxf(mn1, fmaxf(sc[tn][2], sc[tn][3]));
        }
        mn0 = fmaxf(mn0, __shfl_xor_sync(0xffffffffu, mn0, 1));
        mn0 = fmaxf(mn0, __shfl_xor_sync(0xffffffffu, mn0, 2));
        mn1 = fmaxf(mn1, __shfl_xor_sync(0xffffffffu, mn1, 1));
        mn1 = fmaxf(mn1, __shfl_xor_sync(0xffffffffu, mn1, 2));
        if (mn0 > m0) {
            float corr = fexp(m0 - mn0);
            l0 *= corr;
            #pragma unroll
            for (int dt = 0; dt < 4; dt++) { oacc[dt][0] *= corr; oacc[dt][1] *= corr; }
            m0 = mn0;
        }
        if (mn1 > m1) {
            float corr = fexp(m1 - mn1);
            l1 *= corr;
            #pragma unroll
            for (int dt = 0; dt < 4; dt++) { oacc[dt][2] *= corr; oacc[dt][3] *= corr; }
            m1 = mn1;
        }
        float ps0 = 0.f, ps1 = 0.f;
        #pragma unroll
        for (int tn = 0; tn < 8; tn++) {
            float p00 = fexp(sc[tn][0] - m0), p01 = fexp(sc[tn][1] - m0);
            float p10 = fexp(sc[tn][2] - m1), p11 = fexp(sc[tn][3] - m1);
            ps0 += p00 + p01; ps1 += p10 + p11;
            int col = tn * 8 + qid * 2;
            *(unsigned*)&Pw[gid * 72 + col]       = pkbf(p00, p01);
            *(unsigned*)&Pw[(gid + 8) * 72 + col] = pkbf(p10, p11);
        }
        ps0 += __shfl_xor_sync(0xffffffffu, ps0, 1);
        ps0 += __shfl_xor_sync(0xffffffffu, ps0, 2);
        ps1 += __shfl_xor_sync(0xffffffffu, ps1, 1);
        ps1 += __shfl_xor_sync(0xffffffffu, ps1, 2);
        l0 += ps0; l1 += ps1;
        __syncwarp();
        // O += P V  (4 x k16 steps over 64 keys, 4 d-tiles)
        #pragma unroll
        for (int k16 = 0; k16 < 4; k16++) {
            const int ao = gid * 72 + k16 * 16 + qid * 2;
            unsigned a0 = *(const unsigned*)&Pw[ao];
            unsigned a1 = *(const unsigned*)&Pw[ao + 8 * 72];
            unsigned a2 = *(const unsigned*)&Pw[ao + 8];
            unsigned a3 = *(const unsigned*)&Pw[ao + 8 * 72 + 8];
            #pragma unroll
            for (int dt = 0; dt < 4; dt++) {
                const int bo = (dt * 8 + gid) * 72 + k16 * 16 + qid * 2;
                mma_bf16(oacc[dt], a0, a1, a2, a3,
                         *(const unsigned*)&Vts[bo], *(const unsigned*)&Vts[bo + 8]);
            }
        }
        __syncwarp();
    }

    const float inv0 = 1.f / l0, inv1 = 1.f / l1;
    const int r0g = qb * 64 + w * 16 + gid, r1g = r0g + 8;
    #pragma unroll
    for (int dt = 0; dt < 4; dt++) {
        const int col = h * 32 + dt * 8 + qid * 2;
        float2 v0, v1;
        v0.x = oacc[dt][0] * inv0; v0.y = oacc[dt][1] * inv0;
        v1.x = oacc[dt][2] * inv1; v1.y = oacc[dt][3] * inv1;
        *(float2*)&O[(size_t)r0g * CDIM + col] = v0;
        *(float2*)&O[(size_t)r1g * CDIM + col] = v1;
    }
}

// one-pass LN: sum and sumsq reduced together
template<int FINAL>
__global__ __launch_bounds__(256) void add_ln_kernel(
    const float* __restrict__ a, const float* __restrict__ b,
    const float* __restrict__ g, const float* __restrict__ be,
    float* __restrict__ out)
{
    __shared__ float red1[8], red2[8];
    int row = blockIdx.x, tid = threadIdx.x;
    float v = a[row * CDIM + tid];
    if (!FINAL) v += b[row * CDIM + tid];
    float s1 = v, s2 = v * v;
    #pragma unroll
    for (int o = 16; o; o >>= 1) {
        s1 += __shfl_xor_sync(0xffffffffu, s1, o);
        s2 += __shfl_xor_sync(0xffffffffu, s2, o);
    }
    if ((tid & 31) == 0) { red1[tid >> 5] = s1; red2[tid >> 5] = s2; }
    __syncthreads();
    float mean = 0.f, ex2 = 0.f;
    #pragma unroll
    for (int i = 0; i < 8; i++) { mean += red1[i]; ex2 += red2[i]; }
    mean *= (1.f / 256.f);
    ex2  *= (1.f / 256.f);
    float var = ex2 - mean * mean;
    float r = (v - mean) * rsqrtf(var + 1e-5f) * g[tid] + be[tid];
    if (FINAL) out[tid * NTOK + row] = r;
    else       out[row * CDIM + tid] = r;
}

extern "C" void kernel_launch(void* const* d_in, const int* in_sizes, int n_in,
                              void* d_out, int out_size)
{
    (void)in_sizes; (void)n_in; (void)out_size;
    const float* src  = (const float*)d_in[0];
    const float* c1w  = (const float*)d_in[1];
    const float* c1b  = (const float*)d_in[2];
    const float* c2w  = (const float*)d_in[3];
    const float* c2b  = (const float*)d_in[4];
    const float* nemb = (const float*)d_in[5];
    const float* Wq   = (const float*)d_in[6];
    const float* bq   = (const float*)d_in[7];
    const float* Wk   = (const float*)d_in[8];
    const float* bk   = (const float*)d_in[9];
    const float* Wv   = (const float*)d_in[10];
    const float* bv   = (const float*)d_in[11];
    const float* Wo   = (const float*)d_in[12];
    const float* bo   = (const float*)d_in[13];
    const float* W1   = (const float*)d_in[14];
    const float* b1   = (const float*)d_in[15];
    const float* W2   = (const float*)d_in[16];
    const float* b2   = (const float*)d_in[17];
    const float* ln1g = (const float*)d_in[18];
    const float* ln1b = (const float*)d_in[19];
    const float* ln2g = (const float*)d_in[20];
    const float* ln2b = (const float*)d_in[21];
    const float* ng   = (const float*)d_in[22];
    const float* nb   = (const float*)d_in[23];

    float *c1, *gp, *x, *sqv, *d2, *q, *k, *v, *att, *ffh, *yb;
    int *nearp, *maxn, *niv;
    cudaGetSymbolAddress((void**)&c1,    g_c1);
    cudaGetSymbolAddress((void**)&gp,    g_gp);
    cudaGetSymbolAddress((void**)&x,     g_x);
    cudaGetSymbolAddress((void**)&sqv,   g_sq);
    cudaGetSymbolAddress((void**)&d2,    g_d2);
    cudaGetSymbolAddress((void**)&nearp, g_near);
    cudaGetSymbolAddress((void**)&maxn,  g_maxnear);
    cudaGetSymbolAddress((void**)&niv,   g_ni);
    cudaGetSymbolAddress((void**)&q,     g_q);
    cudaGetSymbolAddress((void**)&k,     g_k);
    cudaGetSymbolAddress((void**)&v,     g_v);
    cudaGetSymbolAddress((void**)&att,   g_att);
    cudaGetSymbolAddress((void**)&ffh,   g_ffh);
    cudaGetSymbolAddress((void**)&yb,    g_y);

    pad_kernel<<<64, 256>>>(x, sqv);
    transpose_kernel<<<dim3(98, 8), dim3(32, 32)>>>(src, x);
    conv1_kernel<<<dim3(32, 49), 256>>>(src, c1w, c1b, c1);
    conv2_kernel<<<dim3(8, 49), 256>>>(c1, c2w, c2b, gp);

    for (int i = 0; i < NLAYER; i++) {
        sq_kernel<<<400, 256>>>(x, sqv, nearp, maxn);
        d2_tf32_kernel<<<dim3(25, 25), 256>>>(x, sqv, d2);
        topk_kernel<<<NTOK, 256>>>(d2, nearp);
        maxni_kernel<<<1, 256>>>(nearp, niv);

        qkv_gemm<<<dim3(50, 12), 128>>>(x, niv, nemb,
            Wq + i*CDIM*CDIM, Wk + i*CDIM*CDIM, Wv + i*CDIM*CDIM,
            bq + i*CDIM, bk + i*CDIM, bv + i*CDIM, q, k, v);

        attn_kernel<<<dim3(49, NHEAD), 128>>>(q, k, v, gp, att);

        mma1_gemm<0><<<dim3(50, 4), 128>>>(att, Wo + i*CDIM*CDIM, bo + i*CDIM, yb, CDIM, CDIM);
        add_ln_kernel<0><<<NTOK, 256>>>(x, yb, ln1g + i*CDIM, ln1b + i*CDIM, x);

        mma1_gemm<1><<<dim3(50, 16), 128>>>(x, W1 + i*DFFN*CDIM, b1 + i*DFFN, ffh, DFFN, CDIM);
        mma1_gemm<0><<<dim3(50, 4), 128>>>(ffh, W2 + i*CDIM*DFFN, b2 + i*CDIM, yb, CDIM, DFFN);
        add_ln_kernel<0><<<NTOK, 256>>>(x, yb, ln2g + i*CDIM, ln2b + i*CDIM, x);
    }

    add_ln_kernel<1><<<NTOK, 256>>>(x, nullptr, ng, nb, (float*)d_out);
}

// round 16
// speedup vs baseline: 1.3183x; 1.0485x over previous
#include <cuda_runtime.h>
#include <cuda_bf16.h>
#include <cstdint>
#include <math.h>

#define NTOK 3136
#define NPAD 3200
#define CDIM 256
#define NHEAD 8
#define DFFN 1024
#define NLAYER 4
#define TOPKK 16
#define HW 56

__device__ float g_c1[128 * NTOK];
__device__ float g_gp[NHEAD * NTOK];
__device__ float g_x[NPAD * CDIM];
__device__ float g_sq[NPAD];
__device__ float g_d2[(size_t)NPAD * NPAD];
__device__ int   g_near[NTOK];
__device__ int   g_maxnear[1];
__device__ int   g_ni[NPAD];
__device__ float g_q[NPAD * CDIM];
__device__ float g_k[NPAD * CDIM];
__device__ float g_v[NPAD * CDIM];
__device__ float g_att[NPAD * CDIM];
__device__ float g_ffh[(size_t)NPAD * DFFN];
__device__ float g_y[NPAD * CDIM];

__device__ __forceinline__ float fexp(float x) {
    x = fmaxf(x, -87.0f);
    float y = x * 1.44269504088896341f;
    float r = rintf(y);
    float f = y - r;
    float p = 1.33335581e-3f;
    p = fmaf(p, f, 9.61812911e-3f);
    p = fmaf(p, f, 5.55041087e-2f);
    p = fmaf(p, f, 2.40226507e-1f);
    p = fmaf(p, f, 6.93147181e-1f);
    p = fmaf(p, f, 1.0f);
    return __int_as_float(__float_as_int(p) + (((int)r) << 23));
}

__device__ __forceinline__ unsigned f2tf32(float v) {
    unsigned r;
    asm("cvt.rna.tf32.f32 %0, %1;" : "=r"(r) : "f"(v));
    return r;
}

// pack two floats to bf16x2 (lo = first arg)
__device__ __forceinline__ unsigned pkbf(float lo, float hi) {
    unsigned r;
    asm("cvt.rn.bf16x2.f32 %0, %1, %2;" : "=r"(r) : "f"(hi), "f"(lo));
    return r;
}

__device__ __forceinline__ void mma_tf32(float c[4],
    unsigned a0, unsigned a1, unsigned a2, unsigned a3,
    unsigned b0, unsigned b1)
{
    asm volatile(
        "mma.sync.aligned.m16n8k8.row.col.f32.tf32.tf32.f32 "
        "{%0,%1,%2,%3}, {%4,%5,%6,%7}, {%8,%9}, {%0,%1,%2,%3};\n"
        : "+f"(c[0]), "+f"(c[1]), "+f"(c[2]), "+f"(c[3])
        : "r"(a0), "r"(a1), "r"(a2), "r"(a3), "r"(b0), "r"(b1));
}

__device__ __forceinline__ void mma_bf16(float c[4],
    unsigned a0, unsigned a1, unsigned a2, unsigned a3,
    unsigned b0, unsigned b1)
{
    asm volatile(
        "mma.sync.aligned.m16n8k16.row.col.f32.bf16.bf16.f32 "
        "{%0,%1,%2,%3}, {%4,%5,%6,%7}, {%8,%9}, {%0,%1,%2,%3};\n"
        : "+f"(c[0]), "+f"(c[1]), "+f"(c[2]), "+f"(c[3])
        : "r"(a0), "r"(a1), "r"(a2), "r"(a3), "r"(b0), "r"(b1));
}

__global__ void pad_kernel(float* __restrict__ x, float* __restrict__ sqv) {
    int i = blockIdx.x * 256 + threadIdx.x;
    x[NTOK * CDIM + i] = 0.f;
    if (i < NPAD - NTOK) sqv[NTOK + i] = 0.f;
}

__global__ void transpose_kernel(const float* __restrict__ src, float* __restrict__ dst) {
    __shared__ float tile[32][33];
    int t0 = blockIdx.x * 32, c0 = blockIdx.y * 32;
    int tx = threadIdx.x, ty = threadIdx.y;
    tile[ty][tx] = src[(c0 + ty) * NTOK + t0 + tx];
    __syncthreads();
    dst[(t0 + ty) * CDIM + c0 + tx] = tile[tx][ty];
}

__global__ __launch_bounds__(256) void conv1_kernel(
    const float* __restrict__ src, const float* __restrict__ wt,
    const float* __restrict__ bias, float* __restrict__ out)
{
    __shared__ float ws[4 * 2304];
    __shared__ float red[4 * 256];
    int cog = blockIdx.x;
    int tid = threadIdx.x;
    int px = tid & 63, cig = tid >> 6;
    int p = blockIdx.y * 64 + px;
    for (int i = tid; i < 4 * 2304; i += 256) ws[i] = wt[cog * 4 * 2304 + i];
    __syncthreads();
    int y = p / HW, x = p % HW;
    float a[4][2];
    #pragma unroll
    for (int j = 0; j < 4; j++) { a[j][0] = 0.f; a[j][1] = 0.f; }
    for (int ci = cig * 64; ci < cig * 64 + 64; ci += 2) {
        #pragma unroll
        for (int par = 0; par < 2; par++) {
            const float* ip = src + (ci + par) * NTOK;
            const float* wp = ws + (ci + par) * 9;
            #pragma unroll
            for (int dy = 0; dy < 3; dy++) {
                int yy = y + dy - 1; if ((unsigned)yy >= HW) continue;
                #pragma unroll
                for (int dx = 0; dx < 3; dx++) {
                    int xx = x + dx - 1; if ((unsigned)xx >= HW) continue;
                    float v = ip[yy * HW + xx]; int wi = dy * 3 + dx;
                    a[0][par] = fmaf(v, wp[wi],          a[0][par]);
                    a[1][par] = fmaf(v, wp[2304 + wi],   a[1][par]);
                    a[2][par] = fmaf(v, wp[4608 + wi],   a[2][par]);
                    a[3][par] = fmaf(v, wp[6912 + wi],   a[3][par]);
                }
            }
        }
    }
    #pragma unroll
    for (int j = 0; j < 4; j++) red[j * 256 + tid] = a[j][0] + a[j][1];
    __syncthreads();
    if (tid < 64) {
        #pragma unroll
        for (int j = 0; j < 4; j++) {
            float s = (red[j*256 + tid] + red[j*256 + tid + 64])
                    + (red[j*256 + tid + 128] + red[j*256 + tid + 192]);
            out[(cog*4+j)*NTOK + p] = fmaxf(s + bias[cog*4+j], 0.f);
        }
    }
}

__global__ __launch_bounds__(256) void conv2_kernel(
    const float* __restrict__ c1, const float* __restrict__ wt,
    const float* __restrict__ bias, float* __restrict__ gp)
{
    __shared__ float ws[1152];
    __shared__ float red[256];
    int co = blockIdx.x;
    int tid = threadIdx.x;
    int px = tid & 63, cig = tid >> 6;
    int p = blockIdx.y * 64 + px;
    for (int i = tid; i < 1152; i += 256) ws[i] = wt[co * 1152 + i];
    __syncthreads();
    int y = p / HW, x = p % HW;
    float a0 = 0.f, a1 = 0.f;
    for (int ci = cig * 32; ci < cig * 32 + 32; ci += 2) {
        #pragma unroll
        for (int dy = 0; dy < 3; dy++) {
            int yy = y + dy - 1; if ((unsigned)yy >= HW) continue;
            #pragma unroll
            for (int dx = 0; dx < 3; dx++) {
                int xx = x + dx - 1; if ((unsigned)xx >= HW) continue;
                int po = yy * HW + xx, wi = dy * 3 + dx;
                a0 = fmaf(c1[(ci+0) * NTOK + po], ws[(ci+0) * 9 + wi], a0);
                a1 = fmaf(c1[(ci+1) * NTOK + po], ws[(ci+1) * 9 + wi], a1);
            }
        }
    }
    red[tid] = a0 + a1;
    __syncthreads();
    if (tid < 64) {
        float a = bias[co] + (red[tid] + red[tid + 64]) + (red[tid + 128] + red[tid + 192]);
        gp[co * NTOK + p] = 1.0f / (1.0f + __expf(-a));
    }
}

__global__ __launch_bounds__(256) void sq_kernel(const float* __restrict__ x,
                                                 float* __restrict__ sq,
                                                 int* __restrict__ nearp,
                                                 int* __restrict__ maxn)
{
    int row = blockIdx.x * 8 + (threadIdx.x >> 5);
    int lane = threadIdx.x & 31;
    const float* r = x + row * CDIM;
    float s = 0.f;
    #pragma unroll
    for (int i = 0; i < 8; i++) { float v = r[lane + i * 32]; s = fmaf(v, v, s); }
    #pragma unroll
    for (int o = 16; o; o >>= 1) s += __shfl_xor_sync(0xffffffffu, s, o);
    if (lane == 0) {
        sq[row] = s;
        if (row < NTOK) nearp[row] = 0;
        if (row == 0) *maxn = 0;
    }
}

// d2 = sq_i + sq_j - 2*X.X^T via single-pass bf16 m16n8k16 (feeds top-k only).
// 128x128 tile, 8 warps (2Mx4N). Smem stride 40 bf16 = 20 words (conflict-free).
__global__ __launch_bounds__(256) void d2_bf16_kernel(
    const float* __restrict__ X, const float* __restrict__ sqv,
    float* __restrict__ C)
{
    __shared__ __nv_bfloat16 As[128 * 40];
    __shared__ __nv_bfloat16 Bs[128 * 40];
    const int tid = threadIdx.x;
    const int wid = tid >> 5, lane = tid & 31;
    const int warpM = wid >> 2, warpN = wid & 3;
    const int i0 = blockIdx.x * 128, j0 = blockIdx.y * 128;
    const int gid = lane >> 2, qid = lane & 3;

    float acc[4][4][4];
    #pragma unroll
    for (int a = 0; a < 4; a++)
        #pragma unroll
        for (int b = 0; b < 4; b++)
            #pragma unroll
            for (int c = 0; c < 4; c++) acc[a][b][c] = 0.f;

    const int lrow = tid >> 1;
    const int lk = (tid & 1) * 16;
    const float* Ag = X + (size_t)(i0 + lrow) * CDIM + lk;
    const float* Bg = X + (size_t)(j0 + lrow) * CDIM + lk;
    const int sbase = lrow * 40 + lk;

    float4 pa[4], pb[4];
    #pragma unroll
    for (int q = 0; q < 4; q++) {
        pa[q] = *(const float4*)(Ag + q * 4);
        pb[q] = *(const float4*)(Bg + q * 4);
    }
    for (int k0 = 0; k0 < CDIM; k0 += 32) {
        __syncthreads();
        #pragma unroll
        for (int q = 0; q < 4; q++) {
            uint2 ua, ub;
            ua.x = pkbf(pa[q].x, pa[q].y); ua.y = pkbf(pa[q].z, pa[q].w);
            ub.x = pkbf(pb[q].x, pb[q].y); ub.y = pkbf(pb[q].z, pb[q].w);
            *(uint2*)&As[sbase + q * 4] = ua;
            *(uint2*)&Bs[sbase + q * 4] = ub;
        }
        __syncthreads();
        if (k0 + 32 < CDIM) {
            #pragma unroll
            for (int q = 0; q < 4; q++) {
                pa[q] = *(const float4*)(Ag + k0 + 32 + q * 4);
                pb[q] = *(const float4*)(Bg + k0 + 32 + q * 4);
            }
        }
        #pragma unroll
        for (int k16 = 0; k16 < 2; k16++) {
            unsigned af[4][4], bf[4][2];
            #pragma unroll
            for (int tm = 0; tm < 4; tm++) {
                const int ao = (warpM * 64 + tm * 16 + gid) * 40 + k16 * 16 + qid * 2;
                af[tm][0] = *(const unsigned*)&As[ao];
                af[tm][1] = *(const unsigned*)&As[ao + 8 * 40];
                af[tm][2] = *(const unsigned*)&As[ao + 8];
                af[tm][3] = *(const unsigned*)&As[ao + 8 * 40 + 8];
            }
            #pragma unroll
            for (int tn = 0; tn < 4; tn++) {
                const int bo = (warpN * 32 + tn * 8 + gid) * 40 + k16 * 16 + qid * 2;
                bf[tn][0] = *(const unsigned*)&Bs[bo];
                bf[tn][1] = *(const unsigned*)&Bs[bo + 8];
            }
            #pragma unroll
            for (int tm = 0; tm < 4; tm++)
                #pragma unroll
                for (int tn = 0; tn < 4; tn++)
                    mma_bf16(acc[tm][tn], af[tm][0], af[tm][1], af[tm][2], af[tm][3],
                             bf[tn][0], bf[tn][1]);
        }
    }

    #pragma unroll
    for (int tm = 0; tm < 4; tm++) {
        const int r0 = i0 + warpM * 64 + tm * 16 + gid;
        const float sr0 = sqv[r0], sr1 = sqv[r0 + 8];
        #pragma unroll
        for (int tn = 0; tn < 4; tn++) {
            const int c0i = j0 + warpN * 32 + tn * 8 + qid * 2;
            const float sc0 = sqv[c0i], sc1 = sqv[c0i + 1];
            float2 v0, v1;
            v0.x = sr0 + sc0 - 2.f * acc[tm][tn][0];
            v0.y = sr0 + sc1 - 2.f * acc[tm][tn][1];
            v1.x = sr1 + sc0 - 2.f * acc[tm][tn][2];
            v1.y = sr1 + sc1 - 2.f * acc[tm][tn][3];
            *(float2*)&C[(size_t)r0 * NPAD + c0i] = v0;
            *(float2*)&C[(size_t)(r0 + 8) * NPAD + c0i] = v1;
        }
    }
}

// single-pass tf32 64x64 GEMM with register prefetch; ADDEMB adds emb[ni[row]]
template<int EPI, int ADDEMB>
__device__ __forceinline__ void gemm64(
    const float* __restrict__ A, const float* __restrict__ B,
    const float* __restrict__ bias, float* __restrict__ C,
    int Nn, int K, int i0, int j0,
    const int* __restrict__ ni, const float* __restrict__ emb)
{
    __shared__ float Ah[64 * 36], Bh[64 * 36];
    const int tid = threadIdx.x;
    const int wid = tid >> 5, lane = tid & 31;
    const int warpM = wid >> 1, warpN = wid & 1;
    const int gid = lane >> 2, qid = lane & 3;

    float acc[2][4][4];
    #pragma unroll
    for (int a = 0; a < 2; a++)
        #pragma unroll
        for (int b = 0; b < 4; b++)
            #pragma unroll
            for (int c = 0; c < 4; c++) acc[a][b][c] = 0.f;

    const int lrow = tid >> 1;
    const int lk = (tid & 1) * 16;
    const float* Ag = A + (size_t)(i0 + lrow) * K + lk;
    const float* Bg = B + (size_t)(j0 + lrow) * K + lk;
    const float* Eg = ADDEMB ? (emb + (size_t)ni[i0 + lrow] * CDIM + lk) : nullptr;
    const int sbase = lrow * 36 + lk;

    float4 pa[4], pb[4];
    #pragma unroll
    for (int q = 0; q < 4; q++) {
        pa[q] = *(const float4*)(Ag + q * 4);
        pb[q] = *(const float4*)(Bg + q * 4);
        if (ADDEMB) {
            float4 ev = *(const float4*)(Eg + q * 4);
            pa[q].x += ev.x; pa[q].y += ev.y; pa[q].z += ev.z; pa[q].w += ev.w;
        }
    }
    for (int k0 = 0; k0 < K; k0 += 32) {
        __syncthreads();
        #pragma unroll
        for (int q = 0; q < 4; q++) {
            float4 at, bt;
            at.x = __uint_as_float(f2tf32(pa[q].x)); at.y = __uint_as_float(f2tf32(pa[q].y));
            at.z = __uint_as_float(f2tf32(pa[q].z)); at.w = __uint_as_float(f2tf32(pa[q].w));
            bt.x = __uint_as_float(f2tf32(pb[q].x)); bt.y = __uint_as_float(f2tf32(pb[q].y));
            bt.z = __uint_as_float(f2tf32(pb[q].z)); bt.w = __uint_as_float(f2tf32(pb[q].w));
            *(float4*)&Ah[sbase + q * 4] = at;
            *(float4*)&Bh[sbase + q * 4] = bt;
        }
        __syncthreads();
        if (k0 + 32 < K) {
            #pragma unroll
            for (int q = 0; q < 4; q++) {
                pa[q] = *(const float4*)(Ag + k0 + 32 + q * 4);
                pb[q] = *(const float4*)(Bg + k0 + 32 + q * 4);
                if (ADDEMB) {
                    float4 ev = *(const float4*)(Eg + k0 + 32 + q * 4);
                    pa[q].x += ev.x; pa[q].y += ev.y; pa[q].z += ev.z; pa[q].w += ev.w;
                }
            }
        }
        #pragma unroll
        for (int k8 = 0; k8 < 4; k8++) {
            unsigned af[2][4], bf[4][2];
            #pragma unroll
            for (int tm = 0; tm < 2; tm++) {
                const int off = (warpM * 32 + tm * 16 + gid) * 36 + k8 * 8 + qid;
                af[tm][0] = __float_as_uint(Ah[off]);
                af[tm][1] = __float_as_uint(Ah[off + 8 * 36]);
                af[tm][2] = __float_as_uint(Ah[off + 4]);
                af[tm][3] = __float_as_uint(Ah[off + 8 * 36 + 4]);
            }
            #pragma unroll
            for (int tn = 0; tn < 4; tn++) {
                const int off = (warpN * 32 + tn * 8 + gid) * 36 + k8 * 8 + qid;
                bf[tn][0] = __float_as_uint(Bh[off]);
                bf[tn][1] = __float_as_uint(Bh[off + 4]);
            }
            #pragma unroll
            for (int tm = 0; tm < 2; tm++)
                #pragma unroll
                for (int tn = 0; tn < 4; tn++)
                    mma_tf32(acc[tm][tn], af[tm][0], af[tm][1], af[tm][2], af[tm][3],
                             bf[tn][0], bf[tn][1]);
        }
    }

    #pragma unroll
    for (int tm = 0; tm < 2; tm++) {
        const int r0 = i0 + warpM * 32 + tm * 16 + gid;
        #pragma unroll
        for (int tn = 0; tn < 4; tn++) {
            const int c0i = j0 + warpN * 32 + tn * 8 + qid * 2;
            const float b0 = bias[c0i], b1 = bias[c0i + 1];
            float2 v0, v1;
            v0.x = acc[tm][tn][0] + b0; v0.y = acc[tm][tn][1] + b1;
            v1.x = acc[tm][tn][2] + b0; v1.y = acc[tm][tn][3] + b1;
            if (EPI == 1) {
                v0.x = fmaxf(v0.x, 0.f); v0.y = fmaxf(v0.y, 0.f);
                v1.x = fmaxf(v1.x, 0.f); v1.y = fmaxf(v1.y, 0.f);
            }
            *(float2*)&C[(size_t)r0 * Nn + c0i] = v0;
            *(float2*)&C[(size_t)(r0 + 8) * Nn + c0i] = v1;
        }
    }
}

template<int EPI>
__global__ __launch_bounds__(128) void mma1_gemm(
    const float* __restrict__ A, const float* __restrict__ B,
    const float* __restrict__ bias, float* __restrict__ C,
    int Nn, int K)
{
    gemm64<EPI, 0>(A, B, bias, C, Nn, K, blockIdx.x * 64, blockIdx.y * 64,
                   nullptr, nullptr);
}

__global__ __launch_bounds__(128) void qkv_gemm(
    const float* __restrict__ x, const int* __restrict__ ni,
    const float* __restrict__ emb,
    const float* __restrict__ Wq, const float* __restrict__ Wk,
    const float* __restrict__ Wv,
    const float* __restrict__ bq, const float* __restrict__ bk,
    const float* __restrict__ bv,
    float* __restrict__ q, float* __restrict__ k, float* __restrict__ v)
{
    int sel = blockIdx.y >> 2, jb = blockIdx.y & 3;
    if (sel == 2) {
        gemm64<0, 0>(x, Wv, bv, v, CDIM, CDIM, blockIdx.x * 64, jb * 64,
                     nullptr, nullptr);
    } else if (sel == 0) {
        gemm64<0, 1>(x, Wq, bq, q, CDIM, CDIM, blockIdx.x * 64, jb * 64, ni, emb);
    } else {
        gemm64<0, 1>(x, Wk, bk, k, CDIM, CDIM, blockIdx.x * 64, jb * 64, ni, emb);
    }
}

__global__ __launch_bounds__(256) void topk_kernel(const float* __restrict__ d2,
                                                   int* __restrict__ nearp)
{
    __shared__ float vals[NTOK];
    __shared__ float wv[8];
    __shared__ int   wi[8];
    int row = blockIdx.x, tid = threadIdx.x;
    int lane = tid & 31, w = tid >> 5;
    const float* rp = d2 + (size_t)row * NPAD;
    for (int i = tid; i < NTOK; i += 256) vals[i] = rp[i];
    __syncthreads();
    for (int it = 0; it < TOPKK; it++) {
        float bv = 3.0e38f; int bi = 0x7FFFFFFF;
        for (int i = tid; i < NTOK; i += 256) {
            float v = vals[i];
            if (v < bv) { bv = v; bi = i; }
        }
        #pragma unroll
        for (int o = 16; o; o >>= 1) {
            float ov = __shfl_xor_sync(0xffffffffu, bv, o);
            int   oi = __shfl_xor_sync(0xffffffffu, bi, o);
            if (ov < bv || (ov == bv && oi < bi)) { bv = ov; bi = oi; }
        }
        if (lane == 0) { wv[w] = bv; wi[w] = bi; }
        __syncthreads();
        if (w == 0) {
            float fv = (lane < 8) ? wv[lane] : 3.0e38f;
            int   fi = (lane < 8) ? wi[lane] : 0x7FFFFFFF;
            #pragma unroll
            for (int o = 4; o; o >>= 1) {
                float ov = __shfl_xor_sync(0xffffffffu, fv, o);
                int   oi = __shfl_xor_sync(0xffffffffu, fi, o);
                if (ov < fv || (ov == fv && oi < fi)) { fv = ov; fi = oi; }
            }
            if (lane == 0) {
                atomicAdd(&nearp[fi], 1);
                vals[fi] = 3.0e38f;
            }
        }
        __syncthreads();
    }
}

__global__ __launch_bounds__(256) void maxni_kernel(const int* __restrict__ nearp,
                                                    int* __restrict__ ni)
{
    __shared__ int sm[256];
    int tid = threadIdx.x;
    int m = 0;
    for (int i = tid; i < NTOK; i += 256) m = max(m, nearp[i]);
    sm[tid] = m;
    __syncthreads();
    for (int s = 128; s > 0; s >>= 1) {
        if (tid < s) sm[tid] = max(sm[tid], sm[tid+s]);
        __syncthreads();
    }
    float mf = (float)sm[0];
    for (int i = tid; i < NPAD; i += 256) {
        int r = 0;
        if (i < NTOK) {
            r = (int)(((float)nearp[i] / mf) * 9.0f);
            if (r > 9) r = 9;
        }
        ni[i] = r;
    }
}

// Flash attention: bf16 m16n8k16, 64 queries/block, K/V register prefetch
__global__ __launch_bounds__(128) void attn_kernel(
    const float* __restrict__ Q, const float* __restrict__ Km,
    const float* __restrict__ V, const float* __restrict__ gp,
    float* __restrict__ O)
{
    __shared__ __nv_bfloat16 Qs[64 * 40];
    __shared__ __nv_bfloat16 Ks[64 * 40];
    __shared__ __nv_bfloat16 Vts[32 * 72];
    __shared__ __nv_bfloat16 Ps[4 * 16 * 72];
    __shared__ float gks[64];

    const int h = blockIdx.y, qb = blockIdx.x, tid = threadIdx.x;
    const int w = tid >> 5, lane = tid & 31;
    const int gid = lane >> 2, qid = lane & 3;
    const float scale = 0.17677669529663687f;

    #pragma unroll
    for (int u = tid; u < 512; u += 128) {
        int i = u >> 3, dq = (u & 7) * 4;
        float4 t = *(const float4*)(Q + (size_t)(qb * 64 + i) * CDIM + h * 32 + dq);
        uint2 pk;
        pk.x = pkbf(t.x * scale, t.y * scale);
        pk.y = pkbf(t.z * scale, t.w * scale);
        *(uint2*)&Qs[i * 40 + dq] = pk;
    }
    const float gq0 = gp[h * NTOK + qb * 64 + w * 16 + gid];
    const float gq1 = gp[h * NTOK + qb * 64 + w * 16 + gid + 8];

    float oacc[4][4];
    #pragma unroll
    for (int dt = 0; dt < 4; dt++)
        #pragma unroll
        for (int c = 0; c < 4; c++) oacc[dt][c] = 0.f;
    float m0 = -1e30f, m1 = -1e30f, l0 = 0.f, l1 = 0.f;
    __nv_bfloat16* Pw = Ps + w * (16 * 72);

    // prefetch kt = 0
    const int pj = tid >> 3, pdq = (tid & 7) * 4;   // staging coords (4 iters via +16 rows)
    float4 pkv[4], pvv[4];
    #pragma unroll
    for (int it = 0; it < 4; it++) {
        size_t gbase = (size_t)(pj + it * 16) * CDIM + h * 32 + pdq;
        pkv[it] = *(const float4*)(Km + gbase);
        pvv[it] = *(const float4*)(V + gbase);
    }
    float pg = (tid < 64) ? gp[h * NTOK + tid] : 0.f;

    for (int kt = 0; kt < 49; kt++) {
        __syncthreads();
        #pragma unroll
        for (int it = 0; it < 4; it++) {
            int j = pj + it * 16, dq = pdq;
            uint2 pk;
            pk.x = pkbf(pkv[it].x, pkv[it].y);
            pk.y = pkbf(pkv[it].z, pkv[it].w);
            *(uint2*)&Ks[j * 40 + dq] = pk;
            Vts[(dq + 0) * 72 + j] = __float2bfloat16_rn(pvv[it].x);
            Vts[(dq + 1) * 72 + j] = __float2bfloat16_rn(pvv[it].y);
            Vts[(dq + 2) * 72 + j] = __float2bfloat16_rn(pvv[it].z);
            Vts[(dq + 3) * 72 + j] = __float2bfloat16_rn(pvv[it].w);
        }
        if (tid < 64) gks[tid] = pg;
        __syncthreads();
        if (kt + 1 < 49) {
            #pragma unroll
            for (int it = 0; it < 4; it++) {
                size_t gbase = (size_t)((kt + 1) * 64 + pj + it * 16) * CDIM + h * 32 + pdq;
                pkv[it] = *(const float4*)(Km + gbase);
                pvv[it] = *(const float4*)(V + gbase);
            }
            if (tid < 64) pg = gp[h * NTOK + (kt + 1) * 64 + tid];
        }

        // S = Q K^T
        float sc[8][4];
        #pragma unroll
        for (int tn = 0; tn < 8; tn++)
            #pragma unroll
            for (int c = 0; c < 4; c++) sc[tn][c] = 0.f;
        #pragma unroll
        for (int k16 = 0; k16 < 2; k16++) {
            const int ao = (w * 16 + gid) * 40 + k16 * 16 + qid * 2;
            unsigned a0 = *(const unsigned*)&Qs[ao];
            unsigned a1 = *(const unsigned*)&Qs[ao + 8 * 40];
            unsigned a2 = *(const unsigned*)&Qs[ao + 8];
            unsigned a3 = *(const unsigned*)&Qs[ao + 8 * 40 + 8];
            #pragma unroll
            for (int tn = 0; tn < 8; tn++) {
                const int bo = (tn * 8 + gid) * 40 + k16 * 16 + qid * 2;
                mma_bf16(sc[tn], a0, a1, a2, a3,
                         *(const unsigned*)&Ks[bo], *(const unsigned*)&Ks[bo + 8]);
            }
        }
        float mn0 = -1e30f, mn1 = -1e30f;
        #pragma unroll
        for (int tn = 0; tn < 8; tn++) {
            float ga = gks[tn * 8 + qid * 2], gb = gks[tn * 8 + qid * 2 + 1];
            sc[tn][0] += fabsf(gq0 - ga); sc[tn][1] += fabsf(gq0 - gb);
            sc[tn][2] += fabsf(gq1 - ga); sc[tn][3] += fabsf(gq1 - gb);
            mn0 = fmaxf(mn0, fmaxf(sc[tn][0], sc[tn][1]));
            mn1 = fmaxf(mn1, fmaxf(sc[tn][2], sc[tn][3]));
        }
        mn0 = fmaxf(mn0, __shfl_xor_sync(0xffffffffu, mn0, 1));
        mn0 = fmaxf(mn0, __shfl_xor_sync(0xffffffffu, mn0, 2));
        mn1 = fmaxf(mn1, __shfl_xor_sync(0xffffffffu, mn1, 1));
        mn1 = fmaxf(mn1, __shfl_xor_sync(0xffffffffu, mn1, 2));
        if (mn0 > m0) {
            float corr = fexp(m0 - mn0);
            l0 *= corr;
            #pragma unroll
            for (int dt = 0; dt < 4; dt++) { oacc[dt][0] *= corr; oacc[dt][1] *= corr; }
            m0 = mn0;
        }
        if (mn1 > m1) {
            float corr = fexp(m1 - mn1);
            l1 *= corr;
            #pragma unroll
            for (int dt = 0; dt < 4; dt++) { oacc[dt][2] *= corr; oacc[dt][3] *= corr; }
            m1 = mn1;
        }
        float ps0 = 0.f, ps1 = 0.f;
        #pragma unroll
        for (int tn = 0; tn < 8; tn++) {
            float p00 = fexp(sc[tn][0] - m0), p01 = fexp(sc[tn][1] - m0);
            float p10 = fexp(sc[tn][2] - m1), p11 = fexp(sc[tn][3] - m1);
            ps0 += p00 + p01; ps1 += p10 + p11;
            int col = tn * 8 + qid * 2;
            *(unsigned*)&Pw[gid * 72 + col]       = pkbf(p00, p01);
            *(unsigned*)&Pw[(gid + 8) * 72 + col] = pkbf(p10, p11);
        }
        ps0 += __shfl_xor_sync(0xffffffffu, ps0, 1);
        ps0 += __shfl_xor_sync(0xffffffffu, ps0, 2);
        ps1 += __shfl_xor_sync(0xffffffffu, ps1, 1);
        ps1 += __shfl_xor_sync(0xffffffffu, ps1, 2);
        l0 += ps0; l1 += ps1;
        __syncwarp();
        #pragma unroll
        for (int k16 = 0; k16 < 4; k16++) {
            const int ao = gid * 72 + k16 * 16 + qid * 2;
            unsigned a0 = *(const unsigned*)&Pw[ao];
            unsigned a1 = *(const unsigned*)&Pw[ao + 8 * 72];
            unsigned a2 = *(const unsigned*)&Pw[ao + 8];
            unsigned a3 = *(const unsigned*)&Pw[ao + 8 * 72 + 8];
            #pragma unroll
            for (int dt = 0; dt < 4; dt++) {
                const int bo = (dt * 8 + gid) * 72 + k16 * 16 + qid * 2;
                mma_bf16(oacc[dt], a0, a1, a2, a3,
                         *(const unsigned*)&Vts[bo], *(const unsigned*)&Vts[bo + 8]);
            }
        }
        __syncwarp();
    }

    const float inv0 = 1.f / l0, inv1 = 1.f / l1;
    const int r0g = qb * 64 + w * 16 + gid, r1g = r0g + 8;
    #pragma unroll
    for (int dt = 0; dt < 4; dt++) {
        const int col = h * 32 + dt * 8 + qid * 2;
        float2 v0, v1;
        v0.x = oacc[dt][0] * inv0; v0.y = oacc[dt][1] * inv0;
        v1.x = oacc[dt][2] * inv1; v1.y = oacc[dt][3] * inv1;
        *(float2*)&O[(size_t)r0g * CDIM + col] = v0;
        *(float2*)&O[(size_t)r1g * CDIM + col] = v1;
    }
}

// one-pass LN: sum and sumsq reduced together
template<int FINAL>
__global__ __launch_bounds__(256) void add_ln_kernel(
    const float* __restrict__ a, const float* __restrict__ b,
    const float* __restrict__ g, const float* __restrict__ be,
    float* __restrict__ out)
{
    __shared__ float red1[8], red2[8];
    int row = blockIdx.x, tid = threadIdx.x;
    float v = a[row * CDIM + tid];
    if (!FINAL) v += b[row * CDIM + tid];
    float s1 = v, s2 = v * v;
    #pragma unroll
    for (int o = 16; o; o >>= 1) {
        s1 += __shfl_xor_sync(0xffffffffu, s1, o);
        s2 += __shfl_xor_sync(0xffffffffu, s2, o);
    }
    if ((tid & 31) == 0) { red1[tid >> 5] = s1; red2[tid >> 5] = s2; }
    __syncthreads();
    float mean = 0.f, ex2 = 0.f;
    #pragma unroll
    for (int i = 0; i < 8; i++) { mean += red1[i]; ex2 += red2[i]; }
    mean *= (1.f / 256.f);
    ex2  *= (1.f / 256.f);
    float var = ex2 - mean * mean;
    float r = (v - mean) * rsqrtf(var + 1e-5f) * g[tid] + be[tid];
    if (FINAL) out[tid * NTOK + row] = r;
    else       out[row * CDIM + tid] = r;
}

extern "C" void kernel_launch(void* const* d_in, const int* in_sizes, int n_in,
                              void* d_out, int out_size)
{
    (void)in_sizes; (void)n_in; (void)out_size;
    const float* src  = (const float*)d_in[0];
    const float* c1w  = (const float*)d_in[1];
    const float* c1b  = (const float*)d_in[2];
    const float* c2w  = (const float*)d_in[3];
    const float* c2b  = (const float*)d_in[4];
    const float* nemb = (const float*)d_in[5];
    const float* Wq   = (const float*)d_in[6];
    const float* bq   = (const float*)d_in[7];
    const float* Wk   = (const float*)d_in[8];
    const float* bk   = (const float*)d_in[9];
    const float* Wv   = (const float*)d_in[10];
    const float* bv   = (const float*)d_in[11];
    const float* Wo   = (const float*)d_in[12];
    const float* bo   = (const float*)d_in[13];
    const float* W1   = (const float*)d_in[14];
    const float* b1   = (const float*)d_in[15];
    const float* W2   = (const float*)d_in[16];
    const float* b2   = (const float*)d_in[17];
    const float* ln1g = (const float*)d_in[18];
    const float* ln1b = (const float*)d_in[19];
    const float* ln2g = (const float*)d_in[20];
    const float* ln2b = (const float*)d_in[21];
    const float* ng   = (const float*)d_in[22];
    const float* nb   = (const float*)d_in[23];

    float *c1, *gp, *x, *sqv, *d2, *q, *k, *v, *att, *ffh, *yb;
    int *nearp, *maxn, *niv;
    cudaGetSymbolAddress((void**)&c1,    g_c1);
    cudaGetSymbolAddress((void**)&gp,    g_gp);
    cudaGetSymbolAddress((void**)&x,     g_x);
    cudaGetSymbolAddress((void**)&sqv,   g_sq);
    cudaGetSymbolAddress((void**)&d2,    g_d2);
    cudaGetSymbolAddress((void**)&nearp, g_near);
    cudaGetSymbolAddress((void**)&maxn,  g_maxnear);
    cudaGetSymbolAddress((void**)&niv,   g_ni);
    cudaGetSymbolAddress((void**)&q,     g_q);
    cudaGetSymbolAddress((void**)&k,     g_k);
    cudaGetSymbolAddress((void**)&v,     g_v);
    cudaGetSymbolAddress((void**)&att,   g_att);
    cudaGetSymbolAddress((void**)&ffh,   g_ffh);
    cudaGetSymbolAddress((void**)&yb,    g_y);

    pad_kernel<<<64, 256>>>(x, sqv);
    transpose_kernel<<<dim3(98, 8), dim3(32, 32)>>>(src, x);
    conv1_kernel<<<dim3(32, 49), 256>>>(src, c1w, c1b, c1);
    conv2_kernel<<<dim3(8, 49), 256>>>(c1, c2w, c2b, gp);

    for (int i = 0; i < NLAYER; i++) {
        sq_kernel<<<400, 256>>>(x, sqv, nearp, maxn);
        d2_bf16_kernel<<<dim3(25, 25), 256>>>(x, sqv, d2);
        topk_kernel<<<NTOK, 256>>>(d2, nearp);
        maxni_kernel<<<1, 256>>>(nearp, niv);

        qkv_gemm<<<dim3(50, 12), 128>>>(x, niv, nemb,
            Wq + i*CDIM*CDIM, Wk + i*CDIM*CDIM, Wv + i*CDIM*CDIM,
            bq + i*CDIM, bk + i*CDIM, bv + i*CDIM, q, k, v);

        attn_kernel<<<dim3(49, NHEAD), 128>>>(q, k, v, gp, att);

        mma1_gemm<0><<<dim3(50, 4), 128>>>(att, Wo + i*CDIM*CDIM, bo + i*CDIM, yb, CDIM, CDIM);
        add_ln_kernel<0><<<NTOK, 256>>>(x, yb, ln1g + i*CDIM, ln1b + i*CDIM, x);

        mma1_gemm<1><<<dim3(50, 16), 128>>>(x, W1 + i*DFFN*CDIM, b1 + i*DFFN, ffh, DFFN, CDIM);
        mma1_gemm<0><<<dim3(50, 4), 128>>>(ffh, W2 + i*CDIM*DFFN, b2 + i*CDIM, yb, CDIM, DFFN);
        add_ln_kernel<0><<<NTOK, 256>>>(x, yb, ln2g + i*CDIM, ln2b + i*CDIM, x);
    }

    add_ln_kernel<1><<<NTOK, 256>>>(x, nullptr, ng, nb, (float*)d_out);
}

// round 17
// speedup vs baseline: 1.3838x; 1.0496x over previous
#include <cuda_runtime.h>
#include <cuda_bf16.h>
#include <cstdint>
#include <math.h>

#define NTOK 3136
#define NPAD 3200
#define CDIM 256
#define NHEAD 8
#define DFFN 1024
#define NLAYER 4
#define TOPKK 16
#define HW 56

__device__ float g_c1[128 * NTOK];
__device__ float g_gp[NHEAD * NTOK];
__device__ float g_x[NPAD * CDIM];
__device__ float g_d2[(size_t)NPAD * NPAD];
__device__ int   g_near[NTOK];
__device__ int   g_ni[NPAD];
__device__ float g_q[NPAD * CDIM];
__device__ float g_k[NPAD * CDIM];
__device__ float g_v[NPAD * CDIM];
__device__ float g_att[NPAD * CDIM];
__device__ float g_ffh[(size_t)NPAD * DFFN];
__device__ float g_y[NPAD * CDIM];

__device__ __forceinline__ float fexp(float x) {
    x = fmaxf(x, -87.0f);
    float y = x * 1.44269504088896341f;
    float r = rintf(y);
    float f = y - r;
    float p = 1.33335581e-3f;
    p = fmaf(p, f, 9.61812911e-3f);
    p = fmaf(p, f, 5.55041087e-2f);
    p = fmaf(p, f, 2.40226507e-1f);
    p = fmaf(p, f, 6.93147181e-1f);
    p = fmaf(p, f, 1.0f);
    return __int_as_float(__float_as_int(p) + (((int)r) << 23));
}

__device__ __forceinline__ unsigned f2tf32(float v) {
    unsigned r;
    asm("cvt.rna.tf32.f32 %0, %1;" : "=r"(r) : "f"(v));
    return r;
}

__device__ __forceinline__ unsigned pkbf(float lo, float hi) {
    unsigned r;
    asm("cvt.rn.bf16x2.f32 %0, %1, %2;" : "=r"(r) : "f"(hi), "f"(lo));
    return r;
}

__device__ __forceinline__ void mma_tf32(float c[4],
    unsigned a0, unsigned a1, unsigned a2, unsigned a3,
    unsigned b0, unsigned b1)
{
    asm volatile(
        "mma.sync.aligned.m16n8k8.row.col.f32.tf32.tf32.f32 "
        "{%0,%1,%2,%3}, {%4,%5,%6,%7}, {%8,%9}, {%0,%1,%2,%3};\n"
        : "+f"(c[0]), "+f"(c[1]), "+f"(c[2]), "+f"(c[3])
        : "r"(a0), "r"(a1), "r"(a2), "r"(a3), "r"(b0), "r"(b1));
}

__device__ __forceinline__ void mma_bf16(float c[4],
    unsigned a0, unsigned a1, unsigned a2, unsigned a3,
    unsigned b0, unsigned b1)
{
    asm volatile(
        "mma.sync.aligned.m16n8k16.row.col.f32.bf16.bf16.f32 "
        "{%0,%1,%2,%3}, {%4,%5,%6,%7}, {%8,%9}, {%0,%1,%2,%3};\n"
        : "+f"(c[0]), "+f"(c[1]), "+f"(c[2]), "+f"(c[3])
        : "r"(a0), "r"(a1), "r"(a2), "r"(a3), "r"(b0), "r"(b1));
}

__global__ void pad_kernel(float* __restrict__ x, int* __restrict__ nearp) {
    int i = blockIdx.x * 256 + threadIdx.x;
    x[NTOK * CDIM + i] = 0.f;
    if (i < NTOK) nearp[i] = 0;
}

__global__ void transpose_kernel(const float* __restrict__ src, float* __restrict__ dst) {
    __shared__ float tile[32][33];
    int t0 = blockIdx.x * 32, c0 = blockIdx.y * 32;
    int tx = threadIdx.x, ty = threadIdx.y;
    tile[ty][tx] = src[(c0 + ty) * NTOK + t0 + tx];
    __syncthreads();
    dst[(t0 + ty) * CDIM + c0 + tx] = tile[tx][ty];
}

__global__ __launch_bounds__(256) void conv1_kernel(
    const float* __restrict__ src, const float* __restrict__ wt,
    const float* __restrict__ bias, float* __restrict__ out)
{
    __shared__ float ws[4 * 2304];
    __shared__ float red[4 * 256];
    int cog = blockIdx.x;
    int tid = threadIdx.x;
    int px = tid & 63, cig = tid >> 6;
    int p = blockIdx.y * 64 + px;
    for (int i = tid; i < 4 * 2304; i += 256) ws[i] = wt[cog * 4 * 2304 + i];
    __syncthreads();
    int y = p / HW, x = p % HW;
    float a[4][2];
    #pragma unroll
    for (int j = 0; j < 4; j++) { a[j][0] = 0.f; a[j][1] = 0.f; }
    for (int ci = cig * 64; ci < cig * 64 + 64; ci += 2) {
        #pragma unroll
        for (int par = 0; par < 2; par++) {
            const float* ip = src + (ci + par) * NTOK;
            const float* wp = ws + (ci + par) * 9;
            #pragma unroll
            for (int dy = 0; dy < 3; dy++) {
                int yy = y + dy - 1; if ((unsigned)yy >= HW) continue;
                #pragma unroll
                for (int dx = 0; dx < 3; dx++) {
                    int xx = x + dx - 1; if ((unsigned)xx >= HW) continue;
                    float v = ip[yy * HW + xx]; int wi = dy * 3 + dx;
                    a[0][par] = fmaf(v, wp[wi],          a[0][par]);
                    a[1][par] = fmaf(v, wp[2304 + wi],   a[1][par]);
                    a[2][par] = fmaf(v, wp[4608 + wi],   a[2][par]);
                    a[3][par] = fmaf(v, wp[6912 + wi],   a[3][par]);
                }
            }
        }
    }
    #pragma unroll
    for (int j = 0; j < 4; j++) red[j * 256 + tid] = a[j][0] + a[j][1];
    __syncthreads();
    if (tid < 64) {
        #pragma unroll
        for (int j = 0; j < 4; j++) {
            float s = (red[j*256 + tid] + red[j*256 + tid + 64])
                    + (red[j*256 + tid + 128] + red[j*256 + tid + 192]);
            out[(cog*4+j)*NTOK + p] = fmaxf(s + bias[cog*4+j], 0.f);
        }
    }
}

__global__ __launch_bounds__(256) void conv2_kernel(
    const float* __restrict__ c1, const float* __restrict__ wt,
    const float* __restrict__ bias, float* __restrict__ gp)
{
    __shared__ float ws[1152];
    __shared__ float red[256];
    int co = blockIdx.x;
    int tid = threadIdx.x;
    int px = tid & 63, cig = tid >> 6;
    int p = blockIdx.y * 64 + px;
    for (int i = tid; i < 1152; i += 256) ws[i] = wt[co * 1152 + i];
    __syncthreads();
    int y = p / HW, x = p % HW;
    float a0 = 0.f, a1 = 0.f;
    for (int ci = cig * 32; ci < cig * 32 + 32; ci += 2) {
        #pragma unroll
        for (int dy = 0; dy < 3; dy++) {
            int yy = y + dy - 1; if ((unsigned)yy >= HW) continue;
            #pragma unroll
            for (int dx = 0; dx < 3; dx++) {
                int xx = x + dx - 1; if ((unsigned)xx >= HW) continue;
                int po = yy * HW + xx, wi = dy * 3 + dx;
                a0 = fmaf(c1[(ci+0) * NTOK + po], ws[(ci+0) * 9 + wi], a0);
                a1 = fmaf(c1[(ci+1) * NTOK + po], ws[(ci+1) * 9 + wi], a1);
            }
        }
    }
    red[tid] = a0 + a1;
    __syncthreads();
    if (tid < 64) {
        float a = bias[co] + (red[tid] + red[tid + 64]) + (red[tid + 128] + red[tid + 192]);
        gp[co * NTOK + p] = 1.0f / (1.0f + __expf(-a));
    }
}

// d2 = sq_i + sq_j - 2*X.X^T, bf16 m16n8k16; row norms computed in-kernel
// during fp32 staging (thread pair shares a row; shfl_xor(1) combine).
__global__ __launch_bounds__(256) void d2_bf16_kernel(
    const float* __restrict__ X, float* __restrict__ C)
{
    __shared__ __nv_bfloat16 As[128 * 40];
    __shared__ __nv_bfloat16 Bs[128 * 40];
    __shared__ float sqA[128], sqB[128];
    const int tid = threadIdx.x;
    const int wid = tid >> 5, lane = tid & 31;
    const int warpM = wid >> 2, warpN = wid & 3;
    const int i0 = blockIdx.x * 128, j0 = blockIdx.y * 128;
    const int gid = lane >> 2, qid = lane & 3;

    float acc[4][4][4];
    #pragma unroll
    for (int a = 0; a < 4; a++)
        #pragma unroll
        for (int b = 0; b < 4; b++)
            #pragma unroll
            for (int c = 0; c < 4; c++) acc[a][b][c] = 0.f;

    const int lrow = tid >> 1;
    const int lk = (tid & 1) * 16;
    const float* Ag = X + (size_t)(i0 + lrow) * CDIM + lk;
    const float* Bg = X + (size_t)(j0 + lrow) * CDIM + lk;
    const int sbase = lrow * 40 + lk;

    float ssqA = 0.f, ssqB = 0.f;
    float4 pa[4], pb[4];
    #pragma unroll
    for (int q = 0; q < 4; q++) {
        pa[q] = *(const float4*)(Ag + q * 4);
        pb[q] = *(const float4*)(Bg + q * 4);
    }
    for (int k0 = 0; k0 < CDIM; k0 += 32) {
        __syncthreads();
        #pragma unroll
        for (int q = 0; q < 4; q++) {
            ssqA = fmaf(pa[q].x, pa[q].x, ssqA); ssqA = fmaf(pa[q].y, pa[q].y, ssqA);
            ssqA = fmaf(pa[q].z, pa[q].z, ssqA); ssqA = fmaf(pa[q].w, pa[q].w, ssqA);
            ssqB = fmaf(pb[q].x, pb[q].x, ssqB); ssqB = fmaf(pb[q].y, pb[q].y, ssqB);
            ssqB = fmaf(pb[q].z, pb[q].z, ssqB); ssqB = fmaf(pb[q].w, pb[q].w, ssqB);
            uint2 ua, ub;
            ua.x = pkbf(pa[q].x, pa[q].y); ua.y = pkbf(pa[q].z, pa[q].w);
            ub.x = pkbf(pb[q].x, pb[q].y); ub.y = pkbf(pb[q].z, pb[q].w);
            *(uint2*)&As[sbase + q * 4] = ua;
            *(uint2*)&Bs[sbase + q * 4] = ub;
        }
        __syncthreads();
        if (k0 + 32 < CDIM) {
            #pragma unroll
            for (int q = 0; q < 4; q++) {
                pa[q] = *(const float4*)(Ag + k0 + 32 + q * 4);
                pb[q] = *(const float4*)(Bg + k0 + 32 + q * 4);
            }
        }
        #pragma unroll
        for (int k16 = 0; k16 < 2; k16++) {
            unsigned af[4][4], bf[4][2];
            #pragma unroll
            for (int tm = 0; tm < 4; tm++) {
                const int ao = (warpM * 64 + tm * 16 + gid) * 40 + k16 * 16 + qid * 2;
                af[tm][0] = *(const unsigned*)&As[ao];
                af[tm][1] = *(const unsigned*)&As[ao + 8 * 40];
                af[tm][2] = *(const unsigned*)&As[ao + 8];
                af[tm][3] = *(const unsigned*)&As[ao + 8 * 40 + 8];
            }
            #pragma unroll
            for (int tn = 0; tn < 4; tn++) {
                const int bo = (warpN * 32 + tn * 8 + gid) * 40 + k16 * 16 + qid * 2;
                bf[tn][0] = *(const unsigned*)&Bs[bo];
                bf[tn][1] = *(const unsigned*)&Bs[bo + 8];
            }
            #pragma unroll
            for (int tm = 0; tm < 4; tm++)
                #pragma unroll
                for (int tn = 0; tn < 4; tn++)
                    mma_bf16(acc[tm][tn], af[tm][0], af[tm][1], af[tm][2], af[tm][3],
                             bf[tn][0], bf[tn][1]);
        }
    }
    // combine half-row norms and publish
    float fullA = ssqA + __shfl_xor_sync(0xffffffffu, ssqA, 1);
    float fullB = ssqB + __shfl_xor_sync(0xffffffffu, ssqB, 1);
    if ((tid & 1) == 0) { sqA[lrow] = fullA; sqB[lrow] = fullB; }
    __syncthreads();

    #pragma unroll
    for (int tm = 0; tm < 4; tm++) {
        const int lr0 = warpM * 64 + tm * 16 + gid;
        const int r0 = i0 + lr0;
        const float sr0 = sqA[lr0], sr1 = sqA[lr0 + 8];
        #pragma unroll
        for (int tn = 0; tn < 4; tn++) {
            const int lc0 = warpN * 32 + tn * 8 + qid * 2;
            const int c0i = j0 + lc0;
            const float sc0 = sqB[lc0], sc1 = sqB[lc0 + 1];
            float2 v0, v1;
            v0.x = sr0 + sc0 - 2.f * acc[tm][tn][0];
            v0.y = sr0 + sc1 - 2.f * acc[tm][tn][1];
            v1.x = sr1 + sc0 - 2.f * acc[tm][tn][2];
            v1.y = sr1 + sc1 - 2.f * acc[tm][tn][3];
            *(float2*)&C[(size_t)r0 * NPAD + c0i] = v0;
            *(float2*)&C[(size_t)(r0 + 8) * NPAD + c0i] = v1;
        }
    }
}

// single-pass tf32 64x64 GEMM with register prefetch; ADDEMB adds emb[ni[row]]
template<int EPI, int ADDEMB>
__device__ __forceinline__ void gemm64(
    const float* __restrict__ A, const float* __restrict__ B,
    const float* __restrict__ bias, float* __restrict__ C,
    int Nn, int K, int i0, int j0,
    const int* __restrict__ ni, const float* __restrict__ emb)
{
    __shared__ float Ah[64 * 36], Bh[64 * 36];
    const int tid = threadIdx.x;
    const int wid = tid >> 5, lane = tid & 31;
    const int warpM = wid >> 1, warpN = wid & 1;
    const int gid = lane >> 2, qid = lane & 3;

    float acc[2][4][4];
    #pragma unroll
    for (int a = 0; a < 2; a++)
        #pragma unroll
        for (int b = 0; b < 4; b++)
            #pragma unroll
            for (int c = 0; c < 4; c++) acc[a][b][c] = 0.f;

    const int lrow = tid >> 1;
    const int lk = (tid & 1) * 16;
    const float* Ag = A + (size_t)(i0 + lrow) * K + lk;
    const float* Bg = B + (size_t)(j0 + lrow) * K + lk;
    const float* Eg = ADDEMB ? (emb + (size_t)ni[i0 + lrow] * CDIM + lk) : nullptr;
    const int sbase = lrow * 36 + lk;

    float4 pa[4], pb[4];
    #pragma unroll
    for (int q = 0; q < 4; q++) {
        pa[q] = *(const float4*)(Ag + q * 4);
        pb[q] = *(const float4*)(Bg + q * 4);
        if (ADDEMB) {
            float4 ev = *(const float4*)(Eg + q * 4);
            pa[q].x += ev.x; pa[q].y += ev.y; pa[q].z += ev.z; pa[q].w += ev.w;
        }
    }
    for (int k0 = 0; k0 < K; k0 += 32) {
        __syncthreads();
        #pragma unroll
        for (int q = 0; q < 4; q++) {
            float4 at, bt;
            at.x = __uint_as_float(f2tf32(pa[q].x)); at.y = __uint_as_float(f2tf32(pa[q].y));
            at.z = __uint_as_float(f2tf32(pa[q].z)); at.w = __uint_as_float(f2tf32(pa[q].w));
            bt.x = __uint_as_float(f2tf32(pb[q].x)); bt.y = __uint_as_float(f2tf32(pb[q].y));
            bt.z = __uint_as_float(f2tf32(pb[q].z)); bt.w = __uint_as_float(f2tf32(pb[q].w));
            *(float4*)&Ah[sbase + q * 4] = at;
            *(float4*)&Bh[sbase + q * 4] = bt;
        }
        __syncthreads();
        if (k0 + 32 < K) {
            #pragma unroll
            for (int q = 0; q < 4; q++) {
                pa[q] = *(const float4*)(Ag + k0 + 32 + q * 4);
                pb[q] = *(const float4*)(Bg + k0 + 32 + q * 4);
                if (ADDEMB) {
                    float4 ev = *(const float4*)(Eg + k0 + 32 + q * 4);
                    pa[q].x += ev.x; pa[q].y += ev.y; pa[q].z += ev.z; pa[q].w += ev.w;
                }
            }
        }
        #pragma unroll
        for (int k8 = 0; k8 < 4; k8++) {
            unsigned af[2][4], bf[4][2];
            #pragma unroll
            for (int tm = 0; tm < 2; tm++) {
                const int off = (warpM * 32 + tm * 16 + gid) * 36 + k8 * 8 + qid;
                af[tm][0] = __float_as_uint(Ah[off]);
                af[tm][1] = __float_as_uint(Ah[off + 8 * 36]);
                af[tm][2] = __float_as_uint(Ah[off + 4]);
                af[tm][3] = __float_as_uint(Ah[off + 8 * 36 + 4]);
            }
            #pragma unroll
            for (int tn = 0; tn < 4; tn++) {
                const int off = (warpN * 32 + tn * 8 + gid) * 36 + k8 * 8 + qid;
                bf[tn][0] = __float_as_uint(Bh[off]);
                bf[tn][1] = __float_as_uint(Bh[off + 4]);
            }
            #pragma unroll
            for (int tm = 0; tm < 2; tm++)
                #pragma unroll
                for (int tn = 0; tn < 4; tn++)
                    mma_tf32(acc[tm][tn], af[tm][0], af[tm][1], af[tm][2], af[tm][3],
                             bf[tn][0], bf[tn][1]);
        }
    }

    #pragma unroll
    for (int tm = 0; tm < 2; tm++) {
        const int r0 = i0 + warpM * 32 + tm * 16 + gid;
        #pragma unroll
        for (int tn = 0; tn < 4; tn++) {
            const int c0i = j0 + warpN * 32 + tn * 8 + qid * 2;
            const float b0 = bias[c0i], b1 = bias[c0i + 1];
            float2 v0, v1;
            v0.x = acc[tm][tn][0] + b0; v0.y = acc[tm][tn][1] + b1;
            v1.x = acc[tm][tn][2] + b0; v1.y = acc[tm][tn][3] + b1;
            if (EPI == 1) {
                v0.x = fmaxf(v0.x, 0.f); v0.y = fmaxf(v0.y, 0.f);
                v1.x = fmaxf(v1.x, 0.f); v1.y = fmaxf(v1.y, 0.f);
            }
            *(float2*)&C[(size_t)r0 * Nn + c0i] = v0;
            *(float2*)&C[(size_t)(r0 + 8) * Nn + c0i] = v1;
        }
    }
}

template<int EPI>
__global__ __launch_bounds__(128) void mma1_gemm(
    const float* __restrict__ A, const float* __restrict__ B,
    const float* __restrict__ bias, float* __restrict__ C,
    int Nn, int K)
{
    gemm64<EPI, 0>(A, B, bias, C, Nn, K, blockIdx.x * 64, blockIdx.y * 64,
                   nullptr, nullptr);
}

__global__ __launch_bounds__(128) void qkv_gemm(
    const float* __restrict__ x, const int* __restrict__ ni,
    const float* __restrict__ emb,
    const float* __restrict__ Wq, const float* __restrict__ Wk,
    const float* __restrict__ Wv,
    const float* __restrict__ bq, const float* __restrict__ bk,
    const float* __restrict__ bv,
    float* __restrict__ q, float* __restrict__ k, float* __restrict__ v)
{
    int sel = blockIdx.y >> 2, jb = blockIdx.y & 3;
    if (sel == 2) {
        gemm64<0, 0>(x, Wv, bv, v, CDIM, CDIM, blockIdx.x * 64, jb * 64,
                     nullptr, nullptr);
    } else if (sel == 0) {
        gemm64<0, 1>(x, Wq, bq, q, CDIM, CDIM, blockIdx.x * 64, jb * 64, ni, emb);
    } else {
        gemm64<0, 1>(x, Wk, bk, k, CDIM, CDIM, blockIdx.x * 64, jb * 64, ni, emb);
    }
}

// top-16 smallest per row: values live in registers (<=13/thread); per
// extraction, shfl argmin over cached thread-minima; only the winner rescans.
__global__ __launch_bounds__(256) void topk_kernel(const float* __restrict__ d2,
                                                   int* __restrict__ nearp)
{
    __shared__ float wv[8];
    __shared__ int   wi[8];
    __shared__ int   bfi;
    const int row = blockIdx.x, tid = threadIdx.x;
    const int lane = tid & 31, w = tid >> 5;
    const float* rp = d2 + (size_t)row * NPAD;

    float lv[13];
    #pragma unroll
    for (int j = 0; j < 13; j++) {
        int idx = tid + j * 256;
        lv[j] = (idx < NTOK) ? rp[idx] : 3.0e38f;
    }
    unsigned alive = 0x1FFFu;
    float cm = 3.0e38f; int cj = 0;
    #pragma unroll
    for (int j = 0; j < 13; j++)
        if (lv[j] < cm) { cm = lv[j]; cj = j; }
    int ci = tid + cj * 256;

    for (int it = 0; it < TOPKK; it++) {
        float bv = cm; int bi = ci;
        #pragma unroll
        for (int o = 16; o; o >>= 1) {
            float ov = __shfl_xor_sync(0xffffffffu, bv, o);
            int   oi = __shfl_xor_sync(0xffffffffu, bi, o);
            if (ov < bv || (ov == bv && oi < bi)) { bv = ov; bi = oi; }
        }
        if (lane == 0) { wv[w] = bv; wi[w] = bi; }
        __syncthreads();
        if (w == 0) {
            float fv = (lane < 8) ? wv[lane] : 3.0e38f;
            int   fi = (lane < 8) ? wi[lane] : 0x7FFFFFFF;
            #pragma unroll
            for (int o = 4; o; o >>= 1) {
                float ov = __shfl_xor_sync(0xffffffffu, fv, o);
                int   oi = __shfl_xor_sync(0xffffffffu, fi, o);
                if (ov < fv || (ov == fv && oi < fi)) { fv = ov; fi = oi; }
            }
            if (lane == 0) {
                atomicAdd(&nearp[fi], 1);
                bfi = fi;
            }
        }
        __syncthreads();
        const int fi = bfi;
        if ((fi & 255) == tid) {
            alive &= ~(1u << (fi >> 8));
            cm = 3.0e38f; cj = 0;
            #pragma unroll
            for (int j = 0; j < 13; j++)
                if (((alive >> j) & 1u) && lv[j] < cm) { cm = lv[j]; cj = j; }
            ci = tid + cj * 256;
        }
    }
}

// max in-degree -> ni bucket; zeroes nearp for the next layer after reading
__global__ __launch_bounds__(256) void maxni_kernel(int* __restrict__ nearp,
                                                    int* __restrict__ ni)
{
    __shared__ int sm[256];
    int tid = threadIdx.x;
    int m = 0;
    for (int i = tid; i < NTOK; i += 256) m = max(m, nearp[i]);
    sm[tid] = m;
    __syncthreads();
    for (int s = 128; s > 0; s >>= 1) {
        if (tid < s) sm[tid] = max(sm[tid], sm[tid+s]);
        __syncthreads();
    }
    float mf = (float)sm[0];
    for (int i = tid; i < NPAD; i += 256) {
        int r = 0;
        if (i < NTOK) {
            r = (int)(((float)nearp[i] / mf) * 9.0f);
            if (r > 9) r = 9;
            nearp[i] = 0;
        }
        ni[i] = r;
    }
}

// Flash attention: bf16 m16n8k16, 64 queries/block, K/V register prefetch
__global__ __launch_bounds__(128) void attn_kernel(
    const float* __restrict__ Q, const float* __restrict__ Km,
    const float* __restrict__ V, const float* __restrict__ gp,
    float* __restrict__ O)
{
    __shared__ __nv_bfloat16 Qs[64 * 40];
    __shared__ __nv_bfloat16 Ks[64 * 40];
    __shared__ __nv_bfloat16 Vts[32 * 72];
    __shared__ __nv_bfloat16 Ps[4 * 16 * 72];
    __shared__ float gks[64];

    const int h = blockIdx.y, qb = blockIdx.x, tid = threadIdx.x;
    const int w = tid >> 5, lane = tid & 31;
    const int gid = lane >> 2, qid = lane & 3;
    const float scale = 0.17677669529663687f;

    #pragma unroll
    for (int u = tid; u < 512; u += 128) {
        int i = u >> 3, dq = (u & 7) * 4;
        float4 t = *(const float4*)(Q + (size_t)(qb * 64 + i) * CDIM + h * 32 + dq);
        uint2 pk;
        pk.x = pkbf(t.x * scale, t.y * scale);
        pk.y = pkbf(t.z * scale, t.w * scale);
        *(uint2*)&Qs[i * 40 + dq] = pk;
    }
    const float gq0 = gp[h * NTOK + qb * 64 + w * 16 + gid];
    const float gq1 = gp[h * NTOK + qb * 64 + w * 16 + gid + 8];

    float oacc[4][4];
    #pragma unroll
    for (int dt = 0; dt < 4; dt++)
        #pragma unroll
        for (int c = 0; c < 4; c++) oacc[dt][c] = 0.f;
    float m0 = -1e30f, m1 = -1e30f, l0 = 0.f, l1 = 0.f;
    __nv_bfloat16* Pw = Ps + w * (16 * 72);

    const int pj = tid >> 3, pdq = (tid & 7) * 4;
    float4 pkv[4], pvv[4];
    #pragma unroll
    for (int it = 0; it < 4; it++) {
        size_t gbase = (size_t)(pj + it * 16) * CDIM + h * 32 + pdq;
        pkv[it] = *(const float4*)(Km + gbase);
        pvv[it] = *(const float4*)(V + gbase);
    }
    float pg = (tid < 64) ? gp[h * NTOK + tid] : 0.f;

    for (int kt = 0; kt < 49; kt++) {
        __syncthreads();
        #pragma unroll
        for (int it = 0; it < 4; it++) {
            int j = pj + it * 16, dq = pdq;
            uint2 pk;
            pk.x = pkbf(pkv[it].x, pkv[it].y);
            pk.y = pkbf(pkv[it].z, pkv[it].w);
            *(uint2*)&Ks[j * 40 + dq] = pk;
            Vts[(dq + 0) * 72 + j] = __float2bfloat16_rn(pvv[it].x);
            Vts[(dq + 1) * 72 + j] = __float2bfloat16_rn(pvv[it].y);
            Vts[(dq + 2) * 72 + j] = __float2bfloat16_rn(pvv[it].z);
            Vts[(dq + 3) * 72 + j] = __float2bfloat16_rn(pvv[it].w);
        }
        if (tid < 64) gks[tid] = pg;
        __syncthreads();
        if (kt + 1 < 49) {
            #pragma unroll
            for (int it = 0; it < 4; it++) {
                size_t gbase = (size_t)((kt + 1) * 64 + pj + it * 16) * CDIM + h * 32 + pdq;
                pkv[it] = *(const float4*)(Km + gbase);
                pvv[it] = *(const float4*)(V + gbase);
            }
            if (tid < 64) pg = gp[h * NTOK + (kt + 1) * 64 + tid];
        }

        float sc[8][4];
        #pragma unroll
        for (int tn = 0; tn < 8; tn++)
            #pragma unroll
            for (int c = 0; c < 4; c++) sc[tn][c] = 0.f;
        #pragma unroll
        for (int k16 = 0; k16 < 2; k16++) {
            const int ao = (w * 16 + gid) * 40 + k16 * 16 + qid * 2;
            unsigned a0 = *(const unsigned*)&Qs[ao];
            unsigned a1 = *(const unsigned*)&Qs[ao + 8 * 40];
            unsigned a2 = *(const unsigned*)&Qs[ao + 8];
            unsigned a3 = *(const unsigned*)&Qs[ao + 8 * 40 + 8];
            #pragma unroll
            for (int tn = 0; tn < 8; tn++) {
                const int bo = (tn * 8 + gid) * 40 + k16 * 16 + qid * 2;
                mma_bf16(sc[tn], a0, a1, a2, a3,
                         *(const unsigned*)&Ks[bo], *(const unsigned*)&Ks[bo + 8]);
            }
        }
        float mn0 = -1e30f, mn1 = -1e30f;
        #pragma unroll
        for (int tn = 0; tn < 8; tn++) {
            float ga = gks[tn * 8 + qid * 2], gb = gks[tn * 8 + qid * 2 + 1];
            sc[tn][0] += fabsf(gq0 - ga); sc[tn][1] += fabsf(gq0 - gb);
            sc[tn][2] += fabsf(gq1 - ga); sc[tn][3] += fabsf(gq1 - gb);
            mn0 = fmaxf(mn0, fmaxf(sc[tn][0], sc[tn][1]));
            mn1 = fmaxf(mn1, fmaxf(sc[tn][2], sc[tn][3]));
        }
        mn0 = fmaxf(mn0, __shfl_xor_sync(0xffffffffu, mn0, 1));
        mn0 = fmaxf(mn0, __shfl_xor_sync(0xffffffffu, mn0, 2));
        mn1 = fmaxf(mn1, __shfl_xor_sync(0xffffffffu, mn1, 1));
        mn1 = fmaxf(mn1, __shfl_xor_sync(0xffffffffu, mn1, 2));
        if (mn0 > m0) {
            float corr = fexp(m0 - mn0);
            l0 *= corr;
            #pragma unroll
            for (int dt = 0; dt < 4; dt++) { oacc[dt][0] *= corr; oacc[dt][1] *= corr; }
            m0 = mn0;
        }
        if (mn1 > m1) {
            float corr = fexp(m1 - mn1);
            l1 *= corr;
            #pragma unroll
            for (int dt = 0; dt < 4; dt++) { oacc[dt][2] *= corr; oacc[dt][3] *= corr; }
            m1 = mn1;
        }
        float ps0 = 0.f, ps1 = 0.f;
        #pragma unroll
        for (int tn = 0; tn < 8; tn++) {
            float p00 = fexp(sc[tn][0] - m0), p01 = fexp(sc[tn][1] - m0);
            float p10 = fexp(sc[tn][2] - m1), p11 = fexp(sc[tn][3] - m1);
            ps0 += p00 + p01; ps1 += p10 + p11;
            int col = tn * 8 + qid * 2;
            *(unsigned*)&Pw[gid * 72 + col]       = pkbf(p00, p01);
            *(unsigned*)&Pw[(gid + 8) * 72 + col] = pkbf(p10, p11);
        }
        ps0 += __shfl_xor_sync(0xffffffffu, ps0, 1);
        ps0 += __shfl_xor_sync(0xffffffffu, ps0, 2);
        ps1 += __shfl_xor_sync(0xffffffffu, ps1, 1);
        ps1 += __shfl_xor_sync(0xffffffffu, ps1, 2);
        l0 += ps0; l1 += ps1;
        __syncwarp();
        #pragma unroll
        for (int k16 = 0; k16 < 4; k16++) {
            const int ao = gid * 72 + k16 * 16 + qid * 2;
            unsigned a0 = *(const unsigned*)&Pw[ao];
            unsigned a1 = *(const unsigned*)&Pw[ao + 8 * 72];
            unsigned a2 = *(const unsigned*)&Pw[ao + 8];
            unsigned a3 = *(const unsigned*)&Pw[ao + 8 * 72 + 8];
            #pragma unroll
            for (int dt = 0; dt < 4; dt++) {
                const int bo = (dt * 8 + gid) * 72 + k16 * 16 + qid * 2;
                mma_bf16(oacc[dt], a0, a1, a2, a3,
                         *(const unsigned*)&Vts[bo], *(const unsigned*)&Vts[bo + 8]);
            }
        }
        __syncwarp();
    }

    const float inv0 = 1.f / l0, inv1 = 1.f / l1;
    const int r0g = qb * 64 + w * 16 + gid, r1g = r0g + 8;
    #pragma unroll
    for (int dt = 0; dt < 4; dt++) {
        const int col = h * 32 + dt * 8 + qid * 2;
        float2 v0, v1;
        v0.x = oacc[dt][0] * inv0; v0.y = oacc[dt][1] * inv0;
        v1.x = oacc[dt][2] * inv1; v1.y = oacc[dt][3] * inv1;
        *(float2*)&O[(size_t)r0g * CDIM + col] = v0;
        *(float2*)&O[(size_t)r1g * CDIM + col] = v1;
    }
}

// one-pass LN: sum and sumsq reduced together
template<int FINAL>
__global__ __launch_bounds__(256) void add_ln_kernel(
    const float* __restrict__ a, const float* __restrict__ b,
    const float* __restrict__ g, const float* __restrict__ be,
    float* __restrict__ out)
{
    __shared__ float red1[8], red2[8];
    int row = blockIdx.x, tid = threadIdx.x;
    float v = a[row * CDIM + tid];
    if (!FINAL) v += b[row * CDIM + tid];
    float s1 = v, s2 = v * v;
    #pragma unroll
    for (int o = 16; o; o >>= 1) {
        s1 += __shfl_xor_sync(0xffffffffu, s1, o);
        s2 += __shfl_xor_sync(0xffffffffu, s2, o);
    }
    if ((tid & 31) == 0) { red1[tid >> 5] = s1; red2[tid >> 5] = s2; }
    __syncthreads();
    float mean = 0.f, ex2 = 0.f;
    #pragma unroll
    for (int i = 0; i < 8; i++) { mean += red1[i]; ex2 += red2[i]; }
    mean *= (1.f / 256.f);
    ex2  *= (1.f / 256.f);
    float var = ex2 - mean * mean;
    float r = (v - mean) * rsqrtf(var + 1e-5f) * g[tid] + be[tid];
    if (FINAL) out[tid * NTOK + row] = r;
    else       out[row * CDIM + tid] = r;
}

extern "C" void kernel_launch(void* const* d_in, const int* in_sizes, int n_in,
                              void* d_out, int out_size)
{
    (void)in_sizes; (void)n_in; (void)out_size;
    const float* src  = (const float*)d_in[0];
    const float* c1w  = (const float*)d_in[1];
    const float* c1b  = (const float*)d_in[2];
    const float* c2w  = (const float*)d_in[3];
    const float* c2b  = (const float*)d_in[4];
    const float* nemb = (const float*)d_in[5];
    const float* Wq   = (const float*)d_in[6];
    const float* bq   = (const float*)d_in[7];
    const float* Wk   = (const float*)d_in[8];
    const float* bk   = (const float*)d_in[9];
    const float* Wv   = (const float*)d_in[10];
    const float* bv   = (const float*)d_in[11];
    const float* Wo   = (const float*)d_in[12];
    const float* bo   = (const float*)d_in[13];
    const float* W1   = (const float*)d_in[14];
    const float* b1   = (const float*)d_in[15];
    const float* W2   = (const float*)d_in[16];
    const float* b2   = (const float*)d_in[17];
    const float* ln1g = (const float*)d_in[18];
    const float* ln1b = (const float*)d_in[19];
    const float* ln2g = (const float*)d_in[20];
    const float* ln2b = (const float*)d_in[21];
    const float* ng   = (const float*)d_in[22];
    const float* nb   = (const float*)d_in[23];

    float *c1, *gp, *x, *d2, *q, *k, *v, *att, *ffh, *yb;
    int *nearp, *niv;
    cudaGetSymbolAddress((void**)&c1,    g_c1);
    cudaGetSymbolAddress((void**)&gp,    g_gp);
    cudaGetSymbolAddress((void**)&x,     g_x);
    cudaGetSymbolAddress((void**)&d2,    g_d2);
    cudaGetSymbolAddress((void**)&nearp, g_near);
    cudaGetSymbolAddress((void**)&niv,   g_ni);
    cudaGetSymbolAddress((void**)&q,     g_q);
    cudaGetSymbolAddress((void**)&k,     g_k);
    cudaGetSymbolAddress((void**)&v,     g_v);
    cudaGetSymbolAddress((void**)&att,   g_att);
    cudaGetSymbolAddress((void**)&ffh,   g_ffh);
    cudaGetSymbolAddress((void**)&yb,    g_y);

    pad_kernel<<<64, 256>>>(x, nearp);
    transpose_kernel<<<dim3(98, 8), dim3(32, 32)>>>(src, x);
    conv1_kernel<<<dim3(32, 49), 256>>>(src, c1w, c1b, c1);
    conv2_kernel<<<dim3(8, 49), 256>>>(c1, c2w, c2b, gp);

    for (int i = 0; i < NLAYER; i++) {
        d2_bf16_kernel<<<dim3(25, 25), 256>>>(x, d2);
        topk_kernel<<<NTOK, 256>>>(d2, nearp);
        maxni_kernel<<<1, 256>>>(nearp, niv);

        qkv_gemm<<<dim3(50, 12), 128>>>(x, niv, nemb,
            Wq + i*CDIM*CDIM, Wk + i*CDIM*CDIM, Wv + i*CDIM*CDIM,
            bq + i*CDIM, bk + i*CDIM, bv + i*CDIM, q, k, v);

        attn_kernel<<<dim3(49, NHEAD), 128>>>(q, k, v, gp, att);

        mma1_gemm<0><<<dim3(50, 4), 128>>>(att, Wo + i*CDIM*CDIM, bo + i*CDIM, yb, CDIM, CDIM);
        add_ln_kernel<0><<<NTOK, 256>>>(x, yb, ln1g + i*CDIM, ln1b + i*CDIM, x);

        mma1_gemm<1><<<dim3(50, 16), 128>>>(x, W1 + i*DFFN*CDIM, b1 + i*DFFN, ffh, DFFN, CDIM);
        mma1_gemm<0><<<dim3(50, 4), 128>>>(ffh, W2 + i*CDIM*DFFN, b2 + i*CDIM, yb, CDIM, DFFN);
        add_ln_kernel<0><<<NTOK, 256>>>(x, yb, ln2g + i*CDIM, ln2b + i*CDIM, x);
    }

    add_ln_kernel<1><<<NTOK, 256>>>(x, nullptr, ng, nb, (float*)d_out);
}